// round 12
// baseline (speedup 1.0000x reference)
#include <cuda_runtime.h>
#include <cuda_fp16.h>
#include <math.h>
#include <stdint.h>

#define NN 50000
#define NE 800000
#define NL 4
#define NG 64
#define EPS 1e-5f

// ---------------- static device scratch ----------------
__device__ __align__(16) float g_h[NN * 64];
__device__ __align__(16) float g_u[NN * 128];      // [h | aggr_h]
__device__ __align__(16) float g_un[NN * 64];
__device__ __align__(16) float g_pos[NN * 3];
__device__ __align__(16) float g_aggr_p[NN * 3];
__device__ __align__(16) __half g_HpreH[(size_t)NN * 256];   // fp16, 25.6MB (L2-resident)
__device__ __align__(16) float g_wpack4[NL][64 * 256];       // k-major [k][op]
__device__ __align__(16) __half g_t1h[(size_t)NE * 64];      // CSR-ordered, fp16
__device__ __align__(16) __half g_t2h[(size_t)NE * 64];      // CSR-ordered, fp16
__device__ __align__(16) __half g_mlinh[(size_t)NE * 64];    // CSR-ordered, fp16
__device__ __align__(16) float g_sc[NE];                     // CSR-ordered
__device__ int g_deg[NN];
__device__ int g_rowstart[NN + 1];
__device__ int g_cursor[NN];
__device__ int g_csrsrc[NE];
__device__ int g_csrdst[NE];
__device__ int g_csre[NE];
__device__ double g_sum[256];
__device__ double g_sumsq[256];
__device__ __align__(16) float g_bnA[256];
__device__ __align__(16) float g_bnB[256];
__device__ __align__(16) float g_pool[NG * 64];
__device__ float g_cnt[NG];

__device__ __forceinline__ float silu_f(float y) {
    return y * (1.0f / (1.0f + __expf(-y)));
}

__device__ __forceinline__ void red_add_v4(float* p, float a, float b, float c, float d) {
    asm volatile("red.global.add.v4.f32 [%0], {%1,%2,%3,%4};"
                 :: "l"(p), "f"(a), "f"(b), "f"(c), "f"(d) : "memory");
}

// fp16 m16n8k16 MMA, fp32 accumulate
__device__ __forceinline__ void mma_f16(float* c, uint32_t a0, uint32_t a1, uint32_t a2, uint32_t a3,
                                        uint32_t b0, uint32_t b1) {
    asm volatile("mma.sync.aligned.m16n8k16.row.col.f32.f16.f16.f32 "
                 "{%0,%1,%2,%3}, {%4,%5,%6,%7}, {%8,%9}, {%0,%1,%2,%3};"
                 : "+f"(c[0]), "+f"(c[1]), "+f"(c[2]), "+f"(c[3])
                 : "r"(a0), "r"(a1), "r"(a2), "r"(a3), "r"(b0), "r"(b1));
}

// split (x,y) into packed fp16 hi + residual-lo pairs
__device__ __forceinline__ void packsplit(float x, float y, uint32_t& h, uint32_t& l) {
    __half hx = __float2half_rn(x), hy = __float2half_rn(y);
    __half lx = __float2half_rn(x - __half2float(hx));
    __half ly = __float2half_rn(y - __half2float(hy));
    __half2 hh = __halves2half2(hx, hy), ll = __halves2half2(lx, ly);
    h = *(uint32_t*)&hh; l = *(uint32_t*)&ll;
}

// ---------------- init ----------------
__global__ void k_init(const float* __restrict__ ns, const float* __restrict__ nt,
                       const float* __restrict__ pos, const float* __restrict__ w,
                       const float* __restrict__ b)
{
    int idx = blockIdx.x * blockDim.x + threadIdx.x;
    if (idx < NG * 64) g_pool[idx] = 0.f;
    if (idx < NG) g_cnt[idx] = 0.f;
    if (idx < 256) { g_sum[idx] = 0.0; g_sumsq[idx] = 0.0; }
    if (idx < NN) g_deg[idx] = 0;
    if (idx >= NN * 64) return;
    int n = idx >> 6, o = idx & 63;
    const float* wr = w + o * 8;
    const float* s = ns + n * 6;
    float acc = b[o];
#pragma unroll
    for (int i = 0; i < 6; i++) acc = fmaf(s[i], wr[i], acc);
    acc = fmaf(nt[n * 2 + 0], wr[6], acc);
    acc = fmaf(nt[n * 2 + 1], wr[7], acc);
    g_h[idx] = acc;
    g_u[(size_t)n * 128 + o] = acc;
    if (o < 3) g_pos[n * 3 + o] = pos[n * 3 + o];
}

// ---------------- CSR build ----------------
__global__ void k_hist(const int* __restrict__ ei)
{
    int e = blockIdx.x * blockDim.x + threadIdx.x;
    if (e < NE) atomicAdd(&g_deg[ei[NE + e]], 1);
}

__global__ __launch_bounds__(1024) void k_scan()
{
    __shared__ int ssum[1024];
    int t = threadIdx.x;
    const int C = 49;
    int begin = t * C;
    int end = begin + C; if (end > NN) end = NN;
    if (begin > NN) begin = NN;
    int s = 0;
    for (int i = begin; i < end; i++) s += g_deg[i];
    ssum[t] = s;
    __syncthreads();
    for (int off = 1; off < 1024; off <<= 1) {
        int v = (t >= off) ? ssum[t - off] : 0;
        __syncthreads();
        ssum[t] += v;
        __syncthreads();
    }
    int run = ssum[t] - s;
    for (int i = begin; i < end; i++) {
        g_rowstart[i] = run;
        g_cursor[i] = run;
        run += g_deg[i];
    }
    if (t == 1023) g_rowstart[NN] = ssum[1023];
}

__global__ void k_fill(const int* __restrict__ ei)
{
    int e = blockIdx.x * blockDim.x + threadIdx.x;
    if (e >= NE) return;
    int s = ei[e], d = ei[NE + e];
    int p = atomicAdd(&g_cursor[d], 1);
    g_csrsrc[p] = s;
    g_csrdst[p] = d;
    g_csre[p] = e;
}

// ---------------- pack h-columns of msg_w1/updc_w1 for ALL layers ----------------
__global__ void k_wpack_all(const float* __restrict__ mw1a, const float* __restrict__ cw1a)
{
    int idx = blockIdx.x * blockDim.x + threadIdx.x;
    if (idx >= NL * 64 * 256) return;
    int l = idx >> 14;
    int r = idx & 16383;
    int k = r >> 8, op = r & 255, o = op & 63;
    const float* mw1 = mw1a + (size_t)l * 64 * 161;
    const float* cw1 = cw1a + (size_t)l * 64 * 161;
    float v;
    if (op < 64)       v = mw1[o * 161 + k];
    else if (op < 128) v = mw1[o * 161 + 64 + k];
    else if (op < 192) v = cw1[o * 161 + k];
    else               v = cw1[o * 161 + 64 + k];
    g_wpack4[l][k * 256 + op] = v;
}

// ---------------- Hpre: tiled GEMM 64n x 128o (2 phases), K=64; fp16 output ----------------
__global__ __launch_bounds__(256) void k_hpre(int layer)
{
    const float* wpack = g_wpack4[layer];
    __shared__ __align__(16) float sA[64][64];
    __shared__ __align__(16) float sB[64][128];
    int tid = threadIdx.x, tx = tid & 15, ty = tid >> 4;
    int ntiles = (NN + 63) >> 6;
    for (int t = blockIdx.x; t < ntiles; t += gridDim.x) {
        int n0 = t << 6;
        __syncthreads();
        {
            int nn = tid >> 2, k0 = (tid & 3) << 4;
            int n = n0 + nn;
#pragma unroll
            for (int m = 0; m < 4; m++) {
                float4 v = (n < NN) ? *(const float4*)&g_h[n * 64 + k0 + 4 * m]
                                    : make_float4(0.f, 0.f, 0.f, 0.f);
                sA[k0 + 4 * m + 0][nn] = v.x;
                sA[k0 + 4 * m + 1][nn] = v.y;
                sA[k0 + 4 * m + 2][nn] = v.z;
                sA[k0 + 4 * m + 3][nn] = v.w;
            }
        }
        for (int ph = 0; ph < 2; ph++) {
            __syncthreads();
#pragma unroll
            for (int r = 0; r < 8; r++) {
                int i = tid + r * 256;
                int k = i >> 5, o4 = (i & 31) << 2;
                *(float4*)&sB[k][o4] = *(const float4*)&wpack[k * 256 + ph * 128 + o4];
            }
            __syncthreads();
            float acc[4][8];
#pragma unroll
            for (int i = 0; i < 4; i++)
#pragma unroll
                for (int j = 0; j < 8; j++) acc[i][j] = 0.f;
#pragma unroll 4
            for (int k = 0; k < 64; k++) {
                float4 a = *(const float4*)&sA[k][tx << 2];
                float4 b0 = *(const float4*)&sB[k][ty << 3];
                float4 b1 = *(const float4*)&sB[k][(ty << 3) + 4];
                float av[4] = {a.x, a.y, a.z, a.w};
                float bv[8] = {b0.x, b0.y, b0.z, b0.w, b1.x, b1.y, b1.z, b1.w};
#pragma unroll
                for (int i = 0; i < 4; i++)
#pragma unroll
                    for (int j = 0; j < 8; j++) acc[i][j] = fmaf(av[i], bv[j], acc[i][j]);
            }
#pragma unroll
            for (int i = 0; i < 4; i++) {
                int n = n0 + (tx << 2) + i;
                if (n < NN) {
                    __half hv[8];
#pragma unroll
                    for (int j = 0; j < 8; j++) hv[j] = __float2half_rn(acc[i][j]);
                    *(uint4*)&g_HpreH[(size_t)n * 256 + ph * 128 + (ty << 3)] = *(uint4*)hv;
                }
            }
        }
    }
}

// ---------------- edge A (fp16 MMA, CSR order): t1/t2 = Hpre gather + r*wr + es@Wes^T + b ----------------
// 256 threads, 8 warps; tile = 64 CSR positions x 128 ch. Warp w covers ch [16w, 16w+16). K=32 (2 k16 steps).
__global__ __launch_bounds__(256) void k_edgeAmma(const float* __restrict__ es,
                                                  const float* __restrict__ mw1, const float* __restrict__ mb1,
                                                  const float* __restrict__ cw1, const float* __restrict__ cb1)
{
    __shared__ __align__(16) char sBuf[64 * 132 * 4];   // union: sEs half[64][40] | sOut float[64][132]
    __half (*sEs)[40] = (__half(*)[40])sBuf;
    float (*sOut)[132] = (float(*)[132])sBuf;
    __shared__ float sR[64];
    __shared__ int sSrc[64], sDst[64];
    __shared__ float sS[128], sQ[128];

    int tid = threadIdx.x;
    int warp = tid >> 5, lane = tid & 31;
    int gid = lane >> 2, tig = lane & 3;

    if (tid < 128) { sS[tid] = 0.f; sQ[tid] = 0.f; }

    // weight A fragments (16 ch x 32 k per warp), fp16 hi/lo split
    uint32_t ah[2][4], al[2][4];
    {
        int r0 = warp * 16 + gid;
        int r1 = r0 + 8;
        const float* w0 = (r0 < 64) ? &mw1[r0 * 161 + 129] : &cw1[(r0 - 64) * 161 + 129];
        const float* w1 = (r1 < 64) ? &mw1[r1 * 161 + 129] : &cw1[(r1 - 64) * 161 + 129];
#pragma unroll
        for (int kb = 0; kb < 2; kb++) {
            int k0 = kb * 16 + 2 * tig;
            packsplit(w0[k0], w0[k0 + 1], ah[kb][0], al[kb][0]);
            packsplit(w1[k0], w1[k0 + 1], ah[kb][1], al[kb][1]);
            packsplit(w0[k0 + 8], w0[k0 + 9], ah[kb][2], al[kb][2]);
            packsplit(w1[k0 + 8], w1[k0 + 9], ah[kb][3], al[kb][3]);
        }
    }
    int ch0 = lane << 2;
    float wr4[4], bb4[4];
#pragma unroll
    for (int j = 0; j < 4; j++) {
        int ch = ch0 + j;
        wr4[j] = (ch < 64) ? mw1[ch * 161 + 128] : cw1[(ch - 64) * 161 + 128];
        bb4[j] = (ch < 64) ? mb1[ch] : cb1[ch - 64];
    }
    int hd_off = (ch0 < 64) ? ch0 : 64 + ch0;
    int hs_off = (ch0 < 64) ? 64 + ch0 : 128 + ch0;
    float st[4] = {0.f, 0.f, 0.f, 0.f}, sq[4] = {0.f, 0.f, 0.f, 0.f};

    for (int t = blockIdx.x; t < NE / 64; t += gridDim.x) {
        int p0 = t << 6;
        __syncthreads();
        if (tid < 64) {
            int p = p0 + tid;
            int s = g_csrsrc[p], d = g_csrdst[p];
            sSrc[tid] = s; sDst[tid] = d;
            float dx = g_pos[d * 3] - g_pos[s * 3];
            float dy = g_pos[d * 3 + 1] - g_pos[s * 3 + 1];
            float dz = g_pos[d * 3 + 2] - g_pos[s * 3 + 2];
            sR[tid] = sqrtf(dx * dx + dy * dy + dz * dz);
        }
        // stage es as fp16 [edge][k]
        {
            int el = tid >> 2, q = tid & 3;
            int eid = g_csre[p0 + el];
            const float4* ep = (const float4*)&es[(size_t)eid * 32 + q * 8];
            float4 v0 = ep[0];
            float4 v1 = ep[1];
            __half hv[8];
            hv[0] = __float2half_rn(v0.x); hv[1] = __float2half_rn(v0.y);
            hv[2] = __float2half_rn(v0.z); hv[3] = __float2half_rn(v0.w);
            hv[4] = __float2half_rn(v1.x); hv[5] = __float2half_rn(v1.y);
            hv[6] = __float2half_rn(v1.z); hv[7] = __float2half_rn(v1.w);
            *(uint4*)&sEs[el][q * 8] = *(uint4*)hv;
        }
        __syncthreads();
        // MMA: per warp C[16 ch][64 edges], 2 kb x 8 nb x 2 (hi/lo)
        float c[8][4];
#pragma unroll
        for (int nb = 0; nb < 8; nb++)
#pragma unroll
            for (int j = 0; j < 4; j++) c[nb][j] = 0.f;
#pragma unroll
        for (int kb = 0; kb < 2; kb++) {
#pragma unroll
            for (int nb = 0; nb < 8; nb++) {
                int col = nb * 8 + gid;
                uint32_t b0 = *(const uint32_t*)&sEs[col][kb * 16 + 2 * tig];
                uint32_t b1 = *(const uint32_t*)&sEs[col][kb * 16 + 2 * tig + 8];
                mma_f16(c[nb], ah[kb][0], ah[kb][1], ah[kb][2], ah[kb][3], b0, b1);
                mma_f16(c[nb], al[kb][0], al[kb][1], al[kb][2], al[kb][3], b0, b1);
            }
        }
        __syncthreads();
        // transpose C into sOut[edge][ch]
        {
            int ch = warp * 16 + gid;
#pragma unroll
            for (int nb = 0; nb < 8; nb++) {
                int e = nb * 8 + 2 * tig;
                sOut[e][ch] = c[nb][0];
                sOut[e + 1][ch] = c[nb][1];
                sOut[e][ch + 8] = c[nb][2];
                sOut[e + 1][ch + 8] = c[nb][3];
            }
        }
        __syncthreads();
        // epilogue: fp16 Hpre gather, fp16 store, stats on rounded values
#pragma unroll 2
        for (int ee = 0; ee < 8; ee++) {
            int e = warp * 8 + ee;
            int d = sDst[e], s = sSrc[e];
            float r = sR[e];
            uint2 du = *(const uint2*)&g_HpreH[(size_t)d * 256 + hd_off];
            uint2 su = *(const uint2*)&g_HpreH[(size_t)s * 256 + hs_off];
            float2 d01 = __half22float2(*(__half2*)&du.x);
            float2 d23 = __half22float2(*(__half2*)&du.y);
            float2 s01 = __half22float2(*(__half2*)&su.x);
            float2 s23 = __half22float2(*(__half2*)&su.y);
            float4 o = *(const float4*)&sOut[e][ch0];
            __half hv[4];
            hv[0] = __float2half_rn(o.x + d01.x + s01.x + fmaf(r, wr4[0], bb4[0]));
            hv[1] = __float2half_rn(o.y + d01.y + s01.y + fmaf(r, wr4[1], bb4[1]));
            hv[2] = __float2half_rn(o.z + d23.x + s23.x + fmaf(r, wr4[2], bb4[2]));
            hv[3] = __float2half_rn(o.w + d23.y + s23.y + fmaf(r, wr4[3], bb4[3]));
            int p = p0 + e;
            __half* out = (ch0 < 64) ? &g_t1h[(size_t)p * 64 + ch0]
                                     : &g_t2h[(size_t)p * 64 + ch0 - 64];
            *(uint2*)out = *(uint2*)hv;
#pragma unroll
            for (int j = 0; j < 4; j++) {
                float yr = __half2float(hv[j]);
                st[j] += yr; sq[j] += yr * yr;
            }
        }
    }
    __syncthreads();
#pragma unroll
    for (int j = 0; j < 4; j++) { atomicAdd(&sS[ch0 + j], st[j]); atomicAdd(&sQ[ch0 + j], sq[j]); }
    __syncthreads();
    if (tid < 128) {
        atomicAdd(&g_sum[tid], (double)sS[tid]);
        atomicAdd(&g_sumsq[tid], (double)sQ[tid]);
    }
}

// ---------------- BN finalize (self-resetting stats) ----------------
__global__ void k_bnfin(int off, int n, double inv,
                        const float* __restrict__ g0, const float* __restrict__ b0,
                        const float* __restrict__ g1, const float* __restrict__ b1)
{
    int c = threadIdx.x;
    if (c >= n) return;
    double m = g_sum[off + c] * inv;
    double v = g_sumsq[off + c] * inv - m * m;
    g_sum[off + c] = 0.0;
    g_sumsq[off + c] = 0.0;
    float gg = (c < 64) ? g0[c] : g1[c - 64];
    float bb = (c < 64) ? b0[c] : b1[c - 64];
    float A = gg * rsqrtf((float)v + EPS);
    g_bnA[off + c] = A;
    g_bnB[off + c] = bb - (float)m * A;
}

// ---------------- edge B (fp16 MMA, 256 thr): mlin = silu(bn(t1)) @ msg_w2^T + b ----------------
// 8 warps: m0=(warp&3)*16 out rows; n0=(warp>>2)*32 edges. K=64 (4 k16 steps).
__global__ __launch_bounds__(256) void k_edgeBmma(const float* __restrict__ mw2, const float* __restrict__ mb2,
                                                  const float* __restrict__ cw2, const float* __restrict__ cb2)
{
    __shared__ __align__(16) char sBuf[64 * 68 * 4];    // union: sX half[64][72]=9216B | sOut float[64][68]=17408B
    __half (*sX)[72] = (__half(*)[72])sBuf;
    float* sOut = (float*)sBuf;
    __shared__ float sS[64], sQ[64];
    __shared__ float sCA[64], sCB[64], sDA[64], sDB[64], sWc2[64];

    int tid = threadIdx.x;
    int warp = tid >> 5, lane = tid & 31;
    int gid = lane >> 2, tig = lane & 3;
    int m0 = (warp & 3) << 4;
    int n0 = (warp >> 2) << 5;

    if (tid < 64) {
        sS[tid] = 0.f; sQ[tid] = 0.f;
        sCA[tid] = g_bnA[tid];        sCB[tid] = g_bnB[tid];
        sDA[tid] = g_bnA[64 + tid];   sDB[tid] = g_bnB[64 + tid];
        sWc2[tid] = cw2[tid];
    }

    // weight A fragments (16 out x 64 k), fp16 hi/lo split
    uint32_t ah[4][4], al[4][4];
    {
        const float* w0 = mw2 + (size_t)(m0 + gid) * 64;
        const float* w1 = mw2 + (size_t)(m0 + gid + 8) * 64;
#pragma unroll
        for (int kb = 0; kb < 4; kb++) {
            int k0 = kb * 16 + 2 * tig;
            packsplit(w0[k0], w0[k0 + 1], ah[kb][0], al[kb][0]);
            packsplit(w1[k0], w1[k0 + 1], ah[kb][1], al[kb][1]);
            packsplit(w0[k0 + 8], w0[k0 + 9], ah[kb][2], al[kb][2]);
            packsplit(w1[k0 + 8], w1[k0 + 9], ah[kb][3], al[kb][3]);
        }
    }
    float bias0 = mb2[m0 + gid], bias1 = mb2[m0 + gid + 8];
    float cbias = cb2[0];
    float s0 = 0.f, q0 = 0.f, s1 = 0.f, q1 = 0.f;

    int el = tid >> 2, q = tid & 3;   // staging: edge el, channels [q*16, q*16+16)

    for (int t = blockIdx.x; t < NE / 64; t += gridDim.x) {
        int e0 = t << 6;
        __syncthreads();
        // stage X = silu(bn1(t1)) as fp16 (fp16 source)
        {
            const uint4* tb = (const uint4*)&g_t1h[(size_t)(e0 + el) * 64 + q * 16];
            __half2 hbuf[8];
            *(uint4*)&hbuf[0] = tb[0];
            *(uint4*)&hbuf[4] = tb[1];
            __half xv[16];
#pragma unroll
            for (int m = 0; m < 8; m++) {
                float2 f = __half22float2(hbuf[m]);
                int c = q * 16 + 2 * m;
                xv[2 * m]     = __float2half_rn(silu_f(fmaf(f.x, sCA[c], sCB[c])));
                xv[2 * m + 1] = __float2half_rn(silu_f(fmaf(f.y, sCA[c + 1], sCB[c + 1])));
            }
            *(uint4*)&sX[el][q * 16] = *(uint4*)&xv[0];
            *(uint4*)&sX[el][q * 16 + 8] = *(uint4*)&xv[8];
        }
        // coord head: 4 threads per edge, 16 ch each -> g_sc
        {
            const uint4* tb = (const uint4*)&g_t2h[(size_t)(e0 + el) * 64 + q * 16];
            __half2 hbuf[8];
            *(uint4*)&hbuf[0] = tb[0];
            *(uint4*)&hbuf[4] = tb[1];
            float part = 0.f;
#pragma unroll
            for (int m = 0; m < 8; m++) {
                float2 f = __half22float2(hbuf[m]);
                int c = q * 16 + 2 * m;
                part += silu_f(fmaf(f.x, sDA[c], sDB[c])) * sWc2[c];
                part += silu_f(fmaf(f.y, sDA[c + 1], sDB[c + 1])) * sWc2[c + 1];
            }
            part += __shfl_xor_sync(0xffffffffu, part, 1);
            part += __shfl_xor_sync(0xffffffffu, part, 2);
            if (q == 0) g_sc[e0 + el] = part + cbias;
        }
        __syncthreads();
        // MMA: per warp C[16 out][32 edges], 4 kb x 4 nb x 2 (hi/lo)
        float c[4][4];
#pragma unroll
        for (int nb = 0; nb < 4; nb++)
#pragma unroll
            for (int j = 0; j < 4; j++) c[nb][j] = 0.f;
#pragma unroll
        for (int kb = 0; kb < 4; kb++) {
#pragma unroll
            for (int nb = 0; nb < 4; nb++) {
                int col = n0 + nb * 8 + gid;
                uint32_t b0 = *(const uint32_t*)&sX[col][kb * 16 + 2 * tig];
                uint32_t b1 = *(const uint32_t*)&sX[col][kb * 16 + 2 * tig + 8];
                mma_f16(c[nb], ah[kb][0], ah[kb][1], ah[kb][2], ah[kb][3], b0, b1);
                mma_f16(c[nb], al[kb][0], al[kb][1], al[kb][2], al[kb][3], b0, b1);
            }
        }
        __syncthreads();
        // epilogue: bias + round-to-fp16 + stats, transpose through smem (union buffer)
#pragma unroll
        for (int nb = 0; nb < 4; nb++) {
            int e = n0 + nb * 8 + 2 * tig;
            float yr00 = __half2float(__float2half_rn(c[nb][0] + bias0));
            float yr01 = __half2float(__float2half_rn(c[nb][1] + bias0));
            float yr10 = __half2float(__float2half_rn(c[nb][2] + bias1));
            float yr11 = __half2float(__float2half_rn(c[nb][3] + bias1));
            sOut[e * 68 + m0 + gid] = yr00;
            sOut[(e + 1) * 68 + m0 + gid] = yr01;
            sOut[e * 68 + m0 + gid + 8] = yr10;
            sOut[(e + 1) * 68 + m0 + gid + 8] = yr11;
            s0 += yr00 + yr01; q0 += yr00 * yr00 + yr01 * yr01;
            s1 += yr10 + yr11; q1 += yr10 * yr10 + yr11 * yr11;
        }
        __syncthreads();
        // coalesced fp16 store
        {
            const float* src = &sOut[el * 68 + q * 16];
            __half hv[16];
#pragma unroll
            for (int m = 0; m < 16; m++) hv[m] = __float2half_rn(src[m]);
            uint4* dst = (uint4*)&g_mlinh[(size_t)(e0 + el) * 64 + q * 16];
            dst[0] = *(uint4*)&hv[0];
            dst[1] = *(uint4*)&hv[8];
        }
    }
    __syncthreads();
    atomicAdd(&sS[m0 + gid], s0); atomicAdd(&sQ[m0 + gid], q0);
    atomicAdd(&sS[m0 + gid + 8], s1); atomicAdd(&sQ[m0 + gid + 8], q1);
    __syncthreads();
    if (tid < 64) {
        atomicAdd(&g_sum[128 + tid], (double)sS[tid]);
        atomicAdd(&g_sumsq[128 + tid], (double)sQ[tid]);
    }
}

// ---------------- aggregation: warp per node, contiguous CSR rows (fp16 mlin) ----------------
__global__ __launch_bounds__(256) void k_aggr()
{
    int gwarp = (blockIdx.x * blockDim.x + threadIdx.x) >> 5;
    int lane = threadIdx.x & 31;
    if (gwarp >= NN) return;
    int n = gwarp;
    int s0 = g_rowstart[n], s1 = g_rowstart[n + 1];
    float A0 = g_bnA[128 + lane], B0 = g_bnB[128 + lane];
    float A1 = g_bnA[160 + lane], B1 = g_bnB[160 + lane];
    float acc0 = 0.f, acc1 = 0.f;
    for (int i = s0; i < s1; i++) {
        float m0 = __half2float(g_mlinh[(size_t)i * 64 + lane]);
        float m1 = __half2float(g_mlinh[(size_t)i * 64 + 32 + lane]);
        acc0 += silu_f(fmaf(m0, A0, B0));
        acc1 += silu_f(fmaf(m1, A1, B1));
    }
    g_u[(size_t)n * 128 + 64 + lane] = acc0;
    g_u[(size_t)n * 128 + 96 + lane] = acc1;
    float px = g_pos[n * 3], py = g_pos[n * 3 + 1], pz = g_pos[n * 3 + 2];
    float cx = 0.f, cy = 0.f, cz = 0.f;
    for (int i = s0 + lane; i < s1; i += 32) {
        int src = g_csrsrc[i];
        float sc = g_sc[i];
        cx += sc * (px - g_pos[src * 3]);
        cy += sc * (py - g_pos[src * 3 + 1]);
        cz += sc * (pz - g_pos[src * 3 + 2]);
    }
#pragma unroll
    for (int o = 16; o > 0; o >>= 1) {
        cx += __shfl_xor_sync(0xffffffffu, cx, o);
        cy += __shfl_xor_sync(0xffffffffu, cy, o);
        cz += __shfl_xor_sync(0xffffffffu, cz, o);
    }
    if (lane == 0) {
        g_aggr_p[n * 3 + 0] = cx;
        g_aggr_p[n * 3 + 1] = cy;
        g_aggr_p[n * 3 + 2] = cz;
    }
}

// ---------------- node 1: tiled 64n x 64o, K=128 ----------------
__global__ __launch_bounds__(256) void k_node1(const float* __restrict__ uw1, const float* __restrict__ ub1)
{
    __shared__ __align__(16) float sW[64][64];
    __shared__ __align__(16) float sA[64][64];
    __shared__ float sS[64], sQ[64];
    int tid = threadIdx.x, tx = tid & 15, ty = tid >> 4;
    if (tid < 64) { sS[tid] = 0.f; sQ[tid] = 0.f; }
    float bb[4];
#pragma unroll
    for (int j = 0; j < 4; j++) bb[j] = ub1[(ty << 2) + j];
    float st[4] = {0.f, 0.f, 0.f, 0.f}, sq[4] = {0.f, 0.f, 0.f, 0.f};
    int ntiles = (NN + 63) >> 6;
    for (int t = blockIdx.x; t < ntiles; t += gridDim.x) {
        int n0 = t << 6;
        float acc[4][4];
#pragma unroll
        for (int i = 0; i < 4; i++)
#pragma unroll
            for (int j = 0; j < 4; j++) acc[i][j] = 0.f;
        for (int half = 0; half < 2; half++) {
            __syncthreads();
            for (int i = tid; i < 1024; i += 256) {
                int o = i & 63, k0 = (i >> 6) << 2;
                float4 v = *(const float4*)&uw1[o * 128 + half * 64 + k0];
                sW[k0 + 0][o] = v.x; sW[k0 + 1][o] = v.y;
                sW[k0 + 2][o] = v.z; sW[k0 + 3][o] = v.w;
            }
            {
                int nn = tid >> 2, k0 = (tid & 3) << 4;
                int n = n0 + nn;
#pragma unroll
                for (int m = 0; m < 4; m++) {
                    float4 v = (n < NN) ? *(const float4*)&g_u[(size_t)n * 128 + half * 64 + k0 + 4 * m]
                                        : make_float4(0.f, 0.f, 0.f, 0.f);
                    sA[k0 + 4 * m + 0][nn] = v.x;
                    sA[k0 + 4 * m + 1][nn] = v.y;
                    sA[k0 + 4 * m + 2][nn] = v.z;
                    sA[k0 + 4 * m + 3][nn] = v.w;
                }
            }
            __syncthreads();
#pragma unroll 4
            for (int k = 0; k < 64; k++) {
                float4 a = *(const float4*)&sA[k][tx << 2];
                float4 b = *(const float4*)&sW[k][ty << 2];
                float av[4] = {a.x, a.y, a.z, a.w};
                float bv[4] = {b.x, b.y, b.z, b.w};
#pragma unroll
                for (int i = 0; i < 4; i++)
#pragma unroll
                    for (int j = 0; j < 4; j++) acc[i][j] = fmaf(av[i], bv[j], acc[i][j]);
            }
        }
#pragma unroll
        for (int i = 0; i < 4; i++) {
            int n = n0 + (tx << 2) + i;
            if (n < NN) {
                float y0 = acc[i][0] + bb[0], y1 = acc[i][1] + bb[1];
                float y2 = acc[i][2] + bb[2], y3 = acc[i][3] + bb[3];
                *(float4*)&g_un[n * 64 + (ty << 2)] = make_float4(y0, y1, y2, y3);
                st[0] += y0; sq[0] += y0 * y0; st[1] += y1; sq[1] += y1 * y1;
                st[2] += y2; sq[2] += y2 * y2; st[3] += y3; sq[3] += y3 * y3;
            }
        }
    }
    __syncthreads();
#pragma unroll
    for (int j = 0; j < 4; j++) {
        atomicAdd(&sS[(ty << 2) + j], st[j]);
        atomicAdd(&sQ[(ty << 2) + j], sq[j]);
    }
    __syncthreads();
    if (tid < 64) {
        atomicAdd(&g_sum[192 + tid], (double)sS[tid]);
        atomicAdd(&g_sumsq[192 + tid], (double)sQ[tid]);
    }
}

// ---------------- node 2: tiled 64n x 64o, K=64; residual + pos update ----------------
__global__ __launch_bounds__(256) void k_node2(const float* __restrict__ uw2, const float* __restrict__ ub2)
{
    __shared__ __align__(16) float sW[64][64];
    __shared__ __align__(16) float sA[64][64];
    int tid = threadIdx.x, tx = tid & 15, ty = tid >> 4;
    for (int i = tid; i < 1024; i += 256) {
        int o = i & 63, k0 = (i >> 6) << 2;
        float4 v = *(const float4*)&uw2[o * 64 + k0];
        sW[k0 + 0][o] = v.x; sW[k0 + 1][o] = v.y;
        sW[k0 + 2][o] = v.z; sW[k0 + 3][o] = v.w;
    }
    int k0s = (tid & 3) << 4;
    float4 cA[4], cB[4];
#pragma unroll
    for (int m = 0; m < 4; m++) {
        cA[m] = *(const float4*)&g_bnA[192 + k0s + 4 * m];
        cB[m] = *(const float4*)&g_bnB[192 + k0s + 4 * m];
    }
    float bb[4];
#pragma unroll
    for (int j = 0; j < 4; j++) bb[j] = ub2[(ty << 2) + j];
    int ntiles = (NN + 63) >> 6;
    for (int t = blockIdx.x; t < ntiles; t += gridDim.x) {
        int n0 = t << 6;
        __syncthreads();
        {
            int nn = tid >> 2;
            int n = n0 + nn;
#pragma unroll
            for (int m = 0; m < 4; m++) {
                float4 v = (n < NN) ? *(const float4*)&g_un[(size_t)n * 64 + k0s + 4 * m]
                                    : make_float4(0.f, 0.f, 0.f, 0.f);
                sA[k0s + 4 * m + 0][nn] = silu_f(fmaf(v.x, cA[m].x, cB[m].x));
                sA[k0s + 4 * m + 1][nn] = silu_f(fmaf(v.y, cA[m].y, cB[m].y));
                sA[k0s + 4 * m + 2][nn] = silu_f(fmaf(v.z, cA[m].z, cB[m].z));
                sA[k0s + 4 * m + 3][nn] = silu_f(fmaf(v.w, cA[m].w, cB[m].w));
            }
        }
        __syncthreads();
        float acc[4][4];
#pragma unroll
        for (int i = 0; i < 4; i++)
#pragma unroll
            for (int j = 0; j < 4; j++) acc[i][j] = 0.f;
#pragma unroll 4
        for (int k = 0; k < 64; k++) {
            float4 a = *(const float4*)&sA[k][tx << 2];
            float4 b = *(const float4*)&sW[k][ty << 2];
            float av[4] = {a.x, a.y, a.z, a.w};
            float bv[4] = {b.x, b.y, b.z, b.w};
#pragma unroll
            for (int i = 0; i < 4; i++)
#pragma unroll
                for (int j = 0; j < 4; j++) acc[i][j] = fmaf(av[i], bv[j], acc[i][j]);
        }
#pragma unroll
        for (int i = 0; i < 4; i++) {
            int n = n0 + (tx << 2) + i;
            if (n < NN) {
                float4 hold = *(const float4*)&g_h[n * 64 + (ty << 2)];
                float h0 = hold.x + acc[i][0] + bb[0];
                float h1 = hold.y + acc[i][1] + bb[1];
                float h2 = hold.z + acc[i][2] + bb[2];
                float h3 = hold.w + acc[i][3] + bb[3];
                float4 hv = make_float4(h0, h1, h2, h3);
                *(float4*)&g_h[n * 64 + (ty << 2)] = hv;
                *(float4*)&g_u[(size_t)n * 128 + (ty << 2)] = hv;
            }
        }
        if (tid < 64) {
            int n = n0 + tid;
            if (n < NN) {
                g_pos[n * 3 + 0] += g_aggr_p[n * 3 + 0];
                g_pos[n * 3 + 1] += g_aggr_p[n * 3 + 1];
                g_pos[n * 3 + 2] += g_aggr_p[n * 3 + 2];
            }
        }
    }
}

// ---------------- pooling ----------------
__global__ void k_pool(const int* __restrict__ batch)
{
    int idx = blockIdx.x * blockDim.x + threadIdx.x;
    if (idx >= NN * 16) return;
    int n = idx >> 4, c4 = (idx & 15) * 4;
    int b = batch[n];
    float4 h = *(const float4*)&g_h[n * 64 + c4];
    red_add_v4(&g_pool[b * 64 + c4], h.x, h.y, h.z, h.w);
    if (c4 == 0) atomicAdd(&g_cnt[b], 1.0f);
}

__global__ void k_pred(const float* __restrict__ w, const float* __restrict__ b,
                       float* __restrict__ out)
{
    int g = blockIdx.x, lane = threadIdx.x;
    float p = g_pool[g * 64 + lane] * w[lane] + g_pool[g * 64 + 32 + lane] * w[32 + lane];
#pragma unroll
    for (int o = 16; o > 0; o >>= 1) p += __shfl_xor_sync(0xffffffffu, p, o);
    if (lane == 0) out[g] = p / fmaxf(g_cnt[g], 1.0f) + b[0];
}

// ---------------- launch ----------------
extern "C" void kernel_launch(void* const* d_in, const int* in_sizes, int n_in,
                              void* d_out, int out_size)
{
    const float* node_s    = (const float*)d_in[0];
    const float* node_type = (const float*)d_in[1];
    const float* pos       = (const float*)d_in[2];
    const int*   ei        = (const int*)d_in[3];
    const float* edge_s    = (const float*)d_in[4];
    const int*   batch     = (const int*)d_in[5];
    const float* lin_in_w  = (const float*)d_in[6];
    const float* lin_in_b  = (const float*)d_in[7];
    const float* msg_w1    = (const float*)d_in[8];
    const float* msg_b1    = (const float*)d_in[9];
    const float* msg_g1    = (const float*)d_in[10];
    const float* msg_be1   = (const float*)d_in[11];
    const float* msg_w2    = (const float*)d_in[12];
    const float* msg_b2    = (const float*)d_in[13];
    const float* msg_g2    = (const float*)d_in[14];
    const float* msg_be2   = (const float*)d_in[15];
    const float* updf_w1   = (const float*)d_in[16];
    const float* updf_b1   = (const float*)d_in[17];
    const float* updf_g1   = (const float*)d_in[18];
    const float* updf_be1  = (const float*)d_in[19];
    const float* updf_w2   = (const float*)d_in[20];
    const float* updf_b2   = (const float*)d_in[21];
    const float* updc_w1   = (const float*)d_in[22];
    const float* updc_b1   = (const float*)d_in[23];
    const float* updc_g1   = (const float*)d_in[24];
    const float* updc_be1  = (const float*)d_in[25];
    const float* updc_w2   = (const float*)d_in[26];
    const float* updc_b2   = (const float*)d_in[27];
    const float* lin_pred_w = (const float*)d_in[28];
    const float* lin_pred_b = (const float*)d_in[29];

    k_init<<<(NN * 64 + 255) / 256, 256>>>(node_s, node_type, pos, lin_in_w, lin_in_b);
    k_hist<<<(NE + 255) / 256, 256>>>(ei);
    k_scan<<<1, 1024>>>();
    k_fill<<<(NE + 255) / 256, 256>>>(ei);
    k_wpack_all<<<(NL * 64 * 256 + 255) / 256, 256>>>(msg_w1, updc_w1);

    for (int l = 0; l < NL; l++) {
        const float* mw1 = msg_w1 + (size_t)l * 64 * 161;
        const float* mb1 = msg_b1 + l * 64;
        const float* mw2 = msg_w2 + (size_t)l * 64 * 64;
        const float* mb2 = msg_b2 + l * 64;
        const float* cw1 = updc_w1 + (size_t)l * 64 * 161;
        const float* cb1 = updc_b1 + l * 64;
        const float* cw2 = updc_w2 + (size_t)l * 64;
        const float* cb2 = updc_b2 + l;
        const float* uw1 = updf_w1 + (size_t)l * 64 * 128;
        const float* ub1 = updf_b1 + l * 64;
        const float* uw2 = updf_w2 + (size_t)l * 64 * 64;
        const float* ub2 = updf_b2 + l * 64;

        k_hpre<<<592, 256>>>(l);
        k_edgeAmma<<<592, 256>>>(edge_s, mw1, mb1, cw1, cb1);
        k_bnfin<<<1, 128>>>(0, 128, 1.0 / NE,
                            msg_g1 + l * 64, msg_be1 + l * 64,
                            updc_g1 + l * 64, updc_be1 + l * 64);
        k_edgeBmma<<<592, 256>>>(mw2, mb2, cw2, cb2);
        k_bnfin<<<1, 64>>>(128, 64, 1.0 / NE,
                           msg_g2 + l * 64, msg_be2 + l * 64,
                           msg_g2 + l * 64, msg_be2 + l * 64);
        k_aggr<<<(NN * 32 + 255) / 256, 256>>>();
        k_node1<<<592, 256>>>(uw1, ub1);
        k_bnfin<<<1, 64>>>(192, 64, 1.0 / NN,
                           updf_g1 + l * 64, updf_be1 + l * 64,
                           updf_g1 + l * 64, updf_be1 + l * 64);
        k_node2<<<592, 256>>>(uw2, ub2);
    }

    k_pool<<<(NN * 16 + 255) / 256, 256>>>(batch);
    k_pred<<<NG, 32>>>(lin_pred_w, lin_pred_b, (float*)d_out);
}

// round 13
// speedup vs baseline: 1.0441x; 1.0441x over previous
#include <cuda_runtime.h>
#include <cuda_fp16.h>
#include <math.h>
#include <stdint.h>

#define NN 50000
#define NE 800000
#define NL 4
#define NG 64
#define EPS 1e-5f

// ---------------- static device scratch ----------------
__device__ __align__(16) float g_h[NN * 64];
__device__ __align__(16) float g_u[NN * 128];      // [h | aggr_h]
__device__ __align__(16) float g_un[NN * 64];
__device__ __align__(16) float g_pos[NN * 3];
__device__ __align__(16) float g_aggr_p[NN * 3];
__device__ __align__(16) __half g_HpreH[(size_t)NN * 256];   // fp16, 25.6MB
__device__ __align__(16) float g_wpack4[NL][64 * 256];       // k-major [k][op]
__device__ __align__(16) __half g_esh[(size_t)NE * 32];      // edge_s, CSR-ordered fp16
__device__ __align__(16) __half g_t1h[(size_t)NE * 64];      // CSR-ordered, fp16
__device__ __align__(16) __half g_t2h[(size_t)NE * 64];      // CSR-ordered, fp16
__device__ __align__(16) __half g_mlinh[(size_t)NE * 64];    // CSR-ordered, fp16
__device__ __align__(16) float g_sc[NE];                     // CSR-ordered
__device__ int g_deg[NN];
__device__ int g_rowstart[NN + 1];
__device__ int g_cursor[NN];
__device__ int g_csrsrc[NE];
__device__ int g_csrdst[NE];
__device__ int g_csre[NE];
__device__ double g_sum[NL * 256];    // per-layer stats slots (no reset needed)
__device__ double g_sumsq[NL * 256];
__device__ __align__(16) float g_pool[NG * 64];
__device__ float g_cnt[NG];

__device__ __forceinline__ float silu_f(float y) {
    return y * (1.0f / (1.0f + __expf(-y)));
}

__device__ __forceinline__ void red_add_v4(float* p, float a, float b, float c, float d) {
    asm volatile("red.global.add.v4.f32 [%0], {%1,%2,%3,%4};"
                 :: "l"(p), "f"(a), "f"(b), "f"(c), "f"(d) : "memory");
}

// fp16 m16n8k16 MMA, fp32 accumulate
__device__ __forceinline__ void mma_f16(float* c, uint32_t a0, uint32_t a1, uint32_t a2, uint32_t a3,
                                        uint32_t b0, uint32_t b1) {
    asm volatile("mma.sync.aligned.m16n8k16.row.col.f32.f16.f16.f32 "
                 "{%0,%1,%2,%3}, {%4,%5,%6,%7}, {%8,%9}, {%0,%1,%2,%3};"
                 : "+f"(c[0]), "+f"(c[1]), "+f"(c[2]), "+f"(c[3])
                 : "r"(a0), "r"(a1), "r"(a2), "r"(a3), "r"(b0), "r"(b1));
}

__device__ __forceinline__ void packsplit(float x, float y, uint32_t& h, uint32_t& l) {
    __half hx = __float2half_rn(x), hy = __float2half_rn(y);
    __half lx = __float2half_rn(x - __half2float(hx));
    __half ly = __float2half_rn(y - __half2float(hy));
    __half2 hh = __halves2half2(hx, hy), ll = __halves2half2(lx, ly);
    h = *(uint32_t*)&hh; l = *(uint32_t*)&ll;
}

// ---------------- init ----------------
__global__ void k_init(const float* __restrict__ ns, const float* __restrict__ nt,
                       const float* __restrict__ pos, const float* __restrict__ w,
                       const float* __restrict__ b)
{
    int idx = blockIdx.x * blockDim.x + threadIdx.x;
    if (idx < NG * 64) g_pool[idx] = 0.f;
    if (idx < NG) g_cnt[idx] = 0.f;
    if (idx < NL * 256) { g_sum[idx] = 0.0; g_sumsq[idx] = 0.0; }
    if (idx < NN) g_deg[idx] = 0;
    if (idx >= NN * 64) return;
    int n = idx >> 6, o = idx & 63;
    const float* wr = w + o * 8;
    const float* s = ns + n * 6;
    float acc = b[o];
#pragma unroll
    for (int i = 0; i < 6; i++) acc = fmaf(s[i], wr[i], acc);
    acc = fmaf(nt[n * 2 + 0], wr[6], acc);
    acc = fmaf(nt[n * 2 + 1], wr[7], acc);
    g_h[idx] = acc;
    g_u[(size_t)n * 128 + o] = acc;
    if (o < 3) g_pos[n * 3 + o] = pos[n * 3 + o];
}

// ---------------- CSR build ----------------
__global__ void k_hist(const int* __restrict__ ei)
{
    int e = blockIdx.x * blockDim.x + threadIdx.x;
    if (e < NE) atomicAdd(&g_deg[ei[NE + e]], 1);
}

__global__ __launch_bounds__(1024) void k_scan()
{
    __shared__ int ssum[1024];
    int t = threadIdx.x;
    const int C = 49;
    int begin = t * C;
    int end = begin + C; if (end > NN) end = NN;
    if (begin > NN) begin = NN;
    int s = 0;
    for (int i = begin; i < end; i++) s += g_deg[i];
    ssum[t] = s;
    __syncthreads();
    for (int off = 1; off < 1024; off <<= 1) {
        int v = (t >= off) ? ssum[t - off] : 0;
        __syncthreads();
        ssum[t] += v;
        __syncthreads();
    }
    int run = ssum[t] - s;
    for (int i = begin; i < end; i++) {
        g_rowstart[i] = run;
        g_cursor[i] = run;
        run += g_deg[i];
    }
    if (t == 1023) g_rowstart[NN] = ssum[1023];
}

__global__ void k_fill(const int* __restrict__ ei)
{
    int e = blockIdx.x * blockDim.x + threadIdx.x;
    if (e >= NE) return;
    int s = ei[e], d = ei[NE + e];
    int p = atomicAdd(&g_cursor[d], 1);
    g_csrsrc[p] = s;
    g_csrdst[p] = d;
    g_csre[p] = e;
}

// ---------------- permute edge_s into CSR order as fp16 (once per launch) ----------------
__global__ void k_esperm(const float* __restrict__ es)
{
    int idx = blockIdx.x * blockDim.x + threadIdx.x;
    if (idx >= NE * 4) return;
    int p = idx >> 2, q = idx & 3;
    int eid = g_csre[p];
    const float4* ep = (const float4*)&es[(size_t)eid * 32 + q * 8];
    float4 v0 = ep[0], v1 = ep[1];
    __half hv[8];
    hv[0] = __float2half_rn(v0.x); hv[1] = __float2half_rn(v0.y);
    hv[2] = __float2half_rn(v0.z); hv[3] = __float2half_rn(v0.w);
    hv[4] = __float2half_rn(v1.x); hv[5] = __float2half_rn(v1.y);
    hv[6] = __float2half_rn(v1.z); hv[7] = __float2half_rn(v1.w);
    *(uint4*)&g_esh[(size_t)p * 32 + q * 8] = *(uint4*)hv;
}

// ---------------- pack h-columns of msg_w1/updc_w1 for ALL layers ----------------
__global__ void k_wpack_all(const float* __restrict__ mw1a, const float* __restrict__ cw1a)
{
    int idx = blockIdx.x * blockDim.x + threadIdx.x;
    if (idx >= NL * 64 * 256) return;
    int l = idx >> 14;
    int r = idx & 16383;
    int k = r >> 8, op = r & 255, o = op & 63;
    const float* mw1 = mw1a + (size_t)l * 64 * 161;
    const float* cw1 = cw1a + (size_t)l * 64 * 161;
    float v;
    if (op < 64)       v = mw1[o * 161 + k];
    else if (op < 128) v = mw1[o * 161 + 64 + k];
    else if (op < 192) v = cw1[o * 161 + k];
    else               v = cw1[o * 161 + 64 + k];
    g_wpack4[l][k * 256 + op] = v;
}

// ---------------- Hpre: tiled GEMM 64n x 128o (2 phases), K=64; fp16 output ----------------
__global__ __launch_bounds__(256) void k_hpre(int layer)
{
    const float* wpack = g_wpack4[layer];
    __shared__ __align__(16) float sA[64][64];
    __shared__ __align__(16) float sB[64][128];
    int tid = threadIdx.x, tx = tid & 15, ty = tid >> 4;
    int ntiles = (NN + 63) >> 6;
    for (int t = blockIdx.x; t < ntiles; t += gridDim.x) {
        int n0 = t << 6;
        __syncthreads();
        {
            int nn = tid >> 2, k0 = (tid & 3) << 4;
            int n = n0 + nn;
#pragma unroll
            for (int m = 0; m < 4; m++) {
                float4 v = (n < NN) ? *(const float4*)&g_h[n * 64 + k0 + 4 * m]
                                    : make_float4(0.f, 0.f, 0.f, 0.f);
                sA[k0 + 4 * m + 0][nn] = v.x;
                sA[k0 + 4 * m + 1][nn] = v.y;
                sA[k0 + 4 * m + 2][nn] = v.z;
                sA[k0 + 4 * m + 3][nn] = v.w;
            }
        }
        for (int ph = 0; ph < 2; ph++) {
            __syncthreads();
#pragma unroll
            for (int r = 0; r < 8; r++) {
                int i = tid + r * 256;
                int k = i >> 5, o4 = (i & 31) << 2;
                *(float4*)&sB[k][o4] = *(const float4*)&wpack[k * 256 + ph * 128 + o4];
            }
            __syncthreads();
            float acc[4][8];
#pragma unroll
            for (int i = 0; i < 4; i++)
#pragma unroll
                for (int j = 0; j < 8; j++) acc[i][j] = 0.f;
#pragma unroll 4
            for (int k = 0; k < 64; k++) {
                float4 a = *(const float4*)&sA[k][tx << 2];
                float4 b0 = *(const float4*)&sB[k][ty << 3];
                float4 b1 = *(const float4*)&sB[k][(ty << 3) + 4];
                float av[4] = {a.x, a.y, a.z, a.w};
                float bv[8] = {b0.x, b0.y, b0.z, b0.w, b1.x, b1.y, b1.z, b1.w};
#pragma unroll
                for (int i = 0; i < 4; i++)
#pragma unroll
                    for (int j = 0; j < 8; j++) acc[i][j] = fmaf(av[i], bv[j], acc[i][j]);
            }
#pragma unroll
            for (int i = 0; i < 4; i++) {
                int n = n0 + (tx << 2) + i;
                if (n < NN) {
                    __half hv[8];
#pragma unroll
                    for (int j = 0; j < 8; j++) hv[j] = __float2half_rn(acc[i][j]);
                    *(uint4*)&g_HpreH[(size_t)n * 256 + ph * 128 + (ty << 3)] = *(uint4*)hv;
                }
            }
        }
    }
}

// ---------------- edge A (fp16 MMA, CSR order) ----------------
__global__ __launch_bounds__(256) void k_edgeAmma(int layer,
                                                  const float* __restrict__ mw1, const float* __restrict__ mb1,
                                                  const float* __restrict__ cw1, const float* __restrict__ cb1)
{
    __shared__ __align__(16) char sBuf[64 * 132 * 4];   // union: sEs half[64][40] | sOut float[64][132]
    __half (*sEs)[40] = (__half(*)[40])sBuf;
    float (*sOut)[132] = (float(*)[132])sBuf;
    __shared__ float sR[64];
    __shared__ int sSrc[64], sDst[64];
    __shared__ float sS[128], sQ[128];

    int tid = threadIdx.x;
    int warp = tid >> 5, lane = tid & 31;
    int gid = lane >> 2, tig = lane & 3;
    int sl = layer * 256;

    if (tid < 128) { sS[tid] = 0.f; sQ[tid] = 0.f; }

    uint32_t ah[2][4], al[2][4];
    {
        int r0 = warp * 16 + gid;
        int r1 = r0 + 8;
        const float* w0 = (r0 < 64) ? &mw1[r0 * 161 + 129] : &cw1[(r0 - 64) * 161 + 129];
        const float* w1 = (r1 < 64) ? &mw1[r1 * 161 + 129] : &cw1[(r1 - 64) * 161 + 129];
#pragma unroll
        for (int kb = 0; kb < 2; kb++) {
            int k0 = kb * 16 + 2 * tig;
            packsplit(w0[k0], w0[k0 + 1], ah[kb][0], al[kb][0]);
            packsplit(w1[k0], w1[k0 + 1], ah[kb][1], al[kb][1]);
            packsplit(w0[k0 + 8], w0[k0 + 9], ah[kb][2], al[kb][2]);
            packsplit(w1[k0 + 8], w1[k0 + 9], ah[kb][3], al[kb][3]);
        }
    }
    int ch0 = lane << 2;
    float wr4[4], bb4[4];
#pragma unroll
    for (int j = 0; j < 4; j++) {
        int ch = ch0 + j;
        wr4[j] = (ch < 64) ? mw1[ch * 161 + 128] : cw1[(ch - 64) * 161 + 128];
        bb4[j] = (ch < 64) ? mb1[ch] : cb1[ch - 64];
    }
    int hd_off = (ch0 < 64) ? ch0 : 64 + ch0;
    int hs_off = (ch0 < 64) ? 64 + ch0 : 128 + ch0;
    float st[4] = {0.f, 0.f, 0.f, 0.f}, sq[4] = {0.f, 0.f, 0.f, 0.f};

    for (int t = blockIdx.x; t < NE / 64; t += gridDim.x) {
        int p0 = t << 6;
        __syncthreads();
        if (tid < 64) {
            int p = p0 + tid;
            int s = g_csrsrc[p], d = g_csrdst[p];
            sSrc[tid] = s; sDst[tid] = d;
            float dx = g_pos[d * 3] - g_pos[s * 3];
            float dy = g_pos[d * 3 + 1] - g_pos[s * 3 + 1];
            float dz = g_pos[d * 3 + 2] - g_pos[s * 3 + 2];
            sR[tid] = sqrtf(dx * dx + dy * dy + dz * dz);
        }
        // stage es: contiguous fp16 copy
        {
            int el = tid >> 2, q = tid & 3;
            *(uint4*)&sEs[el][q * 8] = *(const uint4*)&g_esh[(size_t)(p0 + el) * 32 + q * 8];
        }
        __syncthreads();
        float c[8][4];
#pragma unroll
        for (int nb = 0; nb < 8; nb++)
#pragma unroll
            for (int j = 0; j < 4; j++) c[nb][j] = 0.f;
#pragma unroll
        for (int kb = 0; kb < 2; kb++) {
#pragma unroll
            for (int nb = 0; nb < 8; nb++) {
                int col = nb * 8 + gid;
                uint32_t b0 = *(const uint32_t*)&sEs[col][kb * 16 + 2 * tig];
                uint32_t b1 = *(const uint32_t*)&sEs[col][kb * 16 + 2 * tig + 8];
                mma_f16(c[nb], ah[kb][0], ah[kb][1], ah[kb][2], ah[kb][3], b0, b1);
                mma_f16(c[nb], al[kb][0], al[kb][1], al[kb][2], al[kb][3], b0, b1);
            }
        }
        __syncthreads();
        {
            int ch = warp * 16 + gid;
#pragma unroll
            for (int nb = 0; nb < 8; nb++) {
                int e = nb * 8 + 2 * tig;
                sOut[e][ch] = c[nb][0];
                sOut[e + 1][ch] = c[nb][1];
                sOut[e][ch + 8] = c[nb][2];
                sOut[e + 1][ch + 8] = c[nb][3];
            }
        }
        __syncthreads();
#pragma unroll 2
        for (int ee = 0; ee < 8; ee++) {
            int e = warp * 8 + ee;
            int d = sDst[e], s = sSrc[e];
            float r = sR[e];
            uint2 du = *(const uint2*)&g_HpreH[(size_t)d * 256 + hd_off];
            uint2 su = *(const uint2*)&g_HpreH[(size_t)s * 256 + hs_off];
            float2 d01 = __half22float2(*(__half2*)&du.x);
            float2 d23 = __half22float2(*(__half2*)&du.y);
            float2 s01 = __half22float2(*(__half2*)&su.x);
            float2 s23 = __half22float2(*(__half2*)&su.y);
            float4 o = *(const float4*)&sOut[e][ch0];
            __half hv[4];
            hv[0] = __float2half_rn(o.x + d01.x + s01.x + fmaf(r, wr4[0], bb4[0]));
            hv[1] = __float2half_rn(o.y + d01.y + s01.y + fmaf(r, wr4[1], bb4[1]));
            hv[2] = __float2half_rn(o.z + d23.x + s23.x + fmaf(r, wr4[2], bb4[2]));
            hv[3] = __float2half_rn(o.w + d23.y + s23.y + fmaf(r, wr4[3], bb4[3]));
            int p = p0 + e;
            __half* out = (ch0 < 64) ? &g_t1h[(size_t)p * 64 + ch0]
                                     : &g_t2h[(size_t)p * 64 + ch0 - 64];
            *(uint2*)out = *(uint2*)hv;
#pragma unroll
            for (int j = 0; j < 4; j++) {
                float yr = __half2float(hv[j]);
                st[j] += yr; sq[j] += yr * yr;
            }
        }
    }
    __syncthreads();
#pragma unroll
    for (int j = 0; j < 4; j++) { atomicAdd(&sS[ch0 + j], st[j]); atomicAdd(&sQ[ch0 + j], sq[j]); }
    __syncthreads();
    if (tid < 128) {
        atomicAdd(&g_sum[sl + tid], (double)sS[tid]);
        atomicAdd(&g_sumsq[sl + tid], (double)sQ[tid]);
    }
}

// ---------------- edge B (fp16 MMA, 256 thr): BN computed locally from stats ----------------
__global__ __launch_bounds__(256) void k_edgeBmma(int layer,
                                                  const float* __restrict__ mg1, const float* __restrict__ mbe1,
                                                  const float* __restrict__ cg1, const float* __restrict__ cbe1,
                                                  const float* __restrict__ mw2, const float* __restrict__ mb2,
                                                  const float* __restrict__ cw2, const float* __restrict__ cb2)
{
    __shared__ __align__(16) char sBuf[64 * 68 * 4];
    __half (*sX)[72] = (__half(*)[72])sBuf;
    float* sOut = (float*)sBuf;
    __shared__ float sS[64], sQ[64];
    __shared__ float sCA[64], sCB[64], sDA[64], sDB[64], sWc2[64];

    int tid = threadIdx.x;
    int warp = tid >> 5, lane = tid & 31;
    int gid = lane >> 2, tig = lane & 3;
    int m0 = (warp & 3) << 4;
    int n0 = (warp >> 2) << 5;
    int sl = layer * 256;

    // compute BN coeffs from stats (edgeA complete by stream order)
    if (tid < 64) {
        double m = g_sum[sl + tid] * (1.0 / NE);
        double v = g_sumsq[sl + tid] * (1.0 / NE) - m * m;
        float A = mg1[tid] * rsqrtf((float)v + EPS);
        sCA[tid] = A; sCB[tid] = mbe1[tid] - (float)m * A;
        sS[tid] = 0.f; sQ[tid] = 0.f;
        sWc2[tid] = cw2[tid];
    } else if (tid < 128) {
        int c = tid - 64;
        double m = g_sum[sl + 64 + c] * (1.0 / NE);
        double v = g_sumsq[sl + 64 + c] * (1.0 / NE) - m * m;
        float A = cg1[c] * rsqrtf((float)v + EPS);
        sDA[c] = A; sDB[c] = cbe1[c] - (float)m * A;
    }

    uint32_t ah[4][4], al[4][4];
    {
        const float* w0 = mw2 + (size_t)(m0 + gid) * 64;
        const float* w1 = mw2 + (size_t)(m0 + gid + 8) * 64;
#pragma unroll
        for (int kb = 0; kb < 4; kb++) {
            int k0 = kb * 16 + 2 * tig;
            packsplit(w0[k0], w0[k0 + 1], ah[kb][0], al[kb][0]);
            packsplit(w1[k0], w1[k0 + 1], ah[kb][1], al[kb][1]);
            packsplit(w0[k0 + 8], w0[k0 + 9], ah[kb][2], al[kb][2]);
            packsplit(w1[k0 + 8], w1[k0 + 9], ah[kb][3], al[kb][3]);
        }
    }
    float bias0 = mb2[m0 + gid], bias1 = mb2[m0 + gid + 8];
    float cbias = cb2[0];
    float s0 = 0.f, q0 = 0.f, s1 = 0.f, q1 = 0.f;

    int el = tid >> 2, q = tid & 3;

    for (int t = blockIdx.x; t < NE / 64; t += gridDim.x) {
        int e0 = t << 6;
        __syncthreads();
        {
            const uint4* tb = (const uint4*)&g_t1h[(size_t)(e0 + el) * 64 + q * 16];
            __half2 hbuf[8];
            *(uint4*)&hbuf[0] = tb[0];
            *(uint4*)&hbuf[4] = tb[1];
            __half xv[16];
#pragma unroll
            for (int m = 0; m < 8; m++) {
                float2 f = __half22float2(hbuf[m]);
                int c = q * 16 + 2 * m;
                xv[2 * m]     = __float2half_rn(silu_f(fmaf(f.x, sCA[c], sCB[c])));
                xv[2 * m + 1] = __float2half_rn(silu_f(fmaf(f.y, sCA[c + 1], sCB[c + 1])));
            }
            *(uint4*)&sX[el][q * 16] = *(uint4*)&xv[0];
            *(uint4*)&sX[el][q * 16 + 8] = *(uint4*)&xv[8];
        }
        {
            const uint4* tb = (const uint4*)&g_t2h[(size_t)(e0 + el) * 64 + q * 16];
            __half2 hbuf[8];
            *(uint4*)&hbuf[0] = tb[0];
            *(uint4*)&hbuf[4] = tb[1];
            float part = 0.f;
#pragma unroll
            for (int m = 0; m < 8; m++) {
                float2 f = __half22float2(hbuf[m]);
                int c = q * 16 + 2 * m;
                part += silu_f(fmaf(f.x, sDA[c], sDB[c])) * sWc2[c];
                part += silu_f(fmaf(f.y, sDA[c + 1], sDB[c + 1])) * sWc2[c + 1];
            }
            part += __shfl_xor_sync(0xffffffffu, part, 1);
            part += __shfl_xor_sync(0xffffffffu, part, 2);
            if (q == 0) g_sc[e0 + el] = part + cbias;
        }
        __syncthreads();
        float c[4][4];
#pragma unroll
        for (int nb = 0; nb < 4; nb++)
#pragma unroll
            for (int j = 0; j < 4; j++) c[nb][j] = 0.f;
#pragma unroll
        for (int kb = 0; kb < 4; kb++) {
#pragma unroll
            for (int nb = 0; nb < 4; nb++) {
                int col = n0 + nb * 8 + gid;
                uint32_t b0 = *(const uint32_t*)&sX[col][kb * 16 + 2 * tig];
                uint32_t b1 = *(const uint32_t*)&sX[col][kb * 16 + 2 * tig + 8];
                mma_f16(c[nb], ah[kb][0], ah[kb][1], ah[kb][2], ah[kb][3], b0, b1);
                mma_f16(c[nb], al[kb][0], al[kb][1], al[kb][2], al[kb][3], b0, b1);
            }
        }
        __syncthreads();
#pragma unroll
        for (int nb = 0; nb < 4; nb++) {
            int e = n0 + nb * 8 + 2 * tig;
            float yr00 = __half2float(__float2half_rn(c[nb][0] + bias0));
            float yr01 = __half2float(__float2half_rn(c[nb][1] + bias0));
            float yr10 = __half2float(__float2half_rn(c[nb][2] + bias1));
            float yr11 = __half2float(__float2half_rn(c[nb][3] + bias1));
            sOut[e * 68 + m0 + gid] = yr00;
            sOut[(e + 1) * 68 + m0 + gid] = yr01;
            sOut[e * 68 + m0 + gid + 8] = yr10;
            sOut[(e + 1) * 68 + m0 + gid + 8] = yr11;
            s0 += yr00 + yr01; q0 += yr00 * yr00 + yr01 * yr01;
            s1 += yr10 + yr11; q1 += yr10 * yr10 + yr11 * yr11;
        }
        __syncthreads();
        {
            const float* src = &sOut[el * 68 + q * 16];
            __half hv[16];
#pragma unroll
            for (int m = 0; m < 16; m++) hv[m] = __float2half_rn(src[m]);
            uint4* dst = (uint4*)&g_mlinh[(size_t)(e0 + el) * 64 + q * 16];
            dst[0] = *(uint4*)&hv[0];
            dst[1] = *(uint4*)&hv[8];
        }
    }
    __syncthreads();
    atomicAdd(&sS[m0 + gid], s0); atomicAdd(&sQ[m0 + gid], q0);
    atomicAdd(&sS[m0 + gid + 8], s1); atomicAdd(&sQ[m0 + gid + 8], q1);
    __syncthreads();
    if (tid < 64) {
        atomicAdd(&g_sum[sl + 128 + tid], (double)sS[tid]);
        atomicAdd(&g_sumsq[sl + 128 + tid], (double)sQ[tid]);
    }
}

// ---------------- aggregation: warp per node; BN computed per-thread from stats ----------------
__global__ __launch_bounds__(256) void k_aggr(int layer,
                                              const float* __restrict__ g2, const float* __restrict__ be2)
{
    int gwarp = (blockIdx.x * blockDim.x + threadIdx.x) >> 5;
    int lane = threadIdx.x & 31;
    if (gwarp >= NN) return;
    int n = gwarp;
    int sl = layer * 256;
    const double inv = 1.0 / NE;
    float A0, B0, A1, B1;
    {
        double m = g_sum[sl + 128 + lane] * inv;
        double v = g_sumsq[sl + 128 + lane] * inv - m * m;
        A0 = g2[lane] * rsqrtf((float)v + EPS);
        B0 = be2[lane] - (float)m * A0;
        m = g_sum[sl + 160 + lane] * inv;
        v = g_sumsq[sl + 160 + lane] * inv - m * m;
        A1 = g2[32 + lane] * rsqrtf((float)v + EPS);
        B1 = be2[32 + lane] - (float)m * A1;
    }
    int s0 = g_rowstart[n], s1 = g_rowstart[n + 1];
    float acc0 = 0.f, acc1 = 0.f;
    for (int i = s0; i < s1; i++) {
        float m0 = __half2float(g_mlinh[(size_t)i * 64 + lane]);
        float m1 = __half2float(g_mlinh[(size_t)i * 64 + 32 + lane]);
        acc0 += silu_f(fmaf(m0, A0, B0));
        acc1 += silu_f(fmaf(m1, A1, B1));
    }
    g_u[(size_t)n * 128 + 64 + lane] = acc0;
    g_u[(size_t)n * 128 + 96 + lane] = acc1;
    float px = g_pos[n * 3], py = g_pos[n * 3 + 1], pz = g_pos[n * 3 + 2];
    float cx = 0.f, cy = 0.f, cz = 0.f;
    for (int i = s0 + lane; i < s1; i += 32) {
        int src = g_csrsrc[i];
        float sc = g_sc[i];
        cx += sc * (px - g_pos[src * 3]);
        cy += sc * (py - g_pos[src * 3 + 1]);
        cz += sc * (pz - g_pos[src * 3 + 2]);
    }
#pragma unroll
    for (int o = 16; o > 0; o >>= 1) {
        cx += __shfl_xor_sync(0xffffffffu, cx, o);
        cy += __shfl_xor_sync(0xffffffffu, cy, o);
        cz += __shfl_xor_sync(0xffffffffu, cz, o);
    }
    if (lane == 0) {
        g_aggr_p[n * 3 + 0] = cx;
        g_aggr_p[n * 3 + 1] = cy;
        g_aggr_p[n * 3 + 2] = cz;
    }
}

// ---------------- node 1: tiled 64n x 64o, K=128 ----------------
__global__ __launch_bounds__(256) void k_node1(int layer,
                                               const float* __restrict__ uw1, const float* __restrict__ ub1)
{
    __shared__ __align__(16) float sW[64][64];
    __shared__ __align__(16) float sA[64][64];
    __shared__ float sS[64], sQ[64];
    int tid = threadIdx.x, tx = tid & 15, ty = tid >> 4;
    int sl = layer * 256;
    if (tid < 64) { sS[tid] = 0.f; sQ[tid] = 0.f; }
    float bb[4];
#pragma unroll
    for (int j = 0; j < 4; j++) bb[j] = ub1[(ty << 2) + j];
    float st[4] = {0.f, 0.f, 0.f, 0.f}, sq[4] = {0.f, 0.f, 0.f, 0.f};
    int ntiles = (NN + 63) >> 6;
    for (int t = blockIdx.x; t < ntiles; t += gridDim.x) {
        int n0 = t << 6;
        float acc[4][4];
#pragma unroll
        for (int i = 0; i < 4; i++)
#pragma unroll
            for (int j = 0; j < 4; j++) acc[i][j] = 0.f;
        for (int half = 0; half < 2; half++) {
            __syncthreads();
            for (int i = tid; i < 1024; i += 256) {
                int o = i & 63, k0 = (i >> 6) << 2;
                float4 v = *(const float4*)&uw1[o * 128 + half * 64 + k0];
                sW[k0 + 0][o] = v.x; sW[k0 + 1][o] = v.y;
                sW[k0 + 2][o] = v.z; sW[k0 + 3][o] = v.w;
            }
            {
                int nn = tid >> 2, k0 = (tid & 3) << 4;
                int n = n0 + nn;
#pragma unroll
                for (int m = 0; m < 4; m++) {
                    float4 v = (n < NN) ? *(const float4*)&g_u[(size_t)n * 128 + half * 64 + k0 + 4 * m]
                                        : make_float4(0.f, 0.f, 0.f, 0.f);
                    sA[k0 + 4 * m + 0][nn] = v.x;
                    sA[k0 + 4 * m + 1][nn] = v.y;
                    sA[k0 + 4 * m + 2][nn] = v.z;
                    sA[k0 + 4 * m + 3][nn] = v.w;
                }
            }
            __syncthreads();
#pragma unroll 4
            for (int k = 0; k < 64; k++) {
                float4 a = *(const float4*)&sA[k][tx << 2];
                float4 b = *(const float4*)&sW[k][ty << 2];
                float av[4] = {a.x, a.y, a.z, a.w};
                float bv[4] = {b.x, b.y, b.z, b.w};
#pragma unroll
                for (int i = 0; i < 4; i++)
#pragma unroll
                    for (int j = 0; j < 4; j++) acc[i][j] = fmaf(av[i], bv[j], acc[i][j]);
            }
        }
#pragma unroll
        for (int i = 0; i < 4; i++) {
            int n = n0 + (tx << 2) + i;
            if (n < NN) {
                float y0 = acc[i][0] + bb[0], y1 = acc[i][1] + bb[1];
                float y2 = acc[i][2] + bb[2], y3 = acc[i][3] + bb[3];
                *(float4*)&g_un[n * 64 + (ty << 2)] = make_float4(y0, y1, y2, y3);
                st[0] += y0; sq[0] += y0 * y0; st[1] += y1; sq[1] += y1 * y1;
                st[2] += y2; sq[2] += y2 * y2; st[3] += y3; sq[3] += y3 * y3;
            }
        }
    }
    __syncthreads();
#pragma unroll
    for (int j = 0; j < 4; j++) {
        atomicAdd(&sS[(ty << 2) + j], st[j]);
        atomicAdd(&sQ[(ty << 2) + j], sq[j]);
    }
    __syncthreads();
    if (tid < 64) {
        atomicAdd(&g_sum[sl + 192 + tid], (double)sS[tid]);
        atomicAdd(&g_sumsq[sl + 192 + tid], (double)sQ[tid]);
    }
}

// ---------------- node 2: BN computed locally; residual + pos update ----------------
__global__ __launch_bounds__(256) void k_node2(int layer,
                                               const float* __restrict__ ug1, const float* __restrict__ ube1,
                                               const float* __restrict__ uw2, const float* __restrict__ ub2)
{
    __shared__ __align__(16) float sW[64][64];
    __shared__ __align__(16) float sA[64][64];
    __shared__ __align__(16) float sBA[64], sBB[64];
    int tid = threadIdx.x, tx = tid & 15, ty = tid >> 4;
    int sl = layer * 256;
    if (tid < 64) {
        double m = g_sum[sl + 192 + tid] * (1.0 / NN);
        double v = g_sumsq[sl + 192 + tid] * (1.0 / NN) - m * m;
        float A = ug1[tid] * rsqrtf((float)v + EPS);
        sBA[tid] = A; sBB[tid] = ube1[tid] - (float)m * A;
    }
    for (int i = tid; i < 1024; i += 256) {
        int o = i & 63, k0 = (i >> 6) << 2;
        float4 v = *(const float4*)&uw2[o * 64 + k0];
        sW[k0 + 0][o] = v.x; sW[k0 + 1][o] = v.y;
        sW[k0 + 2][o] = v.z; sW[k0 + 3][o] = v.w;
    }
    __syncthreads();
    int k0s = (tid & 3) << 4;
    float4 cA[4], cB[4];
#pragma unroll
    for (int m = 0; m < 4; m++) {
        cA[m] = *(const float4*)&sBA[k0s + 4 * m];
        cB[m] = *(const float4*)&sBB[k0s + 4 * m];
    }
    float bb[4];
#pragma unroll
    for (int j = 0; j < 4; j++) bb[j] = ub2[(ty << 2) + j];
    int ntiles = (NN + 63) >> 6;
    for (int t = blockIdx.x; t < ntiles; t += gridDim.x) {
        int n0 = t << 6;
        __syncthreads();
        {
            int nn = tid >> 2;
            int n = n0 + nn;
#pragma unroll
            for (int m = 0; m < 4; m++) {
                float4 v = (n < NN) ? *(const float4*)&g_un[(size_t)n * 64 + k0s + 4 * m]
                                    : make_float4(0.f, 0.f, 0.f, 0.f);
                sA[k0s + 4 * m + 0][nn] = silu_f(fmaf(v.x, cA[m].x, cB[m].x));
                sA[k0s + 4 * m + 1][nn] = silu_f(fmaf(v.y, cA[m].y, cB[m].y));
                sA[k0s + 4 * m + 2][nn] = silu_f(fmaf(v.z, cA[m].z, cB[m].z));
                sA[k0s + 4 * m + 3][nn] = silu_f(fmaf(v.w, cA[m].w, cB[m].w));
            }
        }
        __syncthreads();
        float acc[4][4];
#pragma unroll
        for (int i = 0; i < 4; i++)
#pragma unroll
            for (int j = 0; j < 4; j++) acc[i][j] = 0.f;
#pragma unroll 4
        for (int k = 0; k < 64; k++) {
            float4 a = *(const float4*)&sA[k][tx << 2];
            float4 b = *(const float4*)&sW[k][ty << 2];
            float av[4] = {a.x, a.y, a.z, a.w};
            float bv[4] = {b.x, b.y, b.z, b.w};
#pragma unroll
            for (int i = 0; i < 4; i++)
#pragma unroll
                for (int j = 0; j < 4; j++) acc[i][j] = fmaf(av[i], bv[j], acc[i][j]);
        }
#pragma unroll
        for (int i = 0; i < 4; i++) {
            int n = n0 + (tx << 2) + i;
            if (n < NN) {
                float4 hold = *(const float4*)&g_h[n * 64 + (ty << 2)];
                float h0 = hold.x + acc[i][0] + bb[0];
                float h1 = hold.y + acc[i][1] + bb[1];
                float h2 = hold.z + acc[i][2] + bb[2];
                float h3 = hold.w + acc[i][3] + bb[3];
                float4 hv = make_float4(h0, h1, h2, h3);
                *(float4*)&g_h[n * 64 + (ty << 2)] = hv;
                *(float4*)&g_u[(size_t)n * 128 + (ty << 2)] = hv;
            }
        }
        if (tid < 64) {
            int n = n0 + tid;
            if (n < NN) {
                g_pos[n * 3 + 0] += g_aggr_p[n * 3 + 0];
                g_pos[n * 3 + 1] += g_aggr_p[n * 3 + 1];
                g_pos[n * 3 + 2] += g_aggr_p[n * 3 + 2];
            }
        }
    }
}

// ---------------- pooling ----------------
__global__ void k_pool(const int* __restrict__ batch)
{
    int idx = blockIdx.x * blockDim.x + threadIdx.x;
    if (idx >= NN * 16) return;
    int n = idx >> 4, c4 = (idx & 15) * 4;
    int b = batch[n];
    float4 h = *(const float4*)&g_h[n * 64 + c4];
    red_add_v4(&g_pool[b * 64 + c4], h.x, h.y, h.z, h.w);
    if (c4 == 0) atomicAdd(&g_cnt[b], 1.0f);
}

__global__ void k_pred(const float* __restrict__ w, const float* __restrict__ b,
                       float* __restrict__ out)
{
    int g = blockIdx.x, lane = threadIdx.x;
    float p = g_pool[g * 64 + lane] * w[lane] + g_pool[g * 64 + 32 + lane] * w[32 + lane];
#pragma unroll
    for (int o = 16; o > 0; o >>= 1) p += __shfl_xor_sync(0xffffffffu, p, o);
    if (lane == 0) out[g] = p / fmaxf(g_cnt[g], 1.0f) + b[0];
}

// ---------------- launch ----------------
extern "C" void kernel_launch(void* const* d_in, const int* in_sizes, int n_in,
                              void* d_out, int out_size)
{
    const float* node_s    = (const float*)d_in[0];
    const float* node_type = (const float*)d_in[1];
    const float* pos       = (const float*)d_in[2];
    const int*   ei        = (const int*)d_in[3];
    const float* edge_s    = (const float*)d_in[4];
    const int*   batch     = (const int*)d_in[5];
    const float* lin_in_w  = (const float*)d_in[6];
    const float* lin_in_b  = (const float*)d_in[7];
    const float* msg_w1    = (const float*)d_in[8];
    const float* msg_b1    = (const float*)d_in[9];
    const float* msg_g1    = (const float*)d_in[10];
    const float* msg_be1   = (const float*)d_in[11];
    const float* msg_w2    = (const float*)d_in[12];
    const float* msg_b2    = (const float*)d_in[13];
    const float* msg_g2    = (const float*)d_in[14];
    const float* msg_be2   = (const float*)d_in[15];
    const float* updf_w1   = (const float*)d_in[16];
    const float* updf_b1   = (const float*)d_in[17];
    const float* updf_g1   = (const float*)d_in[18];
    const float* updf_be1  = (const float*)d_in[19];
    const float* updf_w2   = (const float*)d_in[20];
    const float* updf_b2   = (const float*)d_in[21];
    const float* updc_w1   = (const float*)d_in[22];
    const float* updc_b1   = (const float*)d_in[23];
    const float* updc_g1   = (const float*)d_in[24];
    const float* updc_be1  = (const float*)d_in[25];
    const float* updc_w2   = (const float*)d_in[26];
    const float* updc_b2   = (const float*)d_in[27];
    const float* lin_pred_w = (const float*)d_in[28];
    const float* lin_pred_b = (const float*)d_in[29];

    k_init<<<(NN * 64 + 255) / 256, 256>>>(node_s, node_type, pos, lin_in_w, lin_in_b);
    k_hist<<<(NE + 255) / 256, 256>>>(ei);
    k_scan<<<1, 1024>>>();
    k_fill<<<(NE + 255) / 256, 256>>>(ei);
    k_esperm<<<(NE * 4 + 255) / 256, 256>>>(edge_s);
    k_wpack_all<<<(NL * 64 * 256 + 255) / 256, 256>>>(msg_w1, updc_w1);

    for (int l = 0; l < NL; l++) {
        const float* mw1 = msg_w1 + (size_t)l * 64 * 161;
        const float* mb1 = msg_b1 + l * 64;
        const float* mw2 = msg_w2 + (size_t)l * 64 * 64;
        const float* mb2 = msg_b2 + l * 64;
        const float* cw1 = updc_w1 + (size_t)l * 64 * 161;
        const float* cb1 = updc_b1 + l * 64;
        const float* cw2 = updc_w2 + (size_t)l * 64;
        const float* cb2 = updc_b2 + l;
        const float* uw1 = updf_w1 + (size_t)l * 64 * 128;
        const float* ub1 = updf_b1 + l * 64;
        const float* uw2 = updf_w2 + (size_t)l * 64 * 64;
        const float* ub2 = updf_b2 + l * 64;

        k_hpre<<<592, 256>>>(l);
        k_edgeAmma<<<592, 256>>>(l, mw1, mb1, cw1, cb1);
        k_edgeBmma<<<592, 256>>>(l, msg_g1 + l * 64, msg_be1 + l * 64,
                                 updc_g1 + l * 64, updc_be1 + l * 64,
                                 mw2, mb2, cw2, cb2);
        k_aggr<<<(NN * 32 + 255) / 256, 256>>>(l, msg_g2 + l * 64, msg_be2 + l * 64);
        k_node1<<<592, 256>>>(l, uw1, ub1);
        k_node2<<<592, 256>>>(l, updf_g1 + l * 64, updf_be1 + l * 64, uw2, ub2);
    }

    k_pool<<<(NN * 16 + 255) / 256, 256>>>(batch);
    k_pred<<<NG, 32>>>(lin_pred_w, lin_pred_b, (float*)d_out);
}

// round 14
// speedup vs baseline: 1.1118x; 1.0648x over previous
#include <cuda_runtime.h>
#include <cuda_fp16.h>
#include <math.h>
#include <stdint.h>

#define NN 50000
#define NE 800000
#define NL 4
#define NG 64
#define EPS 1e-5f

// ---------------- static device scratch ----------------
__device__ __align__(16) float g_h[NN * 64];
__device__ __align__(16) float g_u[NN * 128];      // [h | aggr_h] fp32
__device__ __align__(16) __half g_unh[NN * 64];    // fp16
__device__ __align__(16) float g_pos[NN * 3];
__device__ __align__(16) float g_aggr_p[NN * 3];
__device__ __align__(16) __half g_HpreH[(size_t)NN * 256];
__device__ __align__(16) float g_wpack4[NL][64 * 256];  // k-major [k][op]
__device__ __align__(16) __half g_esh[(size_t)NE * 32];
__device__ __align__(16) __half g_t1h[(size_t)NE * 64];
__device__ __align__(16) __half g_t2h[(size_t)NE * 64];
__device__ __align__(16) __half g_mlinh[(size_t)NE * 64];
__device__ __align__(16) float g_sc[NE];
__device__ int g_deg[NN];
__device__ int g_rowstart[NN + 1];
__device__ int g_cursor[NN];
__device__ int g_csrsrc[NE];
__device__ int g_csrdst[NE];
__device__ int g_csre[NE];
__device__ double g_sum[NL * 256];
__device__ double g_sumsq[NL * 256];
__device__ __align__(16) float g_pool[NG * 64];
__device__ float g_cnt[NG];

__device__ __forceinline__ float silu_f(float y) {
    return y * (1.0f / (1.0f + __expf(-y)));
}

__device__ __forceinline__ void red_add_v4(float* p, float a, float b, float c, float d) {
    asm volatile("red.global.add.v4.f32 [%0], {%1,%2,%3,%4};"
                 :: "l"(p), "f"(a), "f"(b), "f"(c), "f"(d) : "memory");
}

__device__ __forceinline__ void mma_f16(float* c, uint32_t a0, uint32_t a1, uint32_t a2, uint32_t a3,
                                        uint32_t b0, uint32_t b1) {
    asm volatile("mma.sync.aligned.m16n8k16.row.col.f32.f16.f16.f32 "
                 "{%0,%1,%2,%3}, {%4,%5,%6,%7}, {%8,%9}, {%0,%1,%2,%3};"
                 : "+f"(c[0]), "+f"(c[1]), "+f"(c[2]), "+f"(c[3])
                 : "r"(a0), "r"(a1), "r"(a2), "r"(a3), "r"(b0), "r"(b1));
}

__device__ __forceinline__ void packsplit(float x, float y, uint32_t& h, uint32_t& l) {
    __half hx = __float2half_rn(x), hy = __float2half_rn(y);
    __half lx = __float2half_rn(x - __half2float(hx));
    __half ly = __float2half_rn(y - __half2float(hy));
    __half2 hh = __halves2half2(hx, hy), ll = __halves2half2(lx, ly);
    h = *(uint32_t*)&hh; l = *(uint32_t*)&ll;
}

// ---------------- init ----------------
__global__ void k_init(const float* __restrict__ ns, const float* __restrict__ nt,
                       const float* __restrict__ pos, const float* __restrict__ w,
                       const float* __restrict__ b)
{
    int idx = blockIdx.x * blockDim.x + threadIdx.x;
    if (idx < NG * 64) g_pool[idx] = 0.f;
    if (idx < NG) g_cnt[idx] = 0.f;
    if (idx < NL * 256) { g_sum[idx] = 0.0; g_sumsq[idx] = 0.0; }
    if (idx < NN) g_deg[idx] = 0;
    if (idx >= NN * 64) return;
    int n = idx >> 6, o = idx & 63;
    const float* wr = w + o * 8;
    const float* s = ns + n * 6;
    float acc = b[o];
#pragma unroll
    for (int i = 0; i < 6; i++) acc = fmaf(s[i], wr[i], acc);
    acc = fmaf(nt[n * 2 + 0], wr[6], acc);
    acc = fmaf(nt[n * 2 + 1], wr[7], acc);
    g_h[idx] = acc;
    g_u[(size_t)n * 128 + o] = acc;
    if (o < 3) g_pos[n * 3 + o] = pos[n * 3 + o];
}

// ---------------- CSR build ----------------
__global__ void k_hist(const int* __restrict__ ei)
{
    int e = blockIdx.x * blockDim.x + threadIdx.x;
    if (e < NE) atomicAdd(&g_deg[ei[NE + e]], 1);
}

__global__ __launch_bounds__(1024) void k_scan()
{
    __shared__ int ssum[1024];
    int t = threadIdx.x;
    const int C = 49;
    int begin = t * C;
    int end = begin + C; if (end > NN) end = NN;
    if (begin > NN) begin = NN;
    int s = 0;
    for (int i = begin; i < end; i++) s += g_deg[i];
    ssum[t] = s;
    __syncthreads();
    for (int off = 1; off < 1024; off <<= 1) {
        int v = (t >= off) ? ssum[t - off] : 0;
        __syncthreads();
        ssum[t] += v;
        __syncthreads();
    }
    int run = ssum[t] - s;
    for (int i = begin; i < end; i++) {
        g_rowstart[i] = run;
        g_cursor[i] = run;
        run += g_deg[i];
    }
    if (t == 1023) g_rowstart[NN] = ssum[1023];
}

__global__ void k_fill(const int* __restrict__ ei)
{
    int e = blockIdx.x * blockDim.x + threadIdx.x;
    if (e >= NE) return;
    int s = ei[e], d = ei[NE + e];
    int p = atomicAdd(&g_cursor[d], 1);
    g_csrsrc[p] = s;
    g_csrdst[p] = d;
    g_csre[p] = e;
}

// ---------------- permute edge_s into CSR order as fp16 ----------------
__global__ void k_esperm(const float* __restrict__ es)
{
    int idx = blockIdx.x * blockDim.x + threadIdx.x;
    if (idx >= NE * 4) return;
    int p = idx >> 2, q = idx & 3;
    int eid = g_csre[p];
    const float4* ep = (const float4*)&es[(size_t)eid * 32 + q * 8];
    float4 v0 = ep[0], v1 = ep[1];
    __half hv[8];
    hv[0] = __float2half_rn(v0.x); hv[1] = __float2half_rn(v0.y);
    hv[2] = __float2half_rn(v0.z); hv[3] = __float2half_rn(v0.w);
    hv[4] = __float2half_rn(v1.x); hv[5] = __float2half_rn(v1.y);
    hv[6] = __float2half_rn(v1.z); hv[7] = __float2half_rn(v1.w);
    *(uint4*)&g_esh[(size_t)p * 32 + q * 8] = *(uint4*)hv;
}

// ---------------- pack h-columns of msg_w1/updc_w1 for ALL layers ----------------
__global__ void k_wpack_all(const float* __restrict__ mw1a, const float* __restrict__ cw1a)
{
    int idx = blockIdx.x * blockDim.x + threadIdx.x;
    if (idx >= NL * 64 * 256) return;
    int l = idx >> 14;
    int r = idx & 16383;
    int k = r >> 8, op = r & 255, o = op & 63;
    const float* mw1 = mw1a + (size_t)l * 64 * 161;
    const float* cw1 = cw1a + (size_t)l * 64 * 161;
    float v;
    if (op < 64)       v = mw1[o * 161 + k];
    else if (op < 128) v = mw1[o * 161 + 64 + k];
    else if (op < 192) v = cw1[o * 161 + k];
    else               v = cw1[o * 161 + 64 + k];
    g_wpack4[l][k * 256 + op] = v;
}

// ---------------- Hpre (fp16 MMA): 64 nodes x 256 out (2 phases), K=64 ----------------
__global__ __launch_bounds__(256) void k_hpre(int layer)
{
    const float* wpack = g_wpack4[layer];
    __shared__ __align__(16) __half sH[64][72];     // 9216B
    __shared__ __align__(16) float sOut[64][132];   // 33792B
    int tid = threadIdx.x;
    int warp = tid >> 5, lane = tid & 31;
    int gid = lane >> 2, tig = lane & 3;

    // weight fragments for both phases: w(op,k) = wpack[k*256+op]
    uint32_t ah[2][4][4], al[2][4][4];
#pragma unroll
    for (int ph = 0; ph < 2; ph++) {
        int op0 = ph * 128 + warp * 16 + gid;
        int op1 = op0 + 8;
#pragma unroll
        for (int kb = 0; kb < 4; kb++) {
            int k0 = kb * 16 + 2 * tig;
            packsplit(wpack[k0 * 256 + op0], wpack[(k0 + 1) * 256 + op0], ah[ph][kb][0], al[ph][kb][0]);
            packsplit(wpack[k0 * 256 + op1], wpack[(k0 + 1) * 256 + op1], ah[ph][kb][1], al[ph][kb][1]);
            packsplit(wpack[(k0 + 8) * 256 + op0], wpack[(k0 + 9) * 256 + op0], ah[ph][kb][2], al[ph][kb][2]);
            packsplit(wpack[(k0 + 8) * 256 + op1], wpack[(k0 + 9) * 256 + op1], ah[ph][kb][3], al[ph][kb][3]);
        }
    }
    int ntiles = (NN + 63) >> 6;
    int el = tid >> 2, q = tid & 3;
    for (int t = blockIdx.x; t < ntiles; t += gridDim.x) {
        int n0 = t << 6;
        __syncthreads();
        // stage h fp16
        {
            int n = n0 + el;
            __half hv[16];
            if (n < NN) {
                const float4* hp = (const float4*)&g_h[n * 64 + q * 16];
#pragma unroll
                for (int m = 0; m < 4; m++) {
                    float4 v = hp[m];
                    hv[4 * m] = __float2half_rn(v.x); hv[4 * m + 1] = __float2half_rn(v.y);
                    hv[4 * m + 2] = __float2half_rn(v.z); hv[4 * m + 3] = __float2half_rn(v.w);
                }
            } else {
#pragma unroll
                for (int m = 0; m < 16; m++) hv[m] = __float2half_rn(0.f);
            }
            *(uint4*)&sH[el][q * 16] = *(uint4*)&hv[0];
            *(uint4*)&sH[el][q * 16 + 8] = *(uint4*)&hv[8];
        }
        __syncthreads();
        for (int ph = 0; ph < 2; ph++) {
            float c[8][4];
#pragma unroll
            for (int nb = 0; nb < 8; nb++)
#pragma unroll
                for (int j = 0; j < 4; j++) c[nb][j] = 0.f;
#pragma unroll
            for (int kb = 0; kb < 4; kb++) {
#pragma unroll
                for (int nb = 0; nb < 8; nb++) {
                    int col = nb * 8 + gid;
                    uint32_t b0 = *(const uint32_t*)&sH[col][kb * 16 + 2 * tig];
                    uint32_t b1 = *(const uint32_t*)&sH[col][kb * 16 + 2 * tig + 8];
                    mma_f16(c[nb], ah[ph][kb][0], ah[ph][kb][1], ah[ph][kb][2], ah[ph][kb][3], b0, b1);
                    mma_f16(c[nb], al[ph][kb][0], al[ph][kb][1], al[ph][kb][2], al[ph][kb][3], b0, b1);
                }
            }
            // transpose into sOut[node][ch]
            {
                int ch = warp * 16 + gid;
#pragma unroll
                for (int nb = 0; nb < 8; nb++) {
                    int e = nb * 8 + 2 * tig;
                    sOut[e][ch] = c[nb][0];
                    sOut[e + 1][ch] = c[nb][1];
                    sOut[e][ch + 8] = c[nb][2];
                    sOut[e + 1][ch + 8] = c[nb][3];
                }
            }
            __syncthreads();
            // coalesced fp16 store: thread covers 32 ch
            {
                int n = n0 + el;
                if (n < NN) {
                    __half hv[32];
#pragma unroll
                    for (int m = 0; m < 32; m++) hv[m] = __float2half_rn(sOut[el][q * 32 + m]);
                    uint4* dst = (uint4*)&g_HpreH[(size_t)n * 256 + ph * 128 + q * 32];
                    dst[0] = *(uint4*)&hv[0];
                    dst[1] = *(uint4*)&hv[8];
                    dst[2] = *(uint4*)&hv[16];
                    dst[3] = *(uint4*)&hv[24];
                }
            }
            __syncthreads();
        }
    }
}

// ---------------- edge A (fp16 MMA, CSR order) ----------------
__global__ __launch_bounds__(256) void k_edgeAmma(int layer,
                                                  const float* __restrict__ mw1, const float* __restrict__ mb1,
                                                  const float* __restrict__ cw1, const float* __restrict__ cb1)
{
    __shared__ __align__(16) char sBuf[64 * 132 * 4];
    __half (*sEs)[40] = (__half(*)[40])sBuf;
    float (*sOut)[132] = (float(*)[132])sBuf;
    __shared__ float sR[64];
    __shared__ int sSrc[64], sDst[64];
    __shared__ float sS[128], sQ[128];

    int tid = threadIdx.x;
    int warp = tid >> 5, lane = tid & 31;
    int gid = lane >> 2, tig = lane & 3;
    int sl = layer * 256;

    if (tid < 128) { sS[tid] = 0.f; sQ[tid] = 0.f; }

    uint32_t ah[2][4], al[2][4];
    {
        int r0 = warp * 16 + gid;
        int r1 = r0 + 8;
        const float* w0 = (r0 < 64) ? &mw1[r0 * 161 + 129] : &cw1[(r0 - 64) * 161 + 129];
        const float* w1 = (r1 < 64) ? &mw1[r1 * 161 + 129] : &cw1[(r1 - 64) * 161 + 129];
#pragma unroll
        for (int kb = 0; kb < 2; kb++) {
            int k0 = kb * 16 + 2 * tig;
            packsplit(w0[k0], w0[k0 + 1], ah[kb][0], al[kb][0]);
            packsplit(w1[k0], w1[k0 + 1], ah[kb][1], al[kb][1]);
            packsplit(w0[k0 + 8], w0[k0 + 9], ah[kb][2], al[kb][2]);
            packsplit(w1[k0 + 8], w1[k0 + 9], ah[kb][3], al[kb][3]);
        }
    }
    int ch0 = lane << 2;
    float wr4[4], bb4[4];
#pragma unroll
    for (int j = 0; j < 4; j++) {
        int ch = ch0 + j;
        wr4[j] = (ch < 64) ? mw1[ch * 161 + 128] : cw1[(ch - 64) * 161 + 128];
        bb4[j] = (ch < 64) ? mb1[ch] : cb1[ch - 64];
    }
    int hd_off = (ch0 < 64) ? ch0 : 64 + ch0;
    int hs_off = (ch0 < 64) ? 64 + ch0 : 128 + ch0;
    float st[4] = {0.f, 0.f, 0.f, 0.f}, sq[4] = {0.f, 0.f, 0.f, 0.f};

    for (int t = blockIdx.x; t < NE / 64; t += gridDim.x) {
        int p0 = t << 6;
        __syncthreads();
        if (tid < 64) {
            int p = p0 + tid;
            int s = g_csrsrc[p], d = g_csrdst[p];
            sSrc[tid] = s; sDst[tid] = d;
            float dx = g_pos[d * 3] - g_pos[s * 3];
            float dy = g_pos[d * 3 + 1] - g_pos[s * 3 + 1];
            float dz = g_pos[d * 3 + 2] - g_pos[s * 3 + 2];
            sR[tid] = sqrtf(dx * dx + dy * dy + dz * dz);
        }
        {
            int el = tid >> 2, q = tid & 3;
            *(uint4*)&sEs[el][q * 8] = *(const uint4*)&g_esh[(size_t)(p0 + el) * 32 + q * 8];
        }
        __syncthreads();
        float c[8][4];
#pragma unroll
        for (int nb = 0; nb < 8; nb++)
#pragma unroll
            for (int j = 0; j < 4; j++) c[nb][j] = 0.f;
#pragma unroll
        for (int kb = 0; kb < 2; kb++) {
#pragma unroll
            for (int nb = 0; nb < 8; nb++) {
                int col = nb * 8 + gid;
                uint32_t b0 = *(const uint32_t*)&sEs[col][kb * 16 + 2 * tig];
                uint32_t b1 = *(const uint32_t*)&sEs[col][kb * 16 + 2 * tig + 8];
                mma_f16(c[nb], ah[kb][0], ah[kb][1], ah[kb][2], ah[kb][3], b0, b1);
                mma_f16(c[nb], al[kb][0], al[kb][1], al[kb][2], al[kb][3], b0, b1);
            }
        }
        __syncthreads();
        {
            int ch = warp * 16 + gid;
#pragma unroll
            for (int nb = 0; nb < 8; nb++) {
                int e = nb * 8 + 2 * tig;
                sOut[e][ch] = c[nb][0];
                sOut[e + 1][ch] = c[nb][1];
                sOut[e][ch + 8] = c[nb][2];
                sOut[e + 1][ch + 8] = c[nb][3];
            }
        }
        __syncthreads();
#pragma unroll 2
        for (int ee = 0; ee < 8; ee++) {
            int e = warp * 8 + ee;
            int d = sDst[e], s = sSrc[e];
            float r = sR[e];
            uint2 du = *(const uint2*)&g_HpreH[(size_t)d * 256 + hd_off];
            uint2 su = *(const uint2*)&g_HpreH[(size_t)s * 256 + hs_off];
            float2 d01 = __half22float2(*(__half2*)&du.x);
            float2 d23 = __half22float2(*(__half2*)&du.y);
            float2 s01 = __half22float2(*(__half2*)&su.x);
            float2 s23 = __half22float2(*(__half2*)&su.y);
            float4 o = *(const float4*)&sOut[e][ch0];
            __half hv[4];
            hv[0] = __float2half_rn(o.x + d01.x + s01.x + fmaf(r, wr4[0], bb4[0]));
            hv[1] = __float2half_rn(o.y + d01.y + s01.y + fmaf(r, wr4[1], bb4[1]));
            hv[2] = __float2half_rn(o.z + d23.x + s23.x + fmaf(r, wr4[2], bb4[2]));
            hv[3] = __float2half_rn(o.w + d23.y + s23.y + fmaf(r, wr4[3], bb4[3]));
            int p = p0 + e;
            __half* out = (ch0 < 64) ? &g_t1h[(size_t)p * 64 + ch0]
                                     : &g_t2h[(size_t)p * 64 + ch0 - 64];
            *(uint2*)out = *(uint2*)hv;
#pragma unroll
            for (int j = 0; j < 4; j++) {
                float yr = __half2float(hv[j]);
                st[j] += yr; sq[j] += yr * yr;
            }
        }
    }
    __syncthreads();
#pragma unroll
    for (int j = 0; j < 4; j++) { atomicAdd(&sS[ch0 + j], st[j]); atomicAdd(&sQ[ch0 + j], sq[j]); }
    __syncthreads();
    if (tid < 128) {
        atomicAdd(&g_sum[sl + tid], (double)sS[tid]);
        atomicAdd(&g_sumsq[sl + tid], (double)sQ[tid]);
    }
}

// ---------------- edge B (fp16 MMA): BN computed locally from stats ----------------
__global__ __launch_bounds__(256) void k_edgeBmma(int layer,
                                                  const float* __restrict__ mg1, const float* __restrict__ mbe1,
                                                  const float* __restrict__ cg1, const float* __restrict__ cbe1,
                                                  const float* __restrict__ mw2, const float* __restrict__ mb2,
                                                  const float* __restrict__ cw2, const float* __restrict__ cb2)
{
    __shared__ __align__(16) char sBuf[64 * 68 * 4];
    __half (*sX)[72] = (__half(*)[72])sBuf;
    float* sOut = (float*)sBuf;
    __shared__ float sS[64], sQ[64];
    __shared__ float sCA[64], sCB[64], sDA[64], sDB[64], sWc2[64];

    int tid = threadIdx.x;
    int warp = tid >> 5, lane = tid & 31;
    int gid = lane >> 2, tig = lane & 3;
    int m0 = (warp & 3) << 4;
    int n0 = (warp >> 2) << 5;
    int sl = layer * 256;

    if (tid < 64) {
        double m = g_sum[sl + tid] * (1.0 / NE);
        double v = g_sumsq[sl + tid] * (1.0 / NE) - m * m;
        float A = mg1[tid] * rsqrtf((float)v + EPS);
        sCA[tid] = A; sCB[tid] = mbe1[tid] - (float)m * A;
        sS[tid] = 0.f; sQ[tid] = 0.f;
        sWc2[tid] = cw2[tid];
    } else if (tid < 128) {
        int c = tid - 64;
        double m = g_sum[sl + 64 + c] * (1.0 / NE);
        double v = g_sumsq[sl + 64 + c] * (1.0 / NE) - m * m;
        float A = cg1[c] * rsqrtf((float)v + EPS);
        sDA[c] = A; sDB[c] = cbe1[c] - (float)m * A;
    }

    uint32_t ah[4][4], al[4][4];
    {
        const float* w0 = mw2 + (size_t)(m0 + gid) * 64;
        const float* w1 = mw2 + (size_t)(m0 + gid + 8) * 64;
#pragma unroll
        for (int kb = 0; kb < 4; kb++) {
            int k0 = kb * 16 + 2 * tig;
            packsplit(w0[k0], w0[k0 + 1], ah[kb][0], al[kb][0]);
            packsplit(w1[k0], w1[k0 + 1], ah[kb][1], al[kb][1]);
            packsplit(w0[k0 + 8], w0[k0 + 9], ah[kb][2], al[kb][2]);
            packsplit(w1[k0 + 8], w1[k0 + 9], ah[kb][3], al[kb][3]);
        }
    }
    float bias0 = mb2[m0 + gid], bias1 = mb2[m0 + gid + 8];
    float cbias = cb2[0];
    float s0 = 0.f, q0 = 0.f, s1 = 0.f, q1 = 0.f;

    int el = tid >> 2, q = tid & 3;

    for (int t = blockIdx.x; t < NE / 64; t += gridDim.x) {
        int e0 = t << 6;
        __syncthreads();
        {
            const uint4* tb = (const uint4*)&g_t1h[(size_t)(e0 + el) * 64 + q * 16];
            __half2 hbuf[8];
            *(uint4*)&hbuf[0] = tb[0];
            *(uint4*)&hbuf[4] = tb[1];
            __half xv[16];
#pragma unroll
            for (int m = 0; m < 8; m++) {
                float2 f = __half22float2(hbuf[m]);
                int c = q * 16 + 2 * m;
                xv[2 * m]     = __float2half_rn(silu_f(fmaf(f.x, sCA[c], sCB[c])));
                xv[2 * m + 1] = __float2half_rn(silu_f(fmaf(f.y, sCA[c + 1], sCB[c + 1])));
            }
            *(uint4*)&sX[el][q * 16] = *(uint4*)&xv[0];
            *(uint4*)&sX[el][q * 16 + 8] = *(uint4*)&xv[8];
        }
        {
            const uint4* tb = (const uint4*)&g_t2h[(size_t)(e0 + el) * 64 + q * 16];
            __half2 hbuf[8];
            *(uint4*)&hbuf[0] = tb[0];
            *(uint4*)&hbuf[4] = tb[1];
            float part = 0.f;
#pragma unroll
            for (int m = 0; m < 8; m++) {
                float2 f = __half22float2(hbuf[m]);
                int c = q * 16 + 2 * m;
                part += silu_f(fmaf(f.x, sDA[c], sDB[c])) * sWc2[c];
                part += silu_f(fmaf(f.y, sDA[c + 1], sDB[c + 1])) * sWc2[c + 1];
            }
            part += __shfl_xor_sync(0xffffffffu, part, 1);
            part += __shfl_xor_sync(0xffffffffu, part, 2);
            if (q == 0) g_sc[e0 + el] = part + cbias;
        }
        __syncthreads();
        float c[4][4];
#pragma unroll
        for (int nb = 0; nb < 4; nb++)
#pragma unroll
            for (int j = 0; j < 4; j++) c[nb][j] = 0.f;
#pragma unroll
        for (int kb = 0; kb < 4; kb++) {
#pragma unroll
            for (int nb = 0; nb < 4; nb++) {
                int col = n0 + nb * 8 + gid;
                uint32_t b0 = *(const uint32_t*)&sX[col][kb * 16 + 2 * tig];
                uint32_t b1 = *(const uint32_t*)&sX[col][kb * 16 + 2 * tig + 8];
                mma_f16(c[nb], ah[kb][0], ah[kb][1], ah[kb][2], ah[kb][3], b0, b1);
                mma_f16(c[nb], al[kb][0], al[kb][1], al[kb][2], al[kb][3], b0, b1);
            }
        }
        __syncthreads();
#pragma unroll
        for (int nb = 0; nb < 4; nb++) {
            int e = n0 + nb * 8 + 2 * tig;
            float yr00 = __half2float(__float2half_rn(c[nb][0] + bias0));
            float yr01 = __half2float(__float2half_rn(c[nb][1] + bias0));
            float yr10 = __half2float(__float2half_rn(c[nb][2] + bias1));
            float yr11 = __half2float(__float2half_rn(c[nb][3] + bias1));
            sOut[e * 68 + m0 + gid] = yr00;
            sOut[(e + 1) * 68 + m0 + gid] = yr01;
            sOut[e * 68 + m0 + gid + 8] = yr10;
            sOut[(e + 1) * 68 + m0 + gid + 8] = yr11;
            s0 += yr00 + yr01; q0 += yr00 * yr00 + yr01 * yr01;
            s1 += yr10 + yr11; q1 += yr10 * yr10 + yr11 * yr11;
        }
        __syncthreads();
        {
            const float* src = &sOut[el * 68 + q * 16];
            __half hv[16];
#pragma unroll
            for (int m = 0; m < 16; m++) hv[m] = __float2half_rn(src[m]);
            uint4* dst = (uint4*)&g_mlinh[(size_t)(e0 + el) * 64 + q * 16];
            dst[0] = *(uint4*)&hv[0];
            dst[1] = *(uint4*)&hv[8];
        }
    }
    __syncthreads();
    atomicAdd(&sS[m0 + gid], s0); atomicAdd(&sQ[m0 + gid], q0);
    atomicAdd(&sS[m0 + gid + 8], s1); atomicAdd(&sQ[m0 + gid + 8], q1);
    __syncthreads();
    if (tid < 64) {
        atomicAdd(&g_sum[sl + 128 + tid], (double)sS[tid]);
        atomicAdd(&g_sumsq[sl + 128 + tid], (double)sQ[tid]);
    }
}

// ---------------- aggregation: warp per node, half2-vectorized mlin loads ----------------
__global__ __launch_bounds__(256) void k_aggr(int layer,
                                              const float* __restrict__ g2, const float* __restrict__ be2)
{
    int gwarp = (blockIdx.x * blockDim.x + threadIdx.x) >> 5;
    int lane = threadIdx.x & 31;
    if (gwarp >= NN) return;
    int n = gwarp;
    int sl = layer * 256;
    const double inv = 1.0 / NE;
    int c0 = 2 * lane;
    float A0, B0, A1, B1;
    {
        double m = g_sum[sl + 128 + c0] * inv;
        double v = g_sumsq[sl + 128 + c0] * inv - m * m;
        A0 = g2[c0] * rsqrtf((float)v + EPS);
        B0 = be2[c0] - (float)m * A0;
        m = g_sum[sl + 128 + c0 + 1] * inv;
        v = g_sumsq[sl + 128 + c0 + 1] * inv - m * m;
        A1 = g2[c0 + 1] * rsqrtf((float)v + EPS);
        B1 = be2[c0 + 1] - (float)m * A1;
    }
    int s0 = g_rowstart[n], s1 = g_rowstart[n + 1];
    float acc0 = 0.f, acc1 = 0.f;
    for (int i = s0; i < s1; i++) {
        uint32_t u = *(const uint32_t*)&g_mlinh[(size_t)i * 64 + c0];
        float2 f = __half22float2(*(__half2*)&u);
        acc0 += silu_f(fmaf(f.x, A0, B0));
        acc1 += silu_f(fmaf(f.y, A1, B1));
    }
    *(float2*)&g_u[(size_t)n * 128 + 64 + c0] = make_float2(acc0, acc1);
    float px = g_pos[n * 3], py = g_pos[n * 3 + 1], pz = g_pos[n * 3 + 2];
    float cx = 0.f, cy = 0.f, cz = 0.f;
    for (int i = s0 + lane; i < s1; i += 32) {
        int src = g_csrsrc[i];
        float sc = g_sc[i];
        cx += sc * (px - g_pos[src * 3]);
        cy += sc * (py - g_pos[src * 3 + 1]);
        cz += sc * (pz - g_pos[src * 3 + 2]);
    }
#pragma unroll
    for (int o = 16; o > 0; o >>= 1) {
        cx += __shfl_xor_sync(0xffffffffu, cx, o);
        cy += __shfl_xor_sync(0xffffffffu, cy, o);
        cz += __shfl_xor_sync(0xffffffffu, cz, o);
    }
    if (lane == 0) {
        g_aggr_p[n * 3 + 0] = cx;
        g_aggr_p[n * 3 + 1] = cy;
        g_aggr_p[n * 3 + 2] = cz;
    }
}

// ---------------- node 1 (fp16 MMA): un = u(128) @ uw1^T + b, fp16 out + stats ----------------
__global__ __launch_bounds__(256) void k_node1(int layer,
                                               const float* __restrict__ uw1, const float* __restrict__ ub1)
{
    __shared__ __align__(16) char sBuf[64 * 68 * 4];   // union: sU half[64][136] | sOut float[64*68]
    __half (*sU)[136] = (__half(*)[136])sBuf;
    float* sOut = (float*)sBuf;
    __shared__ float sS[64], sQ[64];
    int tid = threadIdx.x;
    int warp = tid >> 5, lane = tid & 31;
    int gid = lane >> 2, tig = lane & 3;
    int m0 = (warp & 3) << 4;
    int n0 = (warp >> 2) << 5;
    int sl = layer * 256;
    if (tid < 64) { sS[tid] = 0.f; sQ[tid] = 0.f; }

    uint32_t ah[8][4], al[8][4];
    {
        const float* w0 = uw1 + (size_t)(m0 + gid) * 128;
        const float* w1 = uw1 + (size_t)(m0 + gid + 8) * 128;
#pragma unroll
        for (int kb = 0; kb < 8; kb++) {
            int k0 = kb * 16 + 2 * tig;
            packsplit(w0[k0], w0[k0 + 1], ah[kb][0], al[kb][0]);
            packsplit(w1[k0], w1[k0 + 1], ah[kb][1], al[kb][1]);
            packsplit(w0[k0 + 8], w0[k0 + 9], ah[kb][2], al[kb][2]);
            packsplit(w1[k0 + 8], w1[k0 + 9], ah[kb][3], al[kb][3]);
        }
    }
    float bias0 = ub1[m0 + gid], bias1 = ub1[m0 + gid + 8];
    float s0 = 0.f, q0 = 0.f, s1 = 0.f, q1 = 0.f;
    int el = tid >> 2, q = tid & 3;
    int ntiles = (NN + 63) >> 6;

    for (int t = blockIdx.x; t < ntiles; t += gridDim.x) {
        int tn0 = t << 6;
        __syncthreads();
        // stage u fp16: thread covers node el, k [q*32, q*32+32)
        {
            int n = tn0 + el;
            __half hv[32];
            if (n < NN) {
                const float4* up = (const float4*)&g_u[(size_t)n * 128 + q * 32];
#pragma unroll
                for (int m = 0; m < 8; m++) {
                    float4 v = up[m];
                    hv[4 * m] = __float2half_rn(v.x); hv[4 * m + 1] = __float2half_rn(v.y);
                    hv[4 * m + 2] = __float2half_rn(v.z); hv[4 * m + 3] = __float2half_rn(v.w);
                }
            } else {
#pragma unroll
                for (int m = 0; m < 32; m++) hv[m] = __float2half_rn(0.f);
            }
            uint4* dst = (uint4*)&sU[el][q * 32];
            dst[0] = *(uint4*)&hv[0];
            dst[1] = *(uint4*)&hv[8];
            dst[2] = *(uint4*)&hv[16];
            dst[3] = *(uint4*)&hv[24];
        }
        __syncthreads();
        float c[4][4];
#pragma unroll
        for (int nb = 0; nb < 4; nb++)
#pragma unroll
            for (int j = 0; j < 4; j++) c[nb][j] = 0.f;
#pragma unroll
        for (int kb = 0; kb < 8; kb++) {
#pragma unroll
            for (int nb = 0; nb < 4; nb++) {
                int col = n0 + nb * 8 + gid;
                uint32_t b0 = *(const uint32_t*)&sU[col][kb * 16 + 2 * tig];
                uint32_t b1 = *(const uint32_t*)&sU[col][kb * 16 + 2 * tig + 8];
                mma_f16(c[nb], ah[kb][0], ah[kb][1], ah[kb][2], ah[kb][3], b0, b1);
                mma_f16(c[nb], al[kb][0], al[kb][1], al[kb][2], al[kb][3], b0, b1);
            }
        }
        __syncthreads();
#pragma unroll
        for (int nb = 0; nb < 4; nb++) {
            int e = n0 + nb * 8 + 2 * tig;
            float yr00 = __half2float(__float2half_rn(c[nb][0] + bias0));
            float yr01 = __half2float(__float2half_rn(c[nb][1] + bias0));
            float yr10 = __half2float(__float2half_rn(c[nb][2] + bias1));
            float yr11 = __half2float(__float2half_rn(c[nb][3] + bias1));
            sOut[e * 68 + m0 + gid] = yr00;
            sOut[(e + 1) * 68 + m0 + gid] = yr01;
            sOut[e * 68 + m0 + gid + 8] = yr10;
            sOut[(e + 1) * 68 + m0 + gid + 8] = yr11;
            bool v0 = (tn0 + e < NN), v1 = (tn0 + e + 1 < NN);
            if (v0) { s0 += yr00; q0 += yr00 * yr00; s1 += yr10; q1 += yr10 * yr10; }
            if (v1) { s0 += yr01; q0 += yr01 * yr01; s1 += yr11; q1 += yr11 * yr11; }
        }
        __syncthreads();
        {
            int n = tn0 + el;
            if (n < NN) {
                const float* src = &sOut[el * 68 + q * 16];
                __half hv[16];
#pragma unroll
                for (int m = 0; m < 16; m++) hv[m] = __float2half_rn(src[m]);
                uint4* dst = (uint4*)&g_unh[(size_t)n * 64 + q * 16];
                dst[0] = *(uint4*)&hv[0];
                dst[1] = *(uint4*)&hv[8];
            }
        }
    }
    __syncthreads();
    atomicAdd(&sS[m0 + gid], s0); atomicAdd(&sQ[m0 + gid], q0);
    atomicAdd(&sS[m0 + gid + 8], s1); atomicAdd(&sQ[m0 + gid + 8], q1);
    __syncthreads();
    if (tid < 64) {
        atomicAdd(&g_sum[sl + 192 + tid], (double)sS[tid]);
        atomicAdd(&g_sumsq[sl + 192 + tid], (double)sQ[tid]);
    }
}

// ---------------- node 2 (fp16 MMA): h += silu(bn(un)) @ uw2^T + b; pos update ----------------
__global__ __launch_bounds__(256) void k_node2(int layer,
                                               const float* __restrict__ ug1, const float* __restrict__ ube1,
                                               const float* __restrict__ uw2, const float* __restrict__ ub2)
{
    __shared__ __align__(16) char sBuf[64 * 68 * 4];
    __half (*sX)[72] = (__half(*)[72])sBuf;
    float* sOut = (float*)sBuf;
    __shared__ float sBA[64], sBB[64];
    int tid = threadIdx.x;
    int warp = tid >> 5, lane = tid & 31;
    int gid = lane >> 2, tig = lane & 3;
    int m0 = (warp & 3) << 4;
    int n0 = (warp >> 2) << 5;
    int sl = layer * 256;
    if (tid < 64) {
        double m = g_sum[sl + 192 + tid] * (1.0 / NN);
        double v = g_sumsq[sl + 192 + tid] * (1.0 / NN) - m * m;
        float A = ug1[tid] * rsqrtf((float)v + EPS);
        sBA[tid] = A; sBB[tid] = ube1[tid] - (float)m * A;
    }
    uint32_t ah[4][4], al[4][4];
    {
        const float* w0 = uw2 + (size_t)(m0 + gid) * 64;
        const float* w1 = uw2 + (size_t)(m0 + gid + 8) * 64;
#pragma unroll
        for (int kb = 0; kb < 4; kb++) {
            int k0 = kb * 16 + 2 * tig;
            packsplit(w0[k0], w0[k0 + 1], ah[kb][0], al[kb][0]);
            packsplit(w1[k0], w1[k0 + 1], ah[kb][1], al[kb][1]);
            packsplit(w0[k0 + 8], w0[k0 + 9], ah[kb][2], al[kb][2]);
            packsplit(w1[k0 + 8], w1[k0 + 9], ah[kb][3], al[kb][3]);
        }
    }
    float bias0 = ub2[m0 + gid], bias1 = ub2[m0 + gid + 8];
    int el = tid >> 2, q = tid & 3;
    int ntiles = (NN + 63) >> 6;
    __syncthreads();

    for (int t = blockIdx.x; t < ntiles; t += gridDim.x) {
        int tn0 = t << 6;
        __syncthreads();
        // stage silu(bn(un)) fp16
        {
            int n = tn0 + el;
            __half xv[16];
            if (n < NN) {
                const uint4* tb = (const uint4*)&g_unh[(size_t)n * 64 + q * 16];
                __half2 hbuf[8];
                *(uint4*)&hbuf[0] = tb[0];
                *(uint4*)&hbuf[4] = tb[1];
#pragma unroll
                for (int m = 0; m < 8; m++) {
                    float2 f = __half22float2(hbuf[m]);
                    int c = q * 16 + 2 * m;
                    xv[2 * m]     = __float2half_rn(silu_f(fmaf(f.x, sBA[c], sBB[c])));
                    xv[2 * m + 1] = __float2half_rn(silu_f(fmaf(f.y, sBA[c + 1], sBB[c + 1])));
                }
            } else {
#pragma unroll
                for (int m = 0; m < 16; m++) xv[m] = __float2half_rn(0.f);
            }
            *(uint4*)&sX[el][q * 16] = *(uint4*)&xv[0];
            *(uint4*)&sX[el][q * 16 + 8] = *(uint4*)&xv[8];
        }
        __syncthreads();
        float c[4][4];
#pragma unroll
        for (int nb = 0; nb < 4; nb++)
#pragma unroll
            for (int j = 0; j < 4; j++) c[nb][j] = 0.f;
#pragma unroll
        for (int kb = 0; kb < 4; kb++) {
#pragma unroll
            for (int nb = 0; nb < 4; nb++) {
                int col = n0 + nb * 8 + gid;
                uint32_t b0 = *(const uint32_t*)&sX[col][kb * 16 + 2 * tig];
                uint32_t b1 = *(const uint32_t*)&sX[col][kb * 16 + 2 * tig + 8];
                mma_f16(c[nb], ah[kb][0], ah[kb][1], ah[kb][2], ah[kb][3], b0, b1);
                mma_f16(c[nb], al[kb][0], al[kb][1], al[kb][2], al[kb][3], b0, b1);
            }
        }
        __syncthreads();
#pragma unroll
        for (int nb = 0; nb < 4; nb++) {
            int e = n0 + nb * 8 + 2 * tig;
            sOut[e * 68 + m0 + gid] = c[nb][0] + bias0;
            sOut[(e + 1) * 68 + m0 + gid] = c[nb][1] + bias0;
            sOut[e * 68 + m0 + gid + 8] = c[nb][2] + bias1;
            sOut[(e + 1) * 68 + m0 + gid + 8] = c[nb][3] + bias1;
        }
        __syncthreads();
        {
            int n = tn0 + el;
            if (n < NN) {
                const float* src = &sOut[el * 68 + q * 16];
#pragma unroll
                for (int m = 0; m < 4; m++) {
                    float4 hold = *(const float4*)&g_h[n * 64 + q * 16 + 4 * m];
                    float4 hv = make_float4(hold.x + src[4 * m], hold.y + src[4 * m + 1],
                                            hold.z + src[4 * m + 2], hold.w + src[4 * m + 3]);
                    *(float4*)&g_h[n * 64 + q * 16 + 4 * m] = hv;
                    *(float4*)&g_u[(size_t)n * 128 + q * 16 + 4 * m] = hv;
                }
            }
        }
        if (tid < 64) {
            int n = tn0 + tid;
            if (n < NN) {
                g_pos[n * 3 + 0] += g_aggr_p[n * 3 + 0];
                g_pos[n * 3 + 1] += g_aggr_p[n * 3 + 1];
                g_pos[n * 3 + 2] += g_aggr_p[n * 3 + 2];
            }
        }
    }
}

// ---------------- pooling ----------------
__global__ void k_pool(const int* __restrict__ batch)
{
    int idx = blockIdx.x * blockDim.x + threadIdx.x;
    if (idx >= NN * 16) return;
    int n = idx >> 4, c4 = (idx & 15) * 4;
    int b = batch[n];
    float4 h = *(const float4*)&g_h[n * 64 + c4];
    red_add_v4(&g_pool[b * 64 + c4], h.x, h.y, h.z, h.w);
    if (c4 == 0) atomicAdd(&g_cnt[b], 1.0f);
}

__global__ void k_pred(const float* __restrict__ w, const float* __restrict__ b,
                       float* __restrict__ out)
{
    int g = blockIdx.x, lane = threadIdx.x;
    float p = g_pool[g * 64 + lane] * w[lane] + g_pool[g * 64 + 32 + lane] * w[32 + lane];
#pragma unroll
    for (int o = 16; o > 0; o >>= 1) p += __shfl_xor_sync(0xffffffffu, p, o);
    if (lane == 0) out[g] = p / fmaxf(g_cnt[g], 1.0f) + b[0];
}

// ---------------- launch ----------------
extern "C" void kernel_launch(void* const* d_in, const int* in_sizes, int n_in,
                              void* d_out, int out_size)
{
    const float* node_s    = (const float*)d_in[0];
    const float* node_type = (const float*)d_in[1];
    const float* pos       = (const float*)d_in[2];
    const int*   ei        = (const int*)d_in[3];
    const float* edge_s    = (const float*)d_in[4];
    const int*   batch     = (const int*)d_in[5];
    const float* lin_in_w  = (const float*)d_in[6];
    const float* lin_in_b  = (const float*)d_in[7];
    const float* msg_w1    = (const float*)d_in[8];
    const float* msg_b1    = (const float*)d_in[9];
    const float* msg_g1    = (const float*)d_in[10];
    const float* msg_be1   = (const float*)d_in[11];
    const float* msg_w2    = (const float*)d_in[12];
    const float* msg_b2    = (const float*)d_in[13];
    const float* msg_g2    = (const float*)d_in[14];
    const float* msg_be2   = (const float*)d_in[15];
    const float* updf_w1   = (const float*)d_in[16];
    const float* updf_b1   = (const float*)d_in[17];
    const float* updf_g1   = (const float*)d_in[18];
    const float* updf_be1  = (const float*)d_in[19];
    const float* updf_w2   = (const float*)d_in[20];
    const float* updf_b2   = (const float*)d_in[21];
    const float* updc_w1   = (const float*)d_in[22];
    const float* updc_b1   = (const float*)d_in[23];
    const float* updc_g1   = (const float*)d_in[24];
    const float* updc_be1  = (const float*)d_in[25];
    const float* updc_w2   = (const float*)d_in[26];
    const float* updc_b2   = (const float*)d_in[27];
    const float* lin_pred_w = (const float*)d_in[28];
    const float* lin_pred_b = (const float*)d_in[29];

    k_init<<<(NN * 64 + 255) / 256, 256>>>(node_s, node_type, pos, lin_in_w, lin_in_b);
    k_hist<<<(NE + 255) / 256, 256>>>(ei);
    k_scan<<<1, 1024>>>();
    k_fill<<<(NE + 255) / 256, 256>>>(ei);
    k_esperm<<<(NE * 4 + 255) / 256, 256>>>(edge_s);
    k_wpack_all<<<(NL * 64 * 256 + 255) / 256, 256>>>(msg_w1, updc_w1);

    for (int l = 0; l < NL; l++) {
        const float* mw1 = msg_w1 + (size_t)l * 64 * 161;
        const float* mb1 = msg_b1 + l * 64;
        const float* mw2 = msg_w2 + (size_t)l * 64 * 64;
        const float* mb2 = msg_b2 + l * 64;
        const float* cw1 = updc_w1 + (size_t)l * 64 * 161;
        const float* cb1 = updc_b1 + l * 64;
        const float* cw2 = updc_w2 + (size_t)l * 64;
        const float* cb2 = updc_b2 + l;
        const float* uw1 = updf_w1 + (size_t)l * 64 * 128;
        const float* ub1 = updf_b1 + l * 64;
        const float* uw2 = updf_w2 + (size_t)l * 64 * 64;
        const float* ub2 = updf_b2 + l * 64;

        k_hpre<<<592, 256>>>(l);
        k_edgeAmma<<<592, 256>>>(l, mw1, mb1, cw1, cb1);
        k_edgeBmma<<<592, 256>>>(l, msg_g1 + l * 64, msg_be1 + l * 64,
                                 updc_g1 + l * 64, updc_be1 + l * 64,
                                 mw2, mb2, cw2, cb2);
        k_aggr<<<(NN * 32 + 255) / 256, 256>>>(l, msg_g2 + l * 64, msg_be2 + l * 64);
        k_node1<<<592, 256>>>(l, uw1, ub1);
        k_node2<<<592, 256>>>(l, updf_g1 + l * 64, updf_be1 + l * 64, uw2, ub2);
    }

    k_pool<<<(NN * 16 + 255) / 256, 256>>>(batch);
    k_pred<<<NG, 32>>>(lin_pred_w, lin_pred_b, (float*)d_out);
}

// round 15
// speedup vs baseline: 1.1176x; 1.0053x over previous
#include <cuda_runtime.h>
#include <cuda_fp16.h>
#include <math.h>
#include <stdint.h>

#define NN 50000
#define NE 800000
#define NL 4
#define NG 64
#define EPS 1e-5f

// ---------------- static device scratch ----------------
__device__ __align__(16) float g_h[NN * 64];
__device__ __align__(16) __half g_uh[(size_t)NN * 128];  // [h | aggr_h] fp16
__device__ __align__(16) __half g_unh[NN * 64];
__device__ __align__(16) float g_pos[NN * 3];
__device__ __align__(16) float g_aggr_p[NN * 3];
__device__ __align__(16) __half g_HpreH[(size_t)NN * 256];
__device__ __align__(16) float g_wpack4[NL][64 * 256];  // k-major [k][op]
__device__ __align__(16) __half g_esh[(size_t)NE * 32];
__device__ __align__(16) __half g_t1h[(size_t)NE * 64];
__device__ __align__(16) __half g_t2h[(size_t)NE * 64];
__device__ __align__(16) __half g_mlinh[(size_t)NE * 64];
__device__ __align__(16) float g_sc[NE];
__device__ int g_deg[NN];           // zero at static init; self-cleaned by k_scan each run
__device__ int g_rowstart[NN + 1];
__device__ int g_cursor[NN];
__device__ int g_csrsrc[NE];
__device__ int g_csrdst[NE];
__device__ double g_sum[NL * 256];
__device__ double g_sumsq[NL * 256];
__device__ __align__(16) float g_pool[NG * 64];
__device__ float g_cnt[NG];

__device__ __forceinline__ float silu_f(float y) {
    return y * (1.0f / (1.0f + __expf(-y)));
}

__device__ __forceinline__ void red_add_v4(float* p, float a, float b, float c, float d) {
    asm volatile("red.global.add.v4.f32 [%0], {%1,%2,%3,%4};"
                 :: "l"(p), "f"(a), "f"(b), "f"(c), "f"(d) : "memory");
}

__device__ __forceinline__ void mma_f16(float* c, uint32_t a0, uint32_t a1, uint32_t a2, uint32_t a3,
                                        uint32_t b0, uint32_t b1) {
    asm volatile("mma.sync.aligned.m16n8k16.row.col.f32.f16.f16.f32 "
                 "{%0,%1,%2,%3}, {%4,%5,%6,%7}, {%8,%9}, {%0,%1,%2,%3};"
                 : "+f"(c[0]), "+f"(c[1]), "+f"(c[2]), "+f"(c[3])
                 : "r"(a0), "r"(a1), "r"(a2), "r"(a3), "r"(b0), "r"(b1));
}

__device__ __forceinline__ void packsplit(float x, float y, uint32_t& h, uint32_t& l) {
    __half hx = __float2half_rn(x), hy = __float2half_rn(y);
    __half lx = __float2half_rn(x - __half2float(hx));
    __half ly = __float2half_rn(y - __half2float(hy));
    __half2 hh = __halves2half2(hx, hy), ll = __halves2half2(lx, ly);
    h = *(uint32_t*)&hh; l = *(uint32_t*)&ll;
}

// ---------------- init: h/uh/pos init + pool/stats zero + hist + wpack ----------------
__global__ void k_init(const float* __restrict__ ns, const float* __restrict__ nt,
                       const float* __restrict__ pos, const float* __restrict__ w,
                       const float* __restrict__ b, const int* __restrict__ ei,
                       const float* __restrict__ mw1a, const float* __restrict__ cw1a)
{
    int idx = blockIdx.x * blockDim.x + threadIdx.x;
    if (idx < NG * 64) g_pool[idx] = 0.f;
    if (idx < NG) g_cnt[idx] = 0.f;
    if (idx < NL * 256) { g_sum[idx] = 0.0; g_sumsq[idx] = 0.0; }
    if (idx < NE) atomicAdd(&g_deg[ei[NE + idx]], 1);   // g_deg zeroed by prev k_scan / static init
    if (idx < NL * 64 * 256) {
        int l = idx >> 14;
        int r = idx & 16383;
        int k = r >> 8, op = r & 255, o = op & 63;
        const float* mw1 = mw1a + (size_t)l * 64 * 161;
        const float* cw1 = cw1a + (size_t)l * 64 * 161;
        float v;
        if (op < 64)       v = mw1[o * 161 + k];
        else if (op < 128) v = mw1[o * 161 + 64 + k];
        else if (op < 192) v = cw1[o * 161 + k];
        else               v = cw1[o * 161 + 64 + k];
        g_wpack4[l][k * 256 + op] = v;
    }
    if (idx >= NN * 64) return;
    int n = idx >> 6, o = idx & 63;
    const float* wr = w + o * 8;
    const float* s = ns + n * 6;
    float acc = b[o];
#pragma unroll
    for (int i = 0; i < 6; i++) acc = fmaf(s[i], wr[i], acc);
    acc = fmaf(nt[n * 2 + 0], wr[6], acc);
    acc = fmaf(nt[n * 2 + 1], wr[7], acc);
    g_h[idx] = acc;
    g_uh[(size_t)n * 128 + o] = __float2half_rn(acc);
    if (o < 3) g_pos[n * 3 + o] = pos[n * 3 + o];
}

// ---------------- scan (self-cleans g_deg for next replay) ----------------
__global__ __launch_bounds__(1024) void k_scan()
{
    __shared__ int ssum[1024];
    int t = threadIdx.x;
    const int C = 49;
    int begin = t * C;
    int end = begin + C; if (end > NN) end = NN;
    if (begin > NN) begin = NN;
    int s = 0;
    for (int i = begin; i < end; i++) s += g_deg[i];
    ssum[t] = s;
    __syncthreads();
    for (int off = 1; off < 1024; off <<= 1) {
        int v = (t >= off) ? ssum[t - off] : 0;
        __syncthreads();
        ssum[t] += v;
        __syncthreads();
    }
    int run = ssum[t] - s;
    for (int i = begin; i < end; i++) {
        g_rowstart[i] = run;
        g_cursor[i] = run;
        run += g_deg[i];
        g_deg[i] = 0;      // self-clean for next replay
    }
    if (t == 1023) g_rowstart[NN] = ssum[1023];
}

// ---------------- fill + permute edge_s into CSR order as fp16 ----------------
__global__ void k_fillperm(const int* __restrict__ ei, const float* __restrict__ es)
{
    int e = blockIdx.x * blockDim.x + threadIdx.x;
    if (e >= NE) return;
    int s = ei[e], d = ei[NE + e];
    int p = atomicAdd(&g_cursor[d], 1);
    g_csrsrc[p] = s;
    g_csrdst[p] = d;
    const float4* ep = (const float4*)&es[(size_t)e * 32];
    __half hv[8];
#pragma unroll
    for (int q = 0; q < 4; q++) {
        float4 v0 = ep[2 * q], v1 = ep[2 * q + 1];
        hv[0] = __float2half_rn(v0.x); hv[1] = __float2half_rn(v0.y);
        hv[2] = __float2half_rn(v0.z); hv[3] = __float2half_rn(v0.w);
        hv[4] = __float2half_rn(v1.x); hv[5] = __float2half_rn(v1.y);
        hv[6] = __float2half_rn(v1.z); hv[7] = __float2half_rn(v1.w);
        *(uint4*)&g_esh[(size_t)p * 32 + q * 8] = *(uint4*)hv;
    }
}

// ---------------- Hpre (fp16 MMA): 64 nodes x 256 out (2 phases), K=64 ----------------
__global__ __launch_bounds__(256) void k_hpre(int layer)
{
    const float* wpack = g_wpack4[layer];
    __shared__ __align__(16) __half sH[64][72];
    __shared__ __align__(16) float sOut[64][132];
    int tid = threadIdx.x;
    int warp = tid >> 5, lane = tid & 31;
    int gid = lane >> 2, tig = lane & 3;

    uint32_t ah[2][4][4], al[2][4][4];
#pragma unroll
    for (int ph = 0; ph < 2; ph++) {
        int op0 = ph * 128 + warp * 16 + gid;
        int op1 = op0 + 8;
#pragma unroll
        for (int kb = 0; kb < 4; kb++) {
            int k0 = kb * 16 + 2 * tig;
            packsplit(wpack[k0 * 256 + op0], wpack[(k0 + 1) * 256 + op0], ah[ph][kb][0], al[ph][kb][0]);
            packsplit(wpack[k0 * 256 + op1], wpack[(k0 + 1) * 256 + op1], ah[ph][kb][1], al[ph][kb][1]);
            packsplit(wpack[(k0 + 8) * 256 + op0], wpack[(k0 + 9) * 256 + op0], ah[ph][kb][2], al[ph][kb][2]);
            packsplit(wpack[(k0 + 8) * 256 + op1], wpack[(k0 + 9) * 256 + op1], ah[ph][kb][3], al[ph][kb][3]);
        }
    }
    int ntiles = (NN + 63) >> 6;
    int el = tid >> 2, q = tid & 3;
    for (int t = blockIdx.x; t < ntiles; t += gridDim.x) {
        int n0 = t << 6;
        __syncthreads();
        {
            int n = n0 + el;
            __half hv[16];
            if (n < NN) {
                const float4* hp = (const float4*)&g_h[n * 64 + q * 16];
#pragma unroll
                for (int m = 0; m < 4; m++) {
                    float4 v = hp[m];
                    hv[4 * m] = __float2half_rn(v.x); hv[4 * m + 1] = __float2half_rn(v.y);
                    hv[4 * m + 2] = __float2half_rn(v.z); hv[4 * m + 3] = __float2half_rn(v.w);
                }
            } else {
#pragma unroll
                for (int m = 0; m < 16; m++) hv[m] = __float2half_rn(0.f);
            }
            *(uint4*)&sH[el][q * 16] = *(uint4*)&hv[0];
            *(uint4*)&sH[el][q * 16 + 8] = *(uint4*)&hv[8];
        }
        __syncthreads();
        for (int ph = 0; ph < 2; ph++) {
            float c[8][4];
#pragma unroll
            for (int nb = 0; nb < 8; nb++)
#pragma unroll
                for (int j = 0; j < 4; j++) c[nb][j] = 0.f;
#pragma unroll
            for (int kb = 0; kb < 4; kb++) {
#pragma unroll
                for (int nb = 0; nb < 8; nb++) {
                    int col = nb * 8 + gid;
                    uint32_t b0 = *(const uint32_t*)&sH[col][kb * 16 + 2 * tig];
                    uint32_t b1 = *(const uint32_t*)&sH[col][kb * 16 + 2 * tig + 8];
                    mma_f16(c[nb], ah[ph][kb][0], ah[ph][kb][1], ah[ph][kb][2], ah[ph][kb][3], b0, b1);
                    mma_f16(c[nb], al[ph][kb][0], al[ph][kb][1], al[ph][kb][2], al[ph][kb][3], b0, b1);
                }
            }
            {
                int ch = warp * 16 + gid;
#pragma unroll
                for (int nb = 0; nb < 8; nb++) {
                    int e = nb * 8 + 2 * tig;
                    sOut[e][ch] = c[nb][0];
                    sOut[e + 1][ch] = c[nb][1];
                    sOut[e][ch + 8] = c[nb][2];
                    sOut[e + 1][ch + 8] = c[nb][3];
                }
            }
            __syncthreads();
            {
                int n = n0 + el;
                if (n < NN) {
                    __half hv[32];
#pragma unroll
                    for (int m = 0; m < 32; m++) hv[m] = __float2half_rn(sOut[el][q * 32 + m]);
                    uint4* dst = (uint4*)&g_HpreH[(size_t)n * 256 + ph * 128 + q * 32];
                    dst[0] = *(uint4*)&hv[0];
                    dst[1] = *(uint4*)&hv[8];
                    dst[2] = *(uint4*)&hv[16];
                    dst[3] = *(uint4*)&hv[24];
                }
            }
            __syncthreads();
        }
    }
}

// ---------------- edge A (fp16 MMA, CSR order) ----------------
__global__ __launch_bounds__(256) void k_edgeAmma(int layer,
                                                  const float* __restrict__ mw1, const float* __restrict__ mb1,
                                                  const float* __restrict__ cw1, const float* __restrict__ cb1)
{
    __shared__ __align__(16) __half sEs[64][40];
    __shared__ __align__(16) float sOut[64][132];
    __shared__ float sR[64];
    __shared__ int sSrc[64], sDst[64];
    __shared__ float sS[128], sQ[128];

    int tid = threadIdx.x;
    int warp = tid >> 5, lane = tid & 31;
    int gid = lane >> 2, tig = lane & 3;
    int sl = layer * 256;

    if (tid < 128) { sS[tid] = 0.f; sQ[tid] = 0.f; }

    uint32_t ah[2][4], al[2][4];
    {
        int r0 = warp * 16 + gid;
        int r1 = r0 + 8;
        const float* w0 = (r0 < 64) ? &mw1[r0 * 161 + 129] : &cw1[(r0 - 64) * 161 + 129];
        const float* w1 = (r1 < 64) ? &mw1[r1 * 161 + 129] : &cw1[(r1 - 64) * 161 + 129];
#pragma unroll
        for (int kb = 0; kb < 2; kb++) {
            int k0 = kb * 16 + 2 * tig;
            packsplit(w0[k0], w0[k0 + 1], ah[kb][0], al[kb][0]);
            packsplit(w1[k0], w1[k0 + 1], ah[kb][1], al[kb][1]);
            packsplit(w0[k0 + 8], w0[k0 + 9], ah[kb][2], al[kb][2]);
            packsplit(w1[k0 + 8], w1[k0 + 9], ah[kb][3], al[kb][3]);
        }
    }
    int ch0 = lane << 2;
    float wr4[4], bb4[4];
#pragma unroll
    for (int j = 0; j < 4; j++) {
        int ch = ch0 + j;
        wr4[j] = (ch < 64) ? mw1[ch * 161 + 128] : cw1[(ch - 64) * 161 + 128];
        bb4[j] = (ch < 64) ? mb1[ch] : cb1[ch - 64];
    }
    int hd_off = (ch0 < 64) ? ch0 : 64 + ch0;
    int hs_off = (ch0 < 64) ? 64 + ch0 : 128 + ch0;
    float st[4] = {0.f, 0.f, 0.f, 0.f}, sq[4] = {0.f, 0.f, 0.f, 0.f};

    for (int t = blockIdx.x; t < NE / 64; t += gridDim.x) {
        int p0 = t << 6;
        __syncthreads();
        if (tid < 64) {
            int p = p0 + tid;
            int s = g_csrsrc[p], d = g_csrdst[p];
            sSrc[tid] = s; sDst[tid] = d;
            float dx = g_pos[d * 3] - g_pos[s * 3];
            float dy = g_pos[d * 3 + 1] - g_pos[s * 3 + 1];
            float dz = g_pos[d * 3 + 2] - g_pos[s * 3 + 2];
            sR[tid] = sqrtf(dx * dx + dy * dy + dz * dz);
        }
        {
            int el = tid >> 2, q = tid & 3;
            *(uint4*)&sEs[el][q * 8] = *(const uint4*)&g_esh[(size_t)(p0 + el) * 32 + q * 8];
        }
        __syncthreads();
        float c[8][4];
#pragma unroll
        for (int nb = 0; nb < 8; nb++)
#pragma unroll
            for (int j = 0; j < 4; j++) c[nb][j] = 0.f;
#pragma unroll
        for (int kb = 0; kb < 2; kb++) {
#pragma unroll
            for (int nb = 0; nb < 8; nb++) {
                int col = nb * 8 + gid;
                uint32_t b0 = *(const uint32_t*)&sEs[col][kb * 16 + 2 * tig];
                uint32_t b1 = *(const uint32_t*)&sEs[col][kb * 16 + 2 * tig + 8];
                mma_f16(c[nb], ah[kb][0], ah[kb][1], ah[kb][2], ah[kb][3], b0, b1);
                mma_f16(c[nb], al[kb][0], al[kb][1], al[kb][2], al[kb][3], b0, b1);
            }
        }
        // transpose into sOut (separate buffer; own-warp MMAs complete in order)
        {
            int ch = warp * 16 + gid;
#pragma unroll
            for (int nb = 0; nb < 8; nb++) {
                int e = nb * 8 + 2 * tig;
                sOut[e][ch] = c[nb][0];
                sOut[e + 1][ch] = c[nb][1];
                sOut[e][ch + 8] = c[nb][2];
                sOut[e + 1][ch + 8] = c[nb][3];
            }
        }
        __syncthreads();
#pragma unroll 2
        for (int ee = 0; ee < 8; ee++) {
            int e = warp * 8 + ee;
            int d = sDst[e], s = sSrc[e];
            float r = sR[e];
            uint2 du = *(const uint2*)&g_HpreH[(size_t)d * 256 + hd_off];
            uint2 su = *(const uint2*)&g_HpreH[(size_t)s * 256 + hs_off];
            float2 d01 = __half22float2(*(__half2*)&du.x);
            float2 d23 = __half22float2(*(__half2*)&du.y);
            float2 s01 = __half22float2(*(__half2*)&su.x);
            float2 s23 = __half22float2(*(__half2*)&su.y);
            float4 o = *(const float4*)&sOut[e][ch0];
            __half hv[4];
            hv[0] = __float2half_rn(o.x + d01.x + s01.x + fmaf(r, wr4[0], bb4[0]));
            hv[1] = __float2half_rn(o.y + d01.y + s01.y + fmaf(r, wr4[1], bb4[1]));
            hv[2] = __float2half_rn(o.z + d23.x + s23.x + fmaf(r, wr4[2], bb4[2]));
            hv[3] = __float2half_rn(o.w + d23.y + s23.y + fmaf(r, wr4[3], bb4[3]));
            int p = p0 + e;
            __half* out = (ch0 < 64) ? &g_t1h[(size_t)p * 64 + ch0]
                                     : &g_t2h[(size_t)p * 64 + ch0 - 64];
            *(uint2*)out = *(uint2*)hv;
#pragma unroll
            for (int j = 0; j < 4; j++) {
                float yr = __half2float(hv[j]);
                st[j] += yr; sq[j] += yr * yr;
            }
        }
    }
    __syncthreads();
#pragma unroll
    for (int j = 0; j < 4; j++) { atomicAdd(&sS[ch0 + j], st[j]); atomicAdd(&sQ[ch0 + j], sq[j]); }
    __syncthreads();
    if (tid < 128) {
        atomicAdd(&g_sum[sl + tid], (double)sS[tid]);
        atomicAdd(&g_sumsq[sl + tid], (double)sQ[tid]);
    }
}

// ---------------- edge B (fp16 MMA): BN computed locally from stats ----------------
__global__ __launch_bounds__(256) void k_edgeBmma(int layer,
                                                  const float* __restrict__ mg1, const float* __restrict__ mbe1,
                                                  const float* __restrict__ cg1, const float* __restrict__ cbe1,
                                                  const float* __restrict__ mw2, const float* __restrict__ mb2,
                                                  const float* __restrict__ cw2, const float* __restrict__ cb2)
{
    __shared__ __align__(16) __half sX[64][72];
    __shared__ __align__(16) float sOut[64 * 68];
    __shared__ float sS[64], sQ[64];
    __shared__ float sCA[64], sCB[64], sDA[64], sDB[64], sWc2[64];

    int tid = threadIdx.x;
    int warp = tid >> 5, lane = tid & 31;
    int gid = lane >> 2, tig = lane & 3;
    int m0 = (warp & 3) << 4;
    int n0 = (warp >> 2) << 5;
    int sl = layer * 256;

    if (tid < 64) {
        double m = g_sum[sl + tid] * (1.0 / NE);
        double v = g_sumsq[sl + tid] * (1.0 / NE) - m * m;
        float A = mg1[tid] * rsqrtf((float)v + EPS);
        sCA[tid] = A; sCB[tid] = mbe1[tid] - (float)m * A;
        sS[tid] = 0.f; sQ[tid] = 0.f;
        sWc2[tid] = cw2[tid];
    } else if (tid < 128) {
        int c = tid - 64;
        double m = g_sum[sl + 64 + c] * (1.0 / NE);
        double v = g_sumsq[sl + 64 + c] * (1.0 / NE) - m * m;
        float A = cg1[c] * rsqrtf((float)v + EPS);
        sDA[c] = A; sDB[c] = cbe1[c] - (float)m * A;
    }

    uint32_t ah[4][4], al[4][4];
    {
        const float* w0 = mw2 + (size_t)(m0 + gid) * 64;
        const float* w1 = mw2 + (size_t)(m0 + gid + 8) * 64;
#pragma unroll
        for (int kb = 0; kb < 4; kb++) {
            int k0 = kb * 16 + 2 * tig;
            packsplit(w0[k0], w0[k0 + 1], ah[kb][0], al[kb][0]);
            packsplit(w1[k0], w1[k0 + 1], ah[kb][1], al[kb][1]);
            packsplit(w0[k0 + 8], w0[k0 + 9], ah[kb][2], al[kb][2]);
            packsplit(w1[k0 + 8], w1[k0 + 9], ah[kb][3], al[kb][3]);
        }
    }
    float bias0 = mb2[m0 + gid], bias1 = mb2[m0 + gid + 8];
    float cbias = cb2[0];
    float s0 = 0.f, q0 = 0.f, s1 = 0.f, q1 = 0.f;

    int el = tid >> 2, q = tid & 3;

    for (int t = blockIdx.x; t < NE / 64; t += gridDim.x) {
        int e0 = t << 6;
        __syncthreads();
        {
            const uint4* tb = (const uint4*)&g_t1h[(size_t)(e0 + el) * 64 + q * 16];
            __half2 hbuf[8];
            *(uint4*)&hbuf[0] = tb[0];
            *(uint4*)&hbuf[4] = tb[1];
            __half xv[16];
#pragma unroll
            for (int m = 0; m < 8; m++) {
                float2 f = __half22float2(hbuf[m]);
                int c = q * 16 + 2 * m;
                xv[2 * m]     = __float2half_rn(silu_f(fmaf(f.x, sCA[c], sCB[c])));
                xv[2 * m + 1] = __float2half_rn(silu_f(fmaf(f.y, sCA[c + 1], sCB[c + 1])));
            }
            *(uint4*)&sX[el][q * 16] = *(uint4*)&xv[0];
            *(uint4*)&sX[el][q * 16 + 8] = *(uint4*)&xv[8];
        }
        {
            const uint4* tb = (const uint4*)&g_t2h[(size_t)(e0 + el) * 64 + q * 16];
            __half2 hbuf[8];
            *(uint4*)&hbuf[0] = tb[0];
            *(uint4*)&hbuf[4] = tb[1];
            float part = 0.f;
#pragma unroll
            for (int m = 0; m < 8; m++) {
                float2 f = __half22float2(hbuf[m]);
                int c = q * 16 + 2 * m;
                part += silu_f(fmaf(f.x, sDA[c], sDB[c])) * sWc2[c];
                part += silu_f(fmaf(f.y, sDA[c + 1], sDB[c + 1])) * sWc2[c + 1];
            }
            part += __shfl_xor_sync(0xffffffffu, part, 1);
            part += __shfl_xor_sync(0xffffffffu, part, 2);
            if (q == 0) g_sc[e0 + el] = part + cbias;
        }
        __syncthreads();
        float c[4][4];
#pragma unroll
        for (int nb = 0; nb < 4; nb++)
#pragma unroll
            for (int j = 0; j < 4; j++) c[nb][j] = 0.f;
#pragma unroll
        for (int kb = 0; kb < 4; kb++) {
#pragma unroll
            for (int nb = 0; nb < 4; nb++) {
                int col = n0 + nb * 8 + gid;
                uint32_t b0 = *(const uint32_t*)&sX[col][kb * 16 + 2 * tig];
                uint32_t b1 = *(const uint32_t*)&sX[col][kb * 16 + 2 * tig + 8];
                mma_f16(c[nb], ah[kb][0], ah[kb][1], ah[kb][2], ah[kb][3], b0, b1);
                mma_f16(c[nb], al[kb][0], al[kb][1], al[kb][2], al[kb][3], b0, b1);
            }
        }
#pragma unroll
        for (int nb = 0; nb < 4; nb++) {
            int e = n0 + nb * 8 + 2 * tig;
            float yr00 = __half2float(__float2half_rn(c[nb][0] + bias0));
            float yr01 = __half2float(__float2half_rn(c[nb][1] + bias0));
            float yr10 = __half2float(__float2half_rn(c[nb][2] + bias1));
            float yr11 = __half2float(__float2half_rn(c[nb][3] + bias1));
            sOut[e * 68 + m0 + gid] = yr00;
            sOut[(e + 1) * 68 + m0 + gid] = yr01;
            sOut[e * 68 + m0 + gid + 8] = yr10;
            sOut[(e + 1) * 68 + m0 + gid + 8] = yr11;
            s0 += yr00 + yr01; q0 += yr00 * yr00 + yr01 * yr01;
            s1 += yr10 + yr11; q1 += yr10 * yr10 + yr11 * yr11;
        }
        __syncthreads();
        {
            const float* src = &sOut[el * 68 + q * 16];
            __half hv[16];
#pragma unroll
            for (int m = 0; m < 16; m++) hv[m] = __float2half_rn(src[m]);
            uint4* dst = (uint4*)&g_mlinh[(size_t)(e0 + el) * 64 + q * 16];
            dst[0] = *(uint4*)&hv[0];
            dst[1] = *(uint4*)&hv[8];
        }
    }
    __syncthreads();
    atomicAdd(&sS[m0 + gid], s0); atomicAdd(&sQ[m0 + gid], q0);
    atomicAdd(&sS[m0 + gid + 8], s1); atomicAdd(&sQ[m0 + gid + 8], q1);
    __syncthreads();
    if (tid < 64) {
        atomicAdd(&g_sum[sl + 128 + tid], (double)sS[tid]);
        atomicAdd(&g_sumsq[sl + 128 + tid], (double)sQ[tid]);
    }
}

// ---------------- aggregation: warp per node, half2 loads; writes g_uh fp16 ----------------
__global__ __launch_bounds__(256) void k_aggr(int layer,
                                              const float* __restrict__ g2, const float* __restrict__ be2)
{
    int gwarp = (blockIdx.x * blockDim.x + threadIdx.x) >> 5;
    int lane = threadIdx.x & 31;
    if (gwarp >= NN) return;
    int n = gwarp;
    int sl = layer * 256;
    const double inv = 1.0 / NE;
    int c0 = 2 * lane;
    float A0, B0, A1, B1;
    {
        double m = g_sum[sl + 128 + c0] * inv;
        double v = g_sumsq[sl + 128 + c0] * inv - m * m;
        A0 = g2[c0] * rsqrtf((float)v + EPS);
        B0 = be2[c0] - (float)m * A0;
        m = g_sum[sl + 128 + c0 + 1] * inv;
        v = g_sumsq[sl + 128 + c0 + 1] * inv - m * m;
        A1 = g2[c0 + 1] * rsqrtf((float)v + EPS);
        B1 = be2[c0 + 1] - (float)m * A1;
    }
    int s0 = g_rowstart[n], s1 = g_rowstart[n + 1];
    float acc0 = 0.f, acc1 = 0.f;
    for (int i = s0; i < s1; i++) {
        uint32_t u = *(const uint32_t*)&g_mlinh[(size_t)i * 64 + c0];
        float2 f = __half22float2(*(__half2*)&u);
        acc0 += silu_f(fmaf(f.x, A0, B0));
        acc1 += silu_f(fmaf(f.y, A1, B1));
    }
    __half2 hv = __halves2half2(__float2half_rn(acc0), __float2half_rn(acc1));
    *(__half2*)&g_uh[(size_t)n * 128 + 64 + c0] = hv;
    float px = g_pos[n * 3], py = g_pos[n * 3 + 1], pz = g_pos[n * 3 + 2];
    float cx = 0.f, cy = 0.f, cz = 0.f;
    for (int i = s0 + lane; i < s1; i += 32) {
        int src = g_csrsrc[i];
        float sc = g_sc[i];
        cx += sc * (px - g_pos[src * 3]);
        cy += sc * (py - g_pos[src * 3 + 1]);
        cz += sc * (pz - g_pos[src * 3 + 2]);
    }
#pragma unroll
    for (int o = 16; o > 0; o >>= 1) {
        cx += __shfl_xor_sync(0xffffffffu, cx, o);
        cy += __shfl_xor_sync(0xffffffffu, cy, o);
        cz += __shfl_xor_sync(0xffffffffu, cz, o);
    }
    if (lane == 0) {
        g_aggr_p[n * 3 + 0] = cx;
        g_aggr_p[n * 3 + 1] = cy;
        g_aggr_p[n * 3 + 2] = cz;
    }
}

// ---------------- node 1 (fp16 MMA): un = uh(128) @ uw1^T + b ----------------
__global__ __launch_bounds__(256) void k_node1(int layer,
                                               const float* __restrict__ uw1, const float* __restrict__ ub1)
{
    __shared__ __align__(16) __half sU[64][136];
    __shared__ __align__(16) float sOut[64 * 68];
    __shared__ float sS[64], sQ[64];
    int tid = threadIdx.x;
    int warp = tid >> 5, lane = tid & 31;
    int gid = lane >> 2, tig = lane & 3;
    int m0 = (warp & 3) << 4;
    int n0 = (warp >> 2) << 5;
    int sl = layer * 256;
    if (tid < 64) { sS[tid] = 0.f; sQ[tid] = 0.f; }

    uint32_t ah[8][4], al[8][4];
    {
        const float* w0 = uw1 + (size_t)(m0 + gid) * 128;
        const float* w1 = uw1 + (size_t)(m0 + gid + 8) * 128;
#pragma unroll
        for (int kb = 0; kb < 8; kb++) {
            int k0 = kb * 16 + 2 * tig;
            packsplit(w0[k0], w0[k0 + 1], ah[kb][0], al[kb][0]);
            packsplit(w1[k0], w1[k0 + 1], ah[kb][1], al[kb][1]);
            packsplit(w0[k0 + 8], w0[k0 + 9], ah[kb][2], al[kb][2]);
            packsplit(w1[k0 + 8], w1[k0 + 9], ah[kb][3], al[kb][3]);
        }
    }
    float bias0 = ub1[m0 + gid], bias1 = ub1[m0 + gid + 8];
    float s0 = 0.f, q0 = 0.f, s1 = 0.f, q1 = 0.f;
    int el = tid >> 2, q = tid & 3;
    int ntiles = (NN + 63) >> 6;

    for (int t = blockIdx.x; t < ntiles; t += gridDim.x) {
        int tn0 = t << 6;
        __syncthreads();
        {
            int n = tn0 + el;
            uint4 v0, v1, v2, v3;
            if (n < NN) {
                const uint4* up = (const uint4*)&g_uh[(size_t)n * 128 + q * 32];
                v0 = up[0]; v1 = up[1]; v2 = up[2]; v3 = up[3];
            } else {
                v0 = v1 = v2 = v3 = make_uint4(0, 0, 0, 0);
            }
            uint4* dst = (uint4*)&sU[el][q * 32];
            dst[0] = v0; dst[1] = v1; dst[2] = v2; dst[3] = v3;
        }
        __syncthreads();
        float c[4][4];
#pragma unroll
        for (int nb = 0; nb < 4; nb++)
#pragma unroll
            for (int j = 0; j < 4; j++) c[nb][j] = 0.f;
#pragma unroll
        for (int kb = 0; kb < 8; kb++) {
#pragma unroll
            for (int nb = 0; nb < 4; nb++) {
                int col = n0 + nb * 8 + gid;
                uint32_t b0 = *(const uint32_t*)&sU[col][kb * 16 + 2 * tig];
                uint32_t b1 = *(const uint32_t*)&sU[col][kb * 16 + 2 * tig + 8];
                mma_f16(c[nb], ah[kb][0], ah[kb][1], ah[kb][2], ah[kb][3], b0, b1);
                mma_f16(c[nb], al[kb][0], al[kb][1], al[kb][2], al[kb][3], b0, b1);
            }
        }
#pragma unroll
        for (int nb = 0; nb < 4; nb++) {
            int e = n0 + nb * 8 + 2 * tig;
            float yr00 = __half2float(__float2half_rn(c[nb][0] + bias0));
            float yr01 = __half2float(__float2half_rn(c[nb][1] + bias0));
            float yr10 = __half2float(__float2half_rn(c[nb][2] + bias1));
            float yr11 = __half2float(__float2half_rn(c[nb][3] + bias1));
            sOut[e * 68 + m0 + gid] = yr00;
            sOut[(e + 1) * 68 + m0 + gid] = yr01;
            sOut[e * 68 + m0 + gid + 8] = yr10;
            sOut[(e + 1) * 68 + m0 + gid + 8] = yr11;
            bool v0 = (tn0 + e < NN), v1 = (tn0 + e + 1 < NN);
            if (v0) { s0 += yr00; q0 += yr00 * yr00; s1 += yr10; q1 += yr10 * yr10; }
            if (v1) { s0 += yr01; q0 += yr01 * yr01; s1 += yr11; q1 += yr11 * yr11; }
        }
        __syncthreads();
        {
            int n = tn0 + el;
            if (n < NN) {
                const float* src = &sOut[el * 68 + q * 16];
                __half hv[16];
#pragma unroll
                for (int m = 0; m < 16; m++) hv[m] = __float2half_rn(src[m]);
                uint4* dst = (uint4*)&g_unh[(size_t)n * 64 + q * 16];
                dst[0] = *(uint4*)&hv[0];
                dst[1] = *(uint4*)&hv[8];
            }
        }
    }
    __syncthreads();
    atomicAdd(&sS[m0 + gid], s0); atomicAdd(&sQ[m0 + gid], q0);
    atomicAdd(&sS[m0 + gid + 8], s1); atomicAdd(&sQ[m0 + gid + 8], q1);
    __syncthreads();
    if (tid < 64) {
        atomicAdd(&g_sum[sl + 192 + tid], (double)sS[tid]);
        atomicAdd(&g_sumsq[sl + 192 + tid], (double)sQ[tid]);
    }
}

// ---------------- node 2 (fp16 MMA): h += silu(bn(un)) @ uw2^T + b; pos update ----------------
__global__ __launch_bounds__(256) void k_node2(int layer,
                                               const float* __restrict__ ug1, const float* __restrict__ ube1,
                                               const float* __restrict__ uw2, const float* __restrict__ ub2)
{
    __shared__ __align__(16) __half sX[64][72];
    __shared__ __align__(16) float sOut[64 * 68];
    __shared__ float sBA[64], sBB[64];
    int tid = threadIdx.x;
    int warp = tid >> 5, lane = tid & 31;
    int gid = lane >> 2, tig = lane & 3;
    int m0 = (warp & 3) << 4;
    int n0 = (warp >> 2) << 5;
    int sl = layer * 256;
    if (tid < 64) {
        double m = g_sum[sl + 192 + tid] * (1.0 / NN);
        double v = g_sumsq[sl + 192 + tid] * (1.0 / NN) - m * m;
        float A = ug1[tid] * rsqrtf((float)v + EPS);
        sBA[tid] = A; sBB[tid] = ube1[tid] - (float)m * A;
    }
    uint32_t ah[4][4], al[4][4];
    {
        const float* w0 = uw2 + (size_t)(m0 + gid) * 64;
        const float* w1 = uw2 + (size_t)(m0 + gid + 8) * 64;
#pragma unroll
        for (int kb = 0; kb < 4; kb++) {
            int k0 = kb * 16 + 2 * tig;
            packsplit(w0[k0], w0[k0 + 1], ah[kb][0], al[kb][0]);
            packsplit(w1[k0], w1[k0 + 1], ah[kb][1], al[kb][1]);
            packsplit(w0[k0 + 8], w0[k0 + 9], ah[kb][2], al[kb][2]);
            packsplit(w1[k0 + 8], w1[k0 + 9], ah[kb][3], al[kb][3]);
        }
    }
    float bias0 = ub2[m0 + gid], bias1 = ub2[m0 + gid + 8];
    int el = tid >> 2, q = tid & 3;
    int ntiles = (NN + 63) >> 6;
    __syncthreads();

    for (int t = blockIdx.x; t < ntiles; t += gridDim.x) {
        int tn0 = t << 6;
        __syncthreads();
        {
            int n = tn0 + el;
            __half xv[16];
            if (n < NN) {
                const uint4* tb = (const uint4*)&g_unh[(size_t)n * 64 + q * 16];
                __half2 hbuf[8];
                *(uint4*)&hbuf[0] = tb[0];
                *(uint4*)&hbuf[4] = tb[1];
#pragma unroll
                for (int m = 0; m < 8; m++) {
                    float2 f = __half22float2(hbuf[m]);
                    int c = q * 16 + 2 * m;
                    xv[2 * m]     = __float2half_rn(silu_f(fmaf(f.x, sBA[c], sBB[c])));
                    xv[2 * m + 1] = __float2half_rn(silu_f(fmaf(f.y, sBA[c + 1], sBB[c + 1])));
                }
            } else {
#pragma unroll
                for (int m = 0; m < 16; m++) xv[m] = __float2half_rn(0.f);
            }
            *(uint4*)&sX[el][q * 16] = *(uint4*)&xv[0];
            *(uint4*)&sX[el][q * 16 + 8] = *(uint4*)&xv[8];
        }
        __syncthreads();
        float c[4][4];
#pragma unroll
        for (int nb = 0; nb < 4; nb++)
#pragma unroll
            for (int j = 0; j < 4; j++) c[nb][j] = 0.f;
#pragma unroll
        for (int kb = 0; kb < 4; kb++) {
#pragma unroll
            for (int nb = 0; nb < 4; nb++) {
                int col = n0 + nb * 8 + gid;
                uint32_t b0 = *(const uint32_t*)&sX[col][kb * 16 + 2 * tig];
                uint32_t b1 = *(const uint32_t*)&sX[col][kb * 16 + 2 * tig + 8];
                mma_f16(c[nb], ah[kb][0], ah[kb][1], ah[kb][2], ah[kb][3], b0, b1);
                mma_f16(c[nb], al[kb][0], al[kb][1], al[kb][2], al[kb][3], b0, b1);
            }
        }
#pragma unroll
        for (int nb = 0; nb < 4; nb++) {
            int e = n0 + nb * 8 + 2 * tig;
            sOut[e * 68 + m0 + gid] = c[nb][0] + bias0;
            sOut[(e + 1) * 68 + m0 + gid] = c[nb][1] + bias0;
            sOut[e * 68 + m0 + gid + 8] = c[nb][2] + bias1;
            sOut[(e + 1) * 68 + m0 + gid + 8] = c[nb][3] + bias1;
        }
        __syncthreads();
        {
            int n = tn0 + el;
            if (n < NN) {
                const float* src = &sOut[el * 68 + q * 16];
#pragma unroll
                for (int m = 0; m < 4; m++) {
                    float4 hold = *(const float4*)&g_h[n * 64 + q * 16 + 4 * m];
                    float4 hv = make_float4(hold.x + src[4 * m], hold.y + src[4 * m + 1],
                                            hold.z + src[4 * m + 2], hold.w + src[4 * m + 3]);
                    *(float4*)&g_h[n * 64 + q * 16 + 4 * m] = hv;
                    __half hh[4];
                    hh[0] = __float2half_rn(hv.x); hh[1] = __float2half_rn(hv.y);
                    hh[2] = __float2half_rn(hv.z); hh[3] = __float2half_rn(hv.w);
                    *(uint2*)&g_uh[(size_t)n * 128 + q * 16 + 4 * m] = *(uint2*)hh;
                }
            }
        }
        if (tid < 64) {
            int n = tn0 + tid;
            if (n < NN) {
                g_pos[n * 3 + 0] += g_aggr_p[n * 3 + 0];
                g_pos[n * 3 + 1] += g_aggr_p[n * 3 + 1];
                g_pos[n * 3 + 2] += g_aggr_p[n * 3 + 2];
            }
        }
    }
}

// ---------------- pooling ----------------
__global__ void k_pool(const int* __restrict__ batch)
{
    int idx = blockIdx.x * blockDim.x + threadIdx.x;
    if (idx >= NN * 16) return;
    int n = idx >> 4, c4 = (idx & 15) * 4;
    int b = batch[n];
    float4 h = *(const float4*)&g_h[n * 64 + c4];
    red_add_v4(&g_pool[b * 64 + c4], h.x, h.y, h.z, h.w);
    if (c4 == 0) atomicAdd(&g_cnt[b], 1.0f);
}

__global__ void k_pred(const float* __restrict__ w, const float* __restrict__ b,
                       float* __restrict__ out)
{
    int g = blockIdx.x, lane = threadIdx.x;
    float p = g_pool[g * 64 + lane] * w[lane] + g_pool[g * 64 + 32 + lane] * w[32 + lane];
#pragma unroll
    for (int o = 16; o > 0; o >>= 1) p += __shfl_xor_sync(0xffffffffu, p, o);
    if (lane == 0) out[g] = p / fmaxf(g_cnt[g], 1.0f) + b[0];
}

// ---------------- launch ----------------
extern "C" void kernel_launch(void* const* d_in, const int* in_sizes, int n_in,
                              void* d_out, int out_size)
{
    const float* node_s    = (const float*)d_in[0];
    const float* node_type = (const float*)d_in[1];
    const float* pos       = (const float*)d_in[2];
    const int*   ei        = (const int*)d_in[3];
    const float* edge_s    = (const float*)d_in[4];
    const int*   batch     = (const int*)d_in[5];
    const float* lin_in_w  = (const float*)d_in[6];
    const float* lin_in_b  = (const float*)d_in[7];
    const float* msg_w1    = (const float*)d_in[8];
    const float* msg_b1    = (const float*)d_in[9];
    const float* msg_g1    = (const float*)d_in[10];
    const float* msg_be1   = (const float*)d_in[11];
    const float* msg_w2    = (const float*)d_in[12];
    const float* msg_b2    = (const float*)d_in[13];
    const float* msg_g2    = (const float*)d_in[14];
    const float* msg_be2   = (const float*)d_in[15];
    const float* updf_w1   = (const float*)d_in[16];
    const float* updf_b1   = (const float*)d_in[17];
    const float* updf_g1   = (const float*)d_in[18];
    const float* updf_be1  = (const float*)d_in[19];
    const float* updf_w2   = (const float*)d_in[20];
    const float* updf_b2   = (const float*)d_in[21];
    const float* updc_w1   = (const float*)d_in[22];
    const float* updc_b1   = (const float*)d_in[23];
    const float* updc_g1   = (const float*)d_in[24];
    const float* updc_be1  = (const float*)d_in[25];
    const float* updc_w2   = (const float*)d_in[26];
    const float* updc_b2   = (const float*)d_in[27];
    const float* lin_pred_w = (const float*)d_in[28];
    const float* lin_pred_b = (const float*)d_in[29];

    k_init<<<(NN * 64 + 255) / 256, 256>>>(node_s, node_type, pos, lin_in_w, lin_in_b,
                                           ei, msg_w1, updc_w1);
    k_scan<<<1, 1024>>>();
    k_fillperm<<<(NE + 255) / 256, 256>>>(ei, edge_s);

    for (int l = 0; l < NL; l++) {
        const float* mw1 = msg_w1 + (size_t)l * 64 * 161;
        const float* mb1 = msg_b1 + l * 64;
        const float* mw2 = msg_w2 + (size_t)l * 64 * 64;
        const float* mb2 = msg_b2 + l * 64;
        const float* cw1 = updc_w1 + (size_t)l * 64 * 161;
        const float* cb1 = updc_b1 + l * 64;
        const float* cw2 = updc_w2 + (size_t)l * 64;
        const float* cb2 = updc_b2 + l;
        const float* uw1 = updf_w1 + (size_t)l * 64 * 128;
        const float* ub1 = updf_b1 + l * 64;
        const float* uw2 = updf_w2 + (size_t)l * 64 * 64;
        const float* ub2 = updf_b2 + l * 64;

        k_hpre<<<592, 256>>>(l);
        k_edgeAmma<<<592, 256>>>(l, mw1, mb1, cw1, cb1);
        k_edgeBmma<<<592, 256>>>(l, msg_g1 + l * 64, msg_be1 + l * 64,
                                 updc_g1 + l * 64, updc_be1 + l * 64,
                                 mw2, mb2, cw2, cb2);
        k_aggr<<<(NN * 32 + 255) / 256, 256>>>(l, msg_g2 + l * 64, msg_be2 + l * 64);
        k_node1<<<592, 256>>>(l, uw1, ub1);
        k_node2<<<592, 256>>>(l, updf_g1 + l * 64, updf_be1 + l * 64, uw2, ub2);
    }

    k_pool<<<(NN * 16 + 255) / 256, 256>>>(batch);
    k_pred<<<NG, 32>>>(lin_pred_w, lin_pred_b, (float*)d_out);
}

// round 16
// speedup vs baseline: 1.1188x; 1.0010x over previous
#include <cuda_runtime.h>
#include <cuda_fp16.h>
#include <math.h>
#include <stdint.h>

#define NN 50000
#define NE 800000
#define NL 4
#define NG 64
#define EPS 1e-5f

// ---------------- static device scratch ----------------
__device__ __align__(16) float g_h[NN * 64];
__device__ __align__(16) __half g_uh[(size_t)NN * 128];  // [h | aggr_h] fp16
__device__ __align__(16) __half g_unh[NN * 64];
__device__ __align__(16) float g_pos[NN * 3];
__device__ __align__(16) float g_aggr_p[NN * 3];
__device__ __align__(16) __half g_HpreH[(size_t)NN * 256];
__device__ __align__(16) float g_wpack4[NL][64 * 256];  // k-major [k][op]
__device__ __align__(16) __half g_esh[(size_t)NE * 32];
__device__ __align__(16) __half g_t1h[(size_t)NE * 64];
__device__ __align__(16) __half g_t2h[(size_t)NE * 64];
__device__ __align__(16) __half g_mlinh[(size_t)NE * 64];
__device__ __align__(16) float g_sc[NE];
__device__ int g_deg[NN];           // zero at static init; self-cleaned by k_scan each run
__device__ int g_rowstart[NN + 1];
__device__ int g_cursor[NN];
__device__ int g_csrsrc[NE];
__device__ int g_csrdst[NE];
__device__ double g_sum[NL * 256];
__device__ double g_sumsq[NL * 256];
__device__ __align__(16) float g_pool[NG * 64];
__device__ float g_cnt[NG];

__device__ __forceinline__ float silu_f(float y) {
    return y * (1.0f / (1.0f + __expf(-y)));
}

__device__ __forceinline__ void red_add_v4(float* p, float a, float b, float c, float d) {
    asm volatile("red.global.add.v4.f32 [%0], {%1,%2,%3,%4};"
                 :: "l"(p), "f"(a), "f"(b), "f"(c), "f"(d) : "memory");
}

__device__ __forceinline__ void mma_f16(float* c, uint32_t a0, uint32_t a1, uint32_t a2, uint32_t a3,
                                        uint32_t b0, uint32_t b1) {
    asm volatile("mma.sync.aligned.m16n8k16.row.col.f32.f16.f16.f32 "
                 "{%0,%1,%2,%3}, {%4,%5,%6,%7}, {%8,%9}, {%0,%1,%2,%3};"
                 : "+f"(c[0]), "+f"(c[1]), "+f"(c[2]), "+f"(c[3])
                 : "r"(a0), "r"(a1), "r"(a2), "r"(a3), "r"(b0), "r"(b1));
}

__device__ __forceinline__ void packsplit(float x, float y, uint32_t& h, uint32_t& l) {
    __half hx = __float2half_rn(x), hy = __float2half_rn(y);
    __half lx = __float2half_rn(x - __half2float(hx));
    __half ly = __float2half_rn(y - __half2float(hy));
    __half2 hh = __halves2half2(hx, hy), ll = __halves2half2(lx, ly);
    h = *(uint32_t*)&hh; l = *(uint32_t*)&ll;
}

// ---------------- init: h/uh/pos init + pool/stats zero + hist + wpack ----------------
__global__ void k_init(const float* __restrict__ ns, const float* __restrict__ nt,
                       const float* __restrict__ pos, const float* __restrict__ w,
                       const float* __restrict__ b, const int* __restrict__ ei,
                       const float* __restrict__ mw1a, const float* __restrict__ cw1a)
{
    int idx = blockIdx.x * blockDim.x + threadIdx.x;
    if (idx < NG * 64) g_pool[idx] = 0.f;
    if (idx < NG) g_cnt[idx] = 0.f;
    if (idx < NL * 256) { g_sum[idx] = 0.0; g_sumsq[idx] = 0.0; }
    if (idx < NE) atomicAdd(&g_deg[ei[NE + idx]], 1);   // g_deg zeroed by prev k_scan / static init
    if (idx < NL * 64 * 256) {
        int l = idx >> 14;
        int r = idx & 16383;
        int k = r >> 8, op = r & 255, o = op & 63;
        const float* mw1 = mw1a + (size_t)l * 64 * 161;
        const float* cw1 = cw1a + (size_t)l * 64 * 161;
        float v;
        if (op < 64)       v = mw1[o * 161 + k];
        else if (op < 128) v = mw1[o * 161 + 64 + k];
        else if (op < 192) v = cw1[o * 161 + k];
        else               v = cw1[o * 161 + 64 + k];
        g_wpack4[l][k * 256 + op] = v;
    }
    if (idx >= NN * 64) return;
    int n = idx >> 6, o = idx & 63;
    const float* wr = w + o * 8;
    const float* s = ns + n * 6;
    float acc = b[o];
#pragma unroll
    for (int i = 0; i < 6; i++) acc = fmaf(s[i], wr[i], acc);
    acc = fmaf(nt[n * 2 + 0], wr[6], acc);
    acc = fmaf(nt[n * 2 + 1], wr[7], acc);
    g_h[idx] = acc;
    g_uh[(size_t)n * 128 + o] = __float2half_rn(acc);
    if (o < 3) g_pos[n * 3 + o] = pos[n * 3 + o];
}

// ---------------- scan (self-cleans g_deg for next replay) ----------------
__global__ __launch_bounds__(1024) void k_scan()
{
    __shared__ int ssum[1024];
    int t = threadIdx.x;
    const int C = 49;
    int begin = t * C;
    int end = begin + C; if (end > NN) end = NN;
    if (begin > NN) begin = NN;
    int s = 0;
    for (int i = begin; i < end; i++) s += g_deg[i];
    ssum[t] = s;
    __syncthreads();
    for (int off = 1; off < 1024; off <<= 1) {
        int v = (t >= off) ? ssum[t - off] : 0;
        __syncthreads();
        ssum[t] += v;
        __syncthreads();
    }
    int run = ssum[t] - s;
    for (int i = begin; i < end; i++) {
        g_rowstart[i] = run;
        g_cursor[i] = run;
        run += g_deg[i];
        g_deg[i] = 0;      // self-clean for next replay
    }
    if (t == 1023) g_rowstart[NN] = ssum[1023];
}

// ---------------- fill + permute edge_s into CSR order as fp16 ----------------
__global__ void k_fillperm(const int* __restrict__ ei, const float* __restrict__ es)
{
    int e = blockIdx.x * blockDim.x + threadIdx.x;
    if (e >= NE) return;
    int s = ei[e], d = ei[NE + e];
    int p = atomicAdd(&g_cursor[d], 1);
    g_csrsrc[p] = s;
    g_csrdst[p] = d;
    const float4* ep = (const float4*)&es[(size_t)e * 32];
    __half hv[8];
#pragma unroll
    for (int q = 0; q < 4; q++) {
        float4 v0 = ep[2 * q], v1 = ep[2 * q + 1];
        hv[0] = __float2half_rn(v0.x); hv[1] = __float2half_rn(v0.y);
        hv[2] = __float2half_rn(v0.z); hv[3] = __float2half_rn(v0.w);
        hv[4] = __float2half_rn(v1.x); hv[5] = __float2half_rn(v1.y);
        hv[6] = __float2half_rn(v1.z); hv[7] = __float2half_rn(v1.w);
        *(uint4*)&g_esh[(size_t)p * 32 + q * 8] = *(uint4*)hv;
    }
}

// ---------------- Hpre (fp16 MMA): 64 nodes x 256 out (2 phases), K=64 ----------------
__global__ __launch_bounds__(256) void k_hpre(int layer)
{
    const float* wpack = g_wpack4[layer];
    __shared__ __align__(16) __half sH[64][72];
    __shared__ __align__(16) float sOut[64][132];
    int tid = threadIdx.x;
    int warp = tid >> 5, lane = tid & 31;
    int gid = lane >> 2, tig = lane & 3;

    uint32_t ah[2][4][4], al[2][4][4];
#pragma unroll
    for (int ph = 0; ph < 2; ph++) {
        int op0 = ph * 128 + warp * 16 + gid;
        int op1 = op0 + 8;
#pragma unroll
        for (int kb = 0; kb < 4; kb++) {
            int k0 = kb * 16 + 2 * tig;
            packsplit(wpack[k0 * 256 + op0], wpack[(k0 + 1) * 256 + op0], ah[ph][kb][0], al[ph][kb][0]);
            packsplit(wpack[k0 * 256 + op1], wpack[(k0 + 1) * 256 + op1], ah[ph][kb][1], al[ph][kb][1]);
            packsplit(wpack[(k0 + 8) * 256 + op0], wpack[(k0 + 9) * 256 + op0], ah[ph][kb][2], al[ph][kb][2]);
            packsplit(wpack[(k0 + 8) * 256 + op1], wpack[(k0 + 9) * 256 + op1], ah[ph][kb][3], al[ph][kb][3]);
        }
    }
    int ntiles = (NN + 63) >> 6;
    int el = tid >> 2, q = tid & 3;
    for (int t = blockIdx.x; t < ntiles; t += gridDim.x) {
        int n0 = t << 6;
        __syncthreads();
        {
            int n = n0 + el;
            __half hv[16];
            if (n < NN) {
                const float4* hp = (const float4*)&g_h[n * 64 + q * 16];
#pragma unroll
                for (int m = 0; m < 4; m++) {
                    float4 v = hp[m];
                    hv[4 * m] = __float2half_rn(v.x); hv[4 * m + 1] = __float2half_rn(v.y);
                    hv[4 * m + 2] = __float2half_rn(v.z); hv[4 * m + 3] = __float2half_rn(v.w);
                }
            } else {
#pragma unroll
                for (int m = 0; m < 16; m++) hv[m] = __float2half_rn(0.f);
            }
            *(uint4*)&sH[el][q * 16] = *(uint4*)&hv[0];
            *(uint4*)&sH[el][q * 16 + 8] = *(uint4*)&hv[8];
        }
        __syncthreads();
        for (int ph = 0; ph < 2; ph++) {
            float c[8][4];
#pragma unroll
            for (int nb = 0; nb < 8; nb++)
#pragma unroll
                for (int j = 0; j < 4; j++) c[nb][j] = 0.f;
#pragma unroll
            for (int kb = 0; kb < 4; kb++) {
#pragma unroll
                for (int nb = 0; nb < 8; nb++) {
                    int col = nb * 8 + gid;
                    uint32_t b0 = *(const uint32_t*)&sH[col][kb * 16 + 2 * tig];
                    uint32_t b1 = *(const uint32_t*)&sH[col][kb * 16 + 2 * tig + 8];
                    mma_f16(c[nb], ah[ph][kb][0], ah[ph][kb][1], ah[ph][kb][2], ah[ph][kb][3], b0, b1);
                    mma_f16(c[nb], al[ph][kb][0], al[ph][kb][1], al[ph][kb][2], al[ph][kb][3], b0, b1);
                }
            }
            {
                int ch = warp * 16 + gid;
#pragma unroll
                for (int nb = 0; nb < 8; nb++) {
                    int e = nb * 8 + 2 * tig;
                    sOut[e][ch] = c[nb][0];
                    sOut[e + 1][ch] = c[nb][1];
                    sOut[e][ch + 8] = c[nb][2];
                    sOut[e + 1][ch + 8] = c[nb][3];
                }
            }
            __syncthreads();
            {
                int n = n0 + el;
                if (n < NN) {
                    __half hv[32];
#pragma unroll
                    for (int m = 0; m < 32; m++) hv[m] = __float2half_rn(sOut[el][q * 32 + m]);
                    uint4* dst = (uint4*)&g_HpreH[(size_t)n * 256 + ph * 128 + q * 32];
                    dst[0] = *(uint4*)&hv[0];
                    dst[1] = *(uint4*)&hv[8];
                    dst[2] = *(uint4*)&hv[16];
                    dst[3] = *(uint4*)&hv[24];
                }
            }
            __syncthreads();
        }
    }
}

// ---------------- edge A (fp16 MMA, CSR order) ----------------
__global__ __launch_bounds__(256) void k_edgeAmma(int layer,
                                                  const float* __restrict__ mw1, const float* __restrict__ mb1,
                                                  const float* __restrict__ cw1, const float* __restrict__ cb1)
{
    __shared__ __align__(16) __half sEs[64][40];
    __shared__ __align__(16) float sOut[64][132];
    __shared__ float sR[64];
    __shared__ int sSrc[64], sDst[64];
    __shared__ float sS[128], sQ[128];

    int tid = threadIdx.x;
    int warp = tid >> 5, lane = tid & 31;
    int gid = lane >> 2, tig = lane & 3;
    int sl = layer * 256;

    if (tid < 128) { sS[tid] = 0.f; sQ[tid] = 0.f; }

    uint32_t ah[2][4], al[2][4];
    {
        int r0 = warp * 16 + gid;
        int r1 = r0 + 8;
        const float* w0 = (r0 < 64) ? &mw1[r0 * 161 + 129] : &cw1[(r0 - 64) * 161 + 129];
        const float* w1 = (r1 < 64) ? &mw1[r1 * 161 + 129] : &cw1[(r1 - 64) * 161 + 129];
#pragma unroll
        for (int kb = 0; kb < 2; kb++) {
            int k0 = kb * 16 + 2 * tig;
            packsplit(w0[k0], w0[k0 + 1], ah[kb][0], al[kb][0]);
            packsplit(w1[k0], w1[k0 + 1], ah[kb][1], al[kb][1]);
            packsplit(w0[k0 + 8], w0[k0 + 9], ah[kb][2], al[kb][2]);
            packsplit(w1[k0 + 8], w1[k0 + 9], ah[kb][3], al[kb][3]);
        }
    }
    int ch0 = lane << 2;
    float wr4[4], bb4[4];
#pragma unroll
    for (int j = 0; j < 4; j++) {
        int ch = ch0 + j;
        wr4[j] = (ch < 64) ? mw1[ch * 161 + 128] : cw1[(ch - 64) * 161 + 128];
        bb4[j] = (ch < 64) ? mb1[ch] : cb1[ch - 64];
    }
    int hd_off = (ch0 < 64) ? ch0 : 64 + ch0;
    int hs_off = (ch0 < 64) ? 64 + ch0 : 128 + ch0;
    float st[4] = {0.f, 0.f, 0.f, 0.f}, sq[4] = {0.f, 0.f, 0.f, 0.f};

    for (int t = blockIdx.x; t < NE / 64; t += gridDim.x) {
        int p0 = t << 6;
        __syncthreads();
        if (tid < 64) {
            int p = p0 + tid;
            int s = g_csrsrc[p], d = g_csrdst[p];
            sSrc[tid] = s; sDst[tid] = d;
            float dx = g_pos[d * 3] - g_pos[s * 3];
            float dy = g_pos[d * 3 + 1] - g_pos[s * 3 + 1];
            float dz = g_pos[d * 3 + 2] - g_pos[s * 3 + 2];
            sR[tid] = sqrtf(dx * dx + dy * dy + dz * dz);
        }
        {
            int el = tid >> 2, q = tid & 3;
            *(uint4*)&sEs[el][q * 8] = *(const uint4*)&g_esh[(size_t)(p0 + el) * 32 + q * 8];
        }
        __syncthreads();
        float c[8][4];
#pragma unroll
        for (int nb = 0; nb < 8; nb++)
#pragma unroll
            for (int j = 0; j < 4; j++) c[nb][j] = 0.f;
#pragma unroll
        for (int kb = 0; kb < 2; kb++) {
#pragma unroll
            for (int nb = 0; nb < 8; nb++) {
                int col = nb * 8 + gid;
                uint32_t b0 = *(const uint32_t*)&sEs[col][kb * 16 + 2 * tig];
                uint32_t b1 = *(const uint32_t*)&sEs[col][kb * 16 + 2 * tig + 8];
                mma_f16(c[nb], ah[kb][0], ah[kb][1], ah[kb][2], ah[kb][3], b0, b1);
                mma_f16(c[nb], al[kb][0], al[kb][1], al[kb][2], al[kb][3], b0, b1);
            }
        }
        // transpose into sOut (separate buffer; own-warp MMAs complete in order)
        {
            int ch = warp * 16 + gid;
#pragma unroll
            for (int nb = 0; nb < 8; nb++) {
                int e = nb * 8 + 2 * tig;
                sOut[e][ch] = c[nb][0];
                sOut[e + 1][ch] = c[nb][1];
                sOut[e][ch + 8] = c[nb][2];
                sOut[e + 1][ch + 8] = c[nb][3];
            }
        }
        __syncthreads();
#pragma unroll 2
        for (int ee = 0; ee < 8; ee++) {
            int e = warp * 8 + ee;
            int d = sDst[e], s = sSrc[e];
            float r = sR[e];
            uint2 du = *(const uint2*)&g_HpreH[(size_t)d * 256 + hd_off];
            uint2 su = *(const uint2*)&g_HpreH[(size_t)s * 256 + hs_off];
            float2 d01 = __half22float2(*(__half2*)&du.x);
            float2 d23 = __half22float2(*(__half2*)&du.y);
            float2 s01 = __half22float2(*(__half2*)&su.x);
            float2 s23 = __half22float2(*(__half2*)&su.y);
            float4 o = *(const float4*)&sOut[e][ch0];
            __half hv[4];
            hv[0] = __float2half_rn(o.x + d01.x + s01.x + fmaf(r, wr4[0], bb4[0]));
            hv[1] = __float2half_rn(o.y + d01.y + s01.y + fmaf(r, wr4[1], bb4[1]));
            hv[2] = __float2half_rn(o.z + d23.x + s23.x + fmaf(r, wr4[2], bb4[2]));
            hv[3] = __float2half_rn(o.w + d23.y + s23.y + fmaf(r, wr4[3], bb4[3]));
            int p = p0 + e;
            __half* out = (ch0 < 64) ? &g_t1h[(size_t)p * 64 + ch0]
                                     : &g_t2h[(size_t)p * 64 + ch0 - 64];
            *(uint2*)out = *(uint2*)hv;
#pragma unroll
            for (int j = 0; j < 4; j++) {
                float yr = __half2float(hv[j]);
                st[j] += yr; sq[j] += yr * yr;
            }
        }
    }
    __syncthreads();
#pragma unroll
    for (int j = 0; j < 4; j++) { atomicAdd(&sS[ch0 + j], st[j]); atomicAdd(&sQ[ch0 + j], sq[j]); }
    __syncthreads();
    if (tid < 128) {
        atomicAdd(&g_sum[sl + tid], (double)sS[tid]);
        atomicAdd(&g_sumsq[sl + tid], (double)sQ[tid]);
    }
}

// ---------------- edge B (fp16 MMA): BN computed locally from stats ----------------
__global__ __launch_bounds__(256) void k_edgeBmma(int layer,
                                                  const float* __restrict__ mg1, const float* __restrict__ mbe1,
                                                  const float* __restrict__ cg1, const float* __restrict__ cbe1,
                                                  const float* __restrict__ mw2, const float* __restrict__ mb2,
                                                  const float* __restrict__ cw2, const float* __restrict__ cb2)
{
    __shared__ __align__(16) __half sX[64][72];
    __shared__ __align__(16) float sOut[64 * 68];
    __shared__ float sS[64], sQ[64];
    __shared__ float sCA[64], sCB[64], sDA[64], sDB[64], sWc2[64];

    int tid = threadIdx.x;
    int warp = tid >> 5, lane = tid & 31;
    int gid = lane >> 2, tig = lane & 3;
    int m0 = (warp & 3) << 4;
    int n0 = (warp >> 2) << 5;
    int sl = layer * 256;

    if (tid < 64) {
        double m = g_sum[sl + tid] * (1.0 / NE);
        double v = g_sumsq[sl + tid] * (1.0 / NE) - m * m;
        float A = mg1[tid] * rsqrtf((float)v + EPS);
        sCA[tid] = A; sCB[tid] = mbe1[tid] - (float)m * A;
        sS[tid] = 0.f; sQ[tid] = 0.f;
        sWc2[tid] = cw2[tid];
    } else if (tid < 128) {
        int c = tid - 64;
        double m = g_sum[sl + 64 + c] * (1.0 / NE);
        double v = g_sumsq[sl + 64 + c] * (1.0 / NE) - m * m;
        float A = cg1[c] * rsqrtf((float)v + EPS);
        sDA[c] = A; sDB[c] = cbe1[c] - (float)m * A;
    }

    uint32_t ah[4][4], al[4][4];
    {
        const float* w0 = mw2 + (size_t)(m0 + gid) * 64;
        const float* w1 = mw2 + (size_t)(m0 + gid + 8) * 64;
#pragma unroll
        for (int kb = 0; kb < 4; kb++) {
            int k0 = kb * 16 + 2 * tig;
            packsplit(w0[k0], w0[k0 + 1], ah[kb][0], al[kb][0]);
            packsplit(w1[k0], w1[k0 + 1], ah[kb][1], al[kb][1]);
            packsplit(w0[k0 + 8], w0[k0 + 9], ah[kb][2], al[kb][2]);
            packsplit(w1[k0 + 8], w1[k0 + 9], ah[kb][3], al[kb][3]);
        }
    }
    float bias0 = mb2[m0 + gid], bias1 = mb2[m0 + gid + 8];
    float cbias = cb2[0];
    float s0 = 0.f, q0 = 0.f, s1 = 0.f, q1 = 0.f;

    int el = tid >> 2, q = tid & 3;

    for (int t = blockIdx.x; t < NE / 64; t += gridDim.x) {
        int e0 = t << 6;
        __syncthreads();
        {
            const uint4* tb = (const uint4*)&g_t1h[(size_t)(e0 + el) * 64 + q * 16];
            __half2 hbuf[8];
            *(uint4*)&hbuf[0] = tb[0];
            *(uint4*)&hbuf[4] = tb[1];
            __half xv[16];
#pragma unroll
            for (int m = 0; m < 8; m++) {
                float2 f = __half22float2(hbuf[m]);
                int c = q * 16 + 2 * m;
                xv[2 * m]     = __float2half_rn(silu_f(fmaf(f.x, sCA[c], sCB[c])));
                xv[2 * m + 1] = __float2half_rn(silu_f(fmaf(f.y, sCA[c + 1], sCB[c + 1])));
            }
            *(uint4*)&sX[el][q * 16] = *(uint4*)&xv[0];
            *(uint4*)&sX[el][q * 16 + 8] = *(uint4*)&xv[8];
        }
        {
            const uint4* tb = (const uint4*)&g_t2h[(size_t)(e0 + el) * 64 + q * 16];
            __half2 hbuf[8];
            *(uint4*)&hbuf[0] = tb[0];
            *(uint4*)&hbuf[4] = tb[1];
            float part = 0.f;
#pragma unroll
            for (int m = 0; m < 8; m++) {
                float2 f = __half22float2(hbuf[m]);
                int c = q * 16 + 2 * m;
                part += silu_f(fmaf(f.x, sDA[c], sDB[c])) * sWc2[c];
                part += silu_f(fmaf(f.y, sDA[c + 1], sDB[c + 1])) * sWc2[c + 1];
            }
            part += __shfl_xor_sync(0xffffffffu, part, 1);
            part += __shfl_xor_sync(0xffffffffu, part, 2);
            if (q == 0) g_sc[e0 + el] = part + cbias;
        }
        __syncthreads();
        float c[4][4];
#pragma unroll
        for (int nb = 0; nb < 4; nb++)
#pragma unroll
            for (int j = 0; j < 4; j++) c[nb][j] = 0.f;
#pragma unroll
        for (int kb = 0; kb < 4; kb++) {
#pragma unroll
            for (int nb = 0; nb < 4; nb++) {
                int col = n0 + nb * 8 + gid;
                uint32_t b0 = *(const uint32_t*)&sX[col][kb * 16 + 2 * tig];
                uint32_t b1 = *(const uint32_t*)&sX[col][kb * 16 + 2 * tig + 8];
                mma_f16(c[nb], ah[kb][0], ah[kb][1], ah[kb][2], ah[kb][3], b0, b1);
                mma_f16(c[nb], al[kb][0], al[kb][1], al[kb][2], al[kb][3], b0, b1);
            }
        }
#pragma unroll
        for (int nb = 0; nb < 4; nb++) {
            int e = n0 + nb * 8 + 2 * tig;
            float yr00 = __half2float(__float2half_rn(c[nb][0] + bias0));
            float yr01 = __half2float(__float2half_rn(c[nb][1] + bias0));
            float yr10 = __half2float(__float2half_rn(c[nb][2] + bias1));
            float yr11 = __half2float(__float2half_rn(c[nb][3] + bias1));
            sOut[e * 68 + m0 + gid] = yr00;
            sOut[(e + 1) * 68 + m0 + gid] = yr01;
            sOut[e * 68 + m0 + gid + 8] = yr10;
            sOut[(e + 1) * 68 + m0 + gid + 8] = yr11;
            s0 += yr00 + yr01; q0 += yr00 * yr00 + yr01 * yr01;
            s1 += yr10 + yr11; q1 += yr10 * yr10 + yr11 * yr11;
        }
        __syncthreads();
        {
            const float* src = &sOut[el * 68 + q * 16];
            __half hv[16];
#pragma unroll
            for (int m = 0; m < 16; m++) hv[m] = __float2half_rn(src[m]);
            uint4* dst = (uint4*)&g_mlinh[(size_t)(e0 + el) * 64 + q * 16];
            dst[0] = *(uint4*)&hv[0];
            dst[1] = *(uint4*)&hv[8];
        }
    }
    __syncthreads();
    atomicAdd(&sS[m0 + gid], s0); atomicAdd(&sQ[m0 + gid], q0);
    atomicAdd(&sS[m0 + gid + 8], s1); atomicAdd(&sQ[m0 + gid + 8], q1);
    __syncthreads();
    if (tid < 64) {
        atomicAdd(&g_sum[sl + 128 + tid], (double)sS[tid]);
        atomicAdd(&g_sumsq[sl + 128 + tid], (double)sQ[tid]);
    }
}

// ---------------- aggregation: warp per node, half2 loads; writes g_uh fp16 ----------------
__global__ __launch_bounds__(256) void k_aggr(int layer,
                                              const float* __restrict__ g2, const float* __restrict__ be2)
{
    int gwarp = (blockIdx.x * blockDim.x + threadIdx.x) >> 5;
    int lane = threadIdx.x & 31;
    if (gwarp >= NN) return;
    int n = gwarp;
    int sl = layer * 256;
    const double inv = 1.0 / NE;
    int c0 = 2 * lane;
    float A0, B0, A1, B1;
    {
        double m = g_sum[sl + 128 + c0] * inv;
        double v = g_sumsq[sl + 128 + c0] * inv - m * m;
        A0 = g2[c0] * rsqrtf((float)v + EPS);
        B0 = be2[c0] - (float)m * A0;
        m = g_sum[sl + 128 + c0 + 1] * inv;
        v = g_sumsq[sl + 128 + c0 + 1] * inv - m * m;
        A1 = g2[c0 + 1] * rsqrtf((float)v + EPS);
        B1 = be2[c0 + 1] - (float)m * A1;
    }
    int s0 = g_rowstart[n], s1 = g_rowstart[n + 1];
    float acc0 = 0.f, acc1 = 0.f;
    for (int i = s0; i < s1; i++) {
        uint32_t u = *(const uint32_t*)&g_mlinh[(size_t)i * 64 + c0];
        float2 f = __half22float2(*(__half2*)&u);
        acc0 += silu_f(fmaf(f.x, A0, B0));
        acc1 += silu_f(fmaf(f.y, A1, B1));
    }
    __half2 hv = __halves2half2(__float2half_rn(acc0), __float2half_rn(acc1));
    *(__half2*)&g_uh[(size_t)n * 128 + 64 + c0] = hv;
    float px = g_pos[n * 3], py = g_pos[n * 3 + 1], pz = g_pos[n * 3 + 2];
    float cx = 0.f, cy = 0.f, cz = 0.f;
    for (int i = s0 + lane; i < s1; i += 32) {
        int src = g_csrsrc[i];
        float sc = g_sc[i];
        cx += sc * (px - g_pos[src * 3]);
        cy += sc * (py - g_pos[src * 3 + 1]);
        cz += sc * (pz - g_pos[src * 3 + 2]);
    }
#pragma unroll
    for (int o = 16; o > 0; o >>= 1) {
        cx += __shfl_xor_sync(0xffffffffu, cx, o);
        cy += __shfl_xor_sync(0xffffffffu, cy, o);
        cz += __shfl_xor_sync(0xffffffffu, cz, o);
    }
    if (lane == 0) {
        g_aggr_p[n * 3 + 0] = cx;
        g_aggr_p[n * 3 + 1] = cy;
        g_aggr_p[n * 3 + 2] = cz;
    }
}

// ---------------- node 1 (fp16 MMA): un = uh(128) @ uw1^T + b ----------------
__global__ __launch_bounds__(256) void k_node1(int layer,
                                               const float* __restrict__ uw1, const float* __restrict__ ub1)
{
    __shared__ __align__(16) __half sU[64][136];
    __shared__ __align__(16) float sOut[64 * 68];
    __shared__ float sS[64], sQ[64];
    int tid = threadIdx.x;
    int warp = tid >> 5, lane = tid & 31;
    int gid = lane >> 2, tig = lane & 3;
    int m0 = (warp & 3) << 4;
    int n0 = (warp >> 2) << 5;
    int sl = layer * 256;
    if (tid < 64) { sS[tid] = 0.f; sQ[tid] = 0.f; }

    uint32_t ah[8][4], al[8][4];
    {
        const float* w0 = uw1 + (size_t)(m0 + gid) * 128;
        const float* w1 = uw1 + (size_t)(m0 + gid + 8) * 128;
#pragma unroll
        for (int kb = 0; kb < 8; kb++) {
            int k0 = kb * 16 + 2 * tig;
            packsplit(w0[k0], w0[k0 + 1], ah[kb][0], al[kb][0]);
            packsplit(w1[k0], w1[k0 + 1], ah[kb][1], al[kb][1]);
            packsplit(w0[k0 + 8], w0[k0 + 9], ah[kb][2], al[kb][2]);
            packsplit(w1[k0 + 8], w1[k0 + 9], ah[kb][3], al[kb][3]);
        }
    }
    float bias0 = ub1[m0 + gid], bias1 = ub1[m0 + gid + 8];
    float s0 = 0.f, q0 = 0.f, s1 = 0.f, q1 = 0.f;
    int el = tid >> 2, q = tid & 3;
    int ntiles = (NN + 63) >> 6;

    for (int t = blockIdx.x; t < ntiles; t += gridDim.x) {
        int tn0 = t << 6;
        __syncthreads();
        {
            int n = tn0 + el;
            uint4 v0, v1, v2, v3;
            if (n < NN) {
                const uint4* up = (const uint4*)&g_uh[(size_t)n * 128 + q * 32];
                v0 = up[0]; v1 = up[1]; v2 = up[2]; v3 = up[3];
            } else {
                v0 = v1 = v2 = v3 = make_uint4(0, 0, 0, 0);
            }
            uint4* dst = (uint4*)&sU[el][q * 32];
            dst[0] = v0; dst[1] = v1; dst[2] = v2; dst[3] = v3;
        }
        __syncthreads();
        float c[4][4];
#pragma unroll
        for (int nb = 0; nb < 4; nb++)
#pragma unroll
            for (int j = 0; j < 4; j++) c[nb][j] = 0.f;
#pragma unroll
        for (int kb = 0; kb < 8; kb++) {
#pragma unroll
            for (int nb = 0; nb < 4; nb++) {
                int col = n0 + nb * 8 + gid;
                uint32_t b0 = *(const uint32_t*)&sU[col][kb * 16 + 2 * tig];
                uint32_t b1 = *(const uint32_t*)&sU[col][kb * 16 + 2 * tig + 8];
                mma_f16(c[nb], ah[kb][0], ah[kb][1], ah[kb][2], ah[kb][3], b0, b1);
                mma_f16(c[nb], al[kb][0], al[kb][1], al[kb][2], al[kb][3], b0, b1);
            }
        }
#pragma unroll
        for (int nb = 0; nb < 4; nb++) {
            int e = n0 + nb * 8 + 2 * tig;
            float yr00 = __half2float(__float2half_rn(c[nb][0] + bias0));
            float yr01 = __half2float(__float2half_rn(c[nb][1] + bias0));
            float yr10 = __half2float(__float2half_rn(c[nb][2] + bias1));
            float yr11 = __half2float(__float2half_rn(c[nb][3] + bias1));
            sOut[e * 68 + m0 + gid] = yr00;
            sOut[(e + 1) * 68 + m0 + gid] = yr01;
            sOut[e * 68 + m0 + gid + 8] = yr10;
            sOut[(e + 1) * 68 + m0 + gid + 8] = yr11;
            bool v0 = (tn0 + e < NN), v1 = (tn0 + e + 1 < NN);
            if (v0) { s0 += yr00; q0 += yr00 * yr00; s1 += yr10; q1 += yr10 * yr10; }
            if (v1) { s0 += yr01; q0 += yr01 * yr01; s1 += yr11; q1 += yr11 * yr11; }
        }
        __syncthreads();
        {
            int n = tn0 + el;
            if (n < NN) {
                const float* src = &sOut[el * 68 + q * 16];
                __half hv[16];
#pragma unroll
                for (int m = 0; m < 16; m++) hv[m] = __float2half_rn(src[m]);
                uint4* dst = (uint4*)&g_unh[(size_t)n * 64 + q * 16];
                dst[0] = *(uint4*)&hv[0];
                dst[1] = *(uint4*)&hv[8];
            }
        }
    }
    __syncthreads();
    atomicAdd(&sS[m0 + gid], s0); atomicAdd(&sQ[m0 + gid], q0);
    atomicAdd(&sS[m0 + gid + 8], s1); atomicAdd(&sQ[m0 + gid + 8], q1);
    __syncthreads();
    if (tid < 64) {
        atomicAdd(&g_sum[sl + 192 + tid], (double)sS[tid]);
        atomicAdd(&g_sumsq[sl + 192 + tid], (double)sQ[tid]);
    }
}

// ---------------- node 2 (fp16 MMA): h += silu(bn(un)) @ uw2^T + b; pos update ----------------
__global__ __launch_bounds__(256) void k_node2(int layer,
                                               const float* __restrict__ ug1, const float* __restrict__ ube1,
                                               const float* __restrict__ uw2, const float* __restrict__ ub2)
{
    __shared__ __align__(16) __half sX[64][72];
    __shared__ __align__(16) float sOut[64 * 68];
    __shared__ float sBA[64], sBB[64];
    int tid = threadIdx.x;
    int warp = tid >> 5, lane = tid & 31;
    int gid = lane >> 2, tig = lane & 3;
    int m0 = (warp & 3) << 4;
    int n0 = (warp >> 2) << 5;
    int sl = layer * 256;
    if (tid < 64) {
        double m = g_sum[sl + 192 + tid] * (1.0 / NN);
        double v = g_sumsq[sl + 192 + tid] * (1.0 / NN) - m * m;
        float A = ug1[tid] * rsqrtf((float)v + EPS);
        sBA[tid] = A; sBB[tid] = ube1[tid] - (float)m * A;
    }
    uint32_t ah[4][4], al[4][4];
    {
        const float* w0 = uw2 + (size_t)(m0 + gid) * 64;
        const float* w1 = uw2 + (size_t)(m0 + gid + 8) * 64;
#pragma unroll
        for (int kb = 0; kb < 4; kb++) {
            int k0 = kb * 16 + 2 * tig;
            packsplit(w0[k0], w0[k0 + 1], ah[kb][0], al[kb][0]);
            packsplit(w1[k0], w1[k0 + 1], ah[kb][1], al[kb][1]);
            packsplit(w0[k0 + 8], w0[k0 + 9], ah[kb][2], al[kb][2]);
            packsplit(w1[k0 + 8], w1[k0 + 9], ah[kb][3], al[kb][3]);
        }
    }
    float bias0 = ub2[m0 + gid], bias1 = ub2[m0 + gid + 8];
    int el = tid >> 2, q = tid & 3;
    int ntiles = (NN + 63) >> 6;
    __syncthreads();

    for (int t = blockIdx.x; t < ntiles; t += gridDim.x) {
        int tn0 = t << 6;
        __syncthreads();
        {
            int n = tn0 + el;
            __half xv[16];
            if (n < NN) {
                const uint4* tb = (const uint4*)&g_unh[(size_t)n * 64 + q * 16];
                __half2 hbuf[8];
                *(uint4*)&hbuf[0] = tb[0];
                *(uint4*)&hbuf[4] = tb[1];
#pragma unroll
                for (int m = 0; m < 8; m++) {
                    float2 f = __half22float2(hbuf[m]);
                    int c = q * 16 + 2 * m;
                    xv[2 * m]     = __float2half_rn(silu_f(fmaf(f.x, sBA[c], sBB[c])));
                    xv[2 * m + 1] = __float2half_rn(silu_f(fmaf(f.y, sBA[c + 1], sBB[c + 1])));
                }
            } else {
#pragma unroll
                for (int m = 0; m < 16; m++) xv[m] = __float2half_rn(0.f);
            }
            *(uint4*)&sX[el][q * 16] = *(uint4*)&xv[0];
            *(uint4*)&sX[el][q * 16 + 8] = *(uint4*)&xv[8];
        }
        __syncthreads();
        float c[4][4];
#pragma unroll
        for (int nb = 0; nb < 4; nb++)
#pragma unroll
            for (int j = 0; j < 4; j++) c[nb][j] = 0.f;
#pragma unroll
        for (int kb = 0; kb < 4; kb++) {
#pragma unroll
            for (int nb = 0; nb < 4; nb++) {
                int col = n0 + nb * 8 + gid;
                uint32_t b0 = *(const uint32_t*)&sX[col][kb * 16 + 2 * tig];
                uint32_t b1 = *(const uint32_t*)&sX[col][kb * 16 + 2 * tig + 8];
                mma_f16(c[nb], ah[kb][0], ah[kb][1], ah[kb][2], ah[kb][3], b0, b1);
                mma_f16(c[nb], al[kb][0], al[kb][1], al[kb][2], al[kb][3], b0, b1);
            }
        }
#pragma unroll
        for (int nb = 0; nb < 4; nb++) {
            int e = n0 + nb * 8 + 2 * tig;
            sOut[e * 68 + m0 + gid] = c[nb][0] + bias0;
            sOut[(e + 1) * 68 + m0 + gid] = c[nb][1] + bias0;
            sOut[e * 68 + m0 + gid + 8] = c[nb][2] + bias1;
            sOut[(e + 1) * 68 + m0 + gid + 8] = c[nb][3] + bias1;
        }
        __syncthreads();
        {
            int n = tn0 + el;
            if (n < NN) {
                const float* src = &sOut[el * 68 + q * 16];
#pragma unroll
                for (int m = 0; m < 4; m++) {
                    float4 hold = *(const float4*)&g_h[n * 64 + q * 16 + 4 * m];
                    float4 hv = make_float4(hold.x + src[4 * m], hold.y + src[4 * m + 1],
                                            hold.z + src[4 * m + 2], hold.w + src[4 * m + 3]);
                    *(float4*)&g_h[n * 64 + q * 16 + 4 * m] = hv;
                    __half hh[4];
                    hh[0] = __float2half_rn(hv.x); hh[1] = __float2half_rn(hv.y);
                    hh[2] = __float2half_rn(hv.z); hh[3] = __float2half_rn(hv.w);
                    *(uint2*)&g_uh[(size_t)n * 128 + q * 16 + 4 * m] = *(uint2*)hh;
                }
            }
        }
        if (tid < 64) {
            int n = tn0 + tid;
            if (n < NN) {
                g_pos[n * 3 + 0] += g_aggr_p[n * 3 + 0];
                g_pos[n * 3 + 1] += g_aggr_p[n * 3 + 1];
                g_pos[n * 3 + 2] += g_aggr_p[n * 3 + 2];
            }
        }
    }
}

// ---------------- pooling ----------------
__global__ void k_pool(const int* __restrict__ batch)
{
    int idx = blockIdx.x * blockDim.x + threadIdx.x;
    if (idx >= NN * 16) return;
    int n = idx >> 4, c4 = (idx & 15) * 4;
    int b = batch[n];
    float4 h = *(const float4*)&g_h[n * 64 + c4];
    red_add_v4(&g_pool[b * 64 + c4], h.x, h.y, h.z, h.w);
    if (c4 == 0) atomicAdd(&g_cnt[b], 1.0f);
}

__global__ void k_pred(const float* __restrict__ w, const float* __restrict__ b,
                       float* __restrict__ out)
{
    int g = blockIdx.x, lane = threadIdx.x;
    float p = g_pool[g * 64 + lane] * w[lane] + g_pool[g * 64 + 32 + lane] * w[32 + lane];
#pragma unroll
    for (int o = 16; o > 0; o >>= 1) p += __shfl_xor_sync(0xffffffffu, p, o);
    if (lane == 0) out[g] = p / fmaxf(g_cnt[g], 1.0f) + b[0];
}

// ---------------- launch ----------------
extern "C" void kernel_launch(void* const* d_in, const int* in_sizes, int n_in,
                              void* d_out, int out_size)
{
    const float* node_s    = (const float*)d_in[0];
    const float* node_type = (const float*)d_in[1];
    const float* pos       = (const float*)d_in[2];
    const int*   ei        = (const int*)d_in[3];
    const float* edge_s    = (const float*)d_in[4];
    const int*   batch     = (const int*)d_in[5];
    const float* lin_in_w  = (const float*)d_in[6];
    const float* lin_in_b  = (const float*)d_in[7];
    const float* msg_w1    = (const float*)d_in[8];
    const float* msg_b1    = (const float*)d_in[9];
    const float* msg_g1    = (const float*)d_in[10];
    const float* msg_be1   = (const float*)d_in[11];
    const float* msg_w2    = (const float*)d_in[12];
    const float* msg_b2    = (const float*)d_in[13];
    const float* msg_g2    = (const float*)d_in[14];
    const float* msg_be2   = (const float*)d_in[15];
    const float* updf_w1   = (const float*)d_in[16];
    const float* updf_b1   = (const float*)d_in[17];
    const float* updf_g1   = (const float*)d_in[18];
    const float* updf_be1  = (const float*)d_in[19];
    const float* updf_w2   = (const float*)d_in[20];
    const float* updf_b2   = (const float*)d_in[21];
    const float* updc_w1   = (const float*)d_in[22];
    const float* updc_b1   = (const float*)d_in[23];
    const float* updc_g1   = (const float*)d_in[24];
    const float* updc_be1  = (const float*)d_in[25];
    const float* updc_w2   = (const float*)d_in[26];
    const float* updc_b2   = (const float*)d_in[27];
    const float* lin_pred_w = (const float*)d_in[28];
    const float* lin_pred_b = (const float*)d_in[29];

    k_init<<<(NN * 64 + 255) / 256, 256>>>(node_s, node_type, pos, lin_in_w, lin_in_b,
                                           ei, msg_w1, updc_w1);
    k_scan<<<1, 1024>>>();
    k_fillperm<<<(NE + 255) / 256, 256>>>(ei, edge_s);

    for (int l = 0; l < NL; l++) {
        const float* mw1 = msg_w1 + (size_t)l * 64 * 161;
        const float* mb1 = msg_b1 + l * 64;
        const float* mw2 = msg_w2 + (size_t)l * 64 * 64;
        const float* mb2 = msg_b2 + l * 64;
        const float* cw1 = updc_w1 + (size_t)l * 64 * 161;
        const float* cb1 = updc_b1 + l * 64;
        const float* cw2 = updc_w2 + (size_t)l * 64;
        const float* cb2 = updc_b2 + l;
        const float* uw1 = updf_w1 + (size_t)l * 64 * 128;
        const float* ub1 = updf_b1 + l * 64;
        const float* uw2 = updf_w2 + (size_t)l * 64 * 64;
        const float* ub2 = updf_b2 + l * 64;

        k_hpre<<<592, 256>>>(l);
        k_edgeAmma<<<592, 256>>>(l, mw1, mb1, cw1, cb1);
        k_edgeBmma<<<592, 256>>>(l, msg_g1 + l * 64, msg_be1 + l * 64,
                                 updc_g1 + l * 64, updc_be1 + l * 64,
                                 mw2, mb2, cw2, cb2);
        k_aggr<<<(NN * 32 + 255) / 256, 256>>>(l, msg_g2 + l * 64, msg_be2 + l * 64);
        k_node1<<<592, 256>>>(l, uw1, ub1);
        k_node2<<<592, 256>>>(l, updf_g1 + l * 64, updf_be1 + l * 64, uw2, ub2);
    }

    k_pool<<<(NN * 16 + 255) / 256, 256>>>(batch);
    k_pred<<<NG, 32>>>(lin_pred_w, lin_pred_b, (float*)d_out);
}